// round 8
// baseline (speedup 1.0000x reference)
#include <cuda_runtime.h>
#include <cuda_fp16.h>
#include <math.h>

// ---------------- problem constants ----------------
#define BB   2
#define NN   2048
#define KNB  30
#define DN   256
#define DE   128
#define NL   3
#define NFI  12
#define EFI  28
#define ETOT (BB*NN*KNB)  // 122880
#define NNODE (BB*NN)     // 4096
#define EPSF 1e-6f
#define BIGF 1e9f
#define FLTMAX 3.402823466e38f

#define S0OUT (NNODE*DN)
#define S1OUT (ETOT*DE)

// ---------------- scratch ----------------
__device__ float  g_nodeh [NNODE*DN];
__device__ __half g_nodehr[NNODE*DN];
__device__ float  g_edgeh [ETOT*DE];
__device__ __half g_edgehr[ETOT*DE];
__device__ int    g_eidx [ETOT];
__device__ float  g_maski[NNODE];
__device__ float  g_maskij[ETOT];
__device__ float  g_denom[NNODE];
__device__ float  g_cnt  [NNODE];
__device__ float  g_R  [NNODE*9];
__device__ float  g_Xc [NNODE*3];
__device__ __half g_t2h[ETOT*DE];
__device__ float  g_Ym [2*NNODE*DN];
__device__ float  g_Ye [2*NNODE*DE];
__device__ float  g_ksum [NNODE*DN];
__device__ __half g_ksumh[NNODE*DN];
__device__ __half g_featr[ETOT*32];
__device__ float  g_bcat[NL*384];          // [bm1 | bue1] per layer

// transposed fp16 weight arena: W^T[n][k]
#define WT_CAT 0
#define WT_E1  (3*2*384*256)            // 589824 : fused stage-1 [l][n<384][k<128]
#define WT_M2  (WT_E1 + 3*384*128)      // 737280
#define WT_UE2 (WT_M2 + 3*256*256)      // 933888
#define WT_WE  (WT_UE2 + 3*128*128)     // 983040
#define WT_TOT (WT_WE + 128*32)         // 987136
__device__ __half g_Wh[WT_TOT];

__device__ __forceinline__ float softplus_f(float x) {
    return fmaxf(x, 0.0f) + log1pf(expf(-fabsf(x)));
}
__device__ __forceinline__ void mma16(float* c, const unsigned* a, const unsigned* b) {
    asm volatile(
        "mma.sync.aligned.m16n8k16.row.col.f32.f16.f16.f32 "
        "{%0,%1,%2,%3},{%4,%5,%6,%7},{%8,%9},{%0,%1,%2,%3};"
        : "+f"(c[0]), "+f"(c[1]), "+f"(c[2]), "+f"(c[3])
        : "r"(a[0]), "r"(a[1]), "r"(a[2]), "r"(a[3]), "r"(b[0]), "r"(b[1]));
}
__device__ __forceinline__ void ldsm4(unsigned& r0, unsigned& r1, unsigned& r2, unsigned& r3,
                                      unsigned addr) {
    asm volatile("ldmatrix.sync.aligned.m8n8.x4.shared.b16 {%0,%1,%2,%3}, [%4];"
        : "=r"(r0), "=r"(r1), "=r"(r2), "=r"(r3) : "r"(addr));
}
__device__ __forceinline__ void cp16(unsigned dst, const void* src) {
    asm volatile("cp.async.cg.shared.global [%0], [%1], 16;" :: "r"(dst), "l"(src));
}
#define CP_COMMIT() asm volatile("cp.async.commit_group;")
#define CP_WAIT1()  asm volatile("cp.async.wait_group 1;")

// ---------------- 0) round + transpose + repack all weights to fp16 ----------------
__global__ void round_w_kernel(const float* __restrict__ Wm1, const float* __restrict__ Wue1,
                               const float* __restrict__ Wm2, const float* __restrict__ Wue2,
                               const float* __restrict__ We,
                               const float* __restrict__ bm1, const float* __restrict__ bue1)
{
    for (int i = blockIdx.x*blockDim.x + threadIdx.x; i < NL*384; i += gridDim.x*blockDim.x) {
        int l = i / 384, n = i % 384;
        g_bcat[i] = (n < 256) ? bm1[l*256 + n] : bue1[l*128 + (n - 256)];
    }
    for (int i = blockIdx.x*blockDim.x + threadIdx.x; i < WT_TOT; i += gridDim.x*blockDim.x) {
        float v;
        if (i < WT_E1) {                        // [l][z][n<384][k<256]
            int l = i / 196608, r = i % 196608;
            int z = r / 98304,  q = r % 98304;
            int n = q / 256,    k = q % 256;
            v = (n < 256) ? Wm1 [((size_t)l*640 + z*256 + k)*256 + n]
                          : Wue1[((size_t)l*640 + z*256 + k)*128 + (n - 256)];
        } else if (i < WT_M2) {                 // fused stage-1: [l][n<384][k<128]
            int r = i - WT_E1;
            int l = r / 49152, q = r % 49152;
            int n = q / 128,   k = q % 128;
            v = (n < 256) ? Wm1 [((size_t)l*640 + 512 + k)*256 + n]
                          : Wue1[((size_t)l*640 + 512 + k)*128 + (n - 256)];
        } else if (i < WT_UE2) {                // [l][n<256][k<256]
            int r = i - WT_M2;
            int l = r / 65536, q = r % 65536;
            int n = q / 256,   k = q % 256;
            v = Wm2[((size_t)l*256 + k)*256 + n];
        } else if (i < WT_WE) {                 // [l][n<128][k<128]
            int r = i - WT_UE2;
            int l = r / 16384, q = r % 16384;
            int n = q / 128,   k = q % 128;
            v = Wue2[((size_t)l*128 + k)*128 + n];
        } else {                                // [n<128][k<32]
            int r = i - WT_WE;
            int n = r / 32, k = r % 32;
            v = (k < EFI) ? We[k*128 + n] : 0.0f;
        }
        g_Wh[i] = __float2half_rn(v);
    }
}

// ---------------- 1) per-node frame, features, node_h init ----------------
__global__ void frame_kernel(const float* __restrict__ X, const int* __restrict__ C,
                             const float* __restrict__ Wn, const float* __restrict__ bn)
{
    __shared__ float s_feat[8][12];
    __shared__ float s_mask[8];
    int warp = threadIdx.x >> 5;
    int lane = threadIdx.x & 31;
    int nlin = blockIdx.x * 8 + warp;

    if (lane == 0) {
        const float* xr = X + (size_t)nlin * 12;
        float Na[3], CA[3], Ct[3], Oa[3];
        #pragma unroll
        for (int d = 0; d < 3; d++) { Na[d]=xr[d]; CA[d]=xr[3+d]; Ct[d]=xr[6+d]; Oa[d]=xr[9+d]; }
        #pragma unroll
        for (int d = 0; d < 3; d++) {
            float s = __fadd_rn(__fadd_rn(__fadd_rn(Na[d], CA[d]), Ct[d]), Oa[d]);
            g_Xc[nlin*3 + d] = __fmul_rn(s, 0.25f);
        }
        float b1[3], b2[3], b3[3], v0[3];
        #pragma unroll
        for (int d = 0; d < 3; d++) {
            b1[d] = CA[d] - Na[d];
            b2[d] = Ct[d] - CA[d];
            b3[d] = Oa[d] - Ct[d];
            v0[d] = Na[d] - CA[d];
        }
        float nb2 = sqrtf(b2[0]*b2[0] + b2[1]*b2[1] + b2[2]*b2[2]);
        float u[3];
        #pragma unroll
        for (int d = 0; d < 3; d++) u[d] = b2[d] / (nb2 + EPSF);
        float dotv = v0[0]*u[0] + v0[1]*u[1] + v0[2]*u[2];
        float t[3];
        #pragma unroll
        for (int d = 0; d < 3; d++) t[d] = v0[d] - dotv * u[d];
        float nt = sqrtf(t[0]*t[0] + t[1]*t[1] + t[2]*t[2]);
        float v[3];
        #pragma unroll
        for (int d = 0; d < 3; d++) v[d] = t[d] / (nt + EPSF);
        float w[3];
        w[0] = u[1]*v[2] - u[2]*v[1];
        w[1] = u[2]*v[0] - u[0]*v[2];
        w[2] = u[0]*v[1] - u[1]*v[0];
        #pragma unroll
        for (int d = 0; d < 3; d++) {
            g_R[nlin*9 + d*3 + 0] = u[d];
            g_R[nlin*9 + d*3 + 1] = v[d];
            g_R[nlin*9 + d*3 + 2] = w[d];
        }
        float nb1 = sqrtf(b1[0]*b1[0] + b1[1]*b1[1] + b1[2]*b1[2]);
        float nb3 = sqrtf(b3[0]*b3[0] + b3[1]*b3[1] + b3[2]*b3[2]);
        #pragma unroll
        for (int d = 0; d < 3; d++) {
            s_feat[warp][0 + d] = b1[d] / (nb1 + EPSF);
            s_feat[warp][4 + d] = b2[d] / (nb2 + EPSF);
            s_feat[warp][8 + d] = b3[d] / (nb3 + EPSF);
        }
        s_feat[warp][3]  = logf(nb1 + EPSF);
        s_feat[warp][7]  = logf(nb2 + EPSF);
        s_feat[warp][11] = logf(nb3 + EPSF);
        float mk = (C[nlin] > 0) ? 1.0f : 0.0f;
        s_mask[warp] = mk;
        g_maski[nlin] = mk;
    }
    __syncwarp();

    float f[12];
    #pragma unroll
    for (int i = 0; i < 12; i++) f[i] = s_feat[warp][i];
    float mk = s_mask[warp];
    #pragma unroll
    for (int r = 0; r < 8; r++) {
        int c = lane + r * 32;
        float acc = bn[c];
        #pragma unroll
        for (int ff = 0; ff < NFI; ff++) acc += f[ff] * Wn[ff*DN + c];
        float v = acc * mk;
        g_nodeh [(size_t)nlin*DN + c] = v;
        g_nodehr[(size_t)nlin*DN + c] = __float2half_rn(v);
    }
}

// ---------------- 2) kNN: warp-per-node, exact semantics ----------------
__global__ __launch_bounds__(128) void knn_kernel(const int* __restrict__ C)
{
    __shared__ float s_d2[4][NN];
    int wid = threadIdx.x >> 5;
    int lane = threadIdx.x & 31;
    int nlin = blockIdx.x * 4 + wid;
    int b = nlin >> 11;
    int n = nlin & (NN - 1);

    float xi0 = g_Xc[nlin*3+0], xi1 = g_Xc[nlin*3+1], xi2 = g_Xc[nlin*3+2];
    const int* Cb = C + b*NN;
    for (int j = lane; j < NN; j += 32) {
        float dx = __fadd_rn(xi0, -g_Xc[(size_t)(b*NN + j)*3 + 0]);
        float dy = __fadd_rn(xi1, -g_Xc[(size_t)(b*NN + j)*3 + 1]);
        float dz = __fadd_rn(xi2, -g_Xc[(size_t)(b*NN + j)*3 + 2]);
        float d2 = __fadd_rn(__fadd_rn(__fmul_rn(dx,dx), __fmul_rn(dy,dy)), __fmul_rn(dz,dz));
        if (Cb[j] <= 0) d2 = __fadd_rn(d2, BIGF);
        if (j == n)     d2 = __fadd_rn(d2, BIGF);
        s_d2[wid][j] = d2;
    }
    __syncwarp();

    float mi = g_maski[nlin];
    float cnt = 0.0f;
    for (int kk = 0; kk < KNB; kk++) {
        float bv = FLTMAX; int bi = 0x7fffffff;
        #pragma unroll 4
        for (int j = lane; j < NN; j += 32) {
            float v = s_d2[wid][j];
            if (v < bv || (v == bv && j < bi)) { bv = v; bi = j; }
        }
        #pragma unroll
        for (int off = 16; off > 0; off >>= 1) {
            float v2 = __shfl_down_sync(0xffffffffu, bv, off);
            int   i2 = __shfl_down_sync(0xffffffffu, bi, off);
            if (v2 < bv || (v2 == bv && i2 < bi)) { bv = v2; bi = i2; }
        }
        bi = __shfl_sync(0xffffffffu, bi, 0);
        if (lane == 0) {
            int e = nlin*KNB + kk;
            g_eidx[e] = bi;
            float mj = (Cb[bi] > 0) ? 1.0f : 0.0f;
            float mij = mi * mj;
            g_maskij[e] = mij;
            cnt += mij;
            s_d2[wid][bi] = FLTMAX;
        }
        __syncwarp();
    }
    if (lane == 0) { g_cnt[nlin] = cnt; g_denom[nlin] = cnt + EPSF; }
}

// ---------------- 3) edge features -> g_featr (fp16, padded to 32) ----------------
__global__ __launch_bounds__(128) void feat_kernel()
{
    int e = blockIdx.x * 128 + threadIdx.x;
    int nlin = e / KNB;
    int b = nlin >> 11;
    int j = g_eidx[e];
    int jl = b*NN + j;

    float dv[3];
    #pragma unroll
    for (int d = 0; d < 3; d++) dv[d] = g_Xc[jl*3+d] - g_Xc[nlin*3+d];
    float dist = sqrtf(dv[0]*dv[0] + dv[1]*dv[1] + dv[2]*dv[2]);
    float Ri[9], Rj[9];
    #pragma unroll
    for (int q = 0; q < 9; q++) { Ri[q] = g_R[nlin*9+q]; Rj[q] = g_R[jl*9+q]; }

    float f[32];
    #pragma unroll
    for (int mc = 0; mc < 16; mc++) {
        float cm = (float)(20.0 * mc / 15.0);
        float z = (dist - cm) * 0.8f;
        f[mc] = expf(-z*z);
    }
    float inv = 1.0f / (dist + EPSF);
    #pragma unroll
    for (int c = 0; c < 3; c++) {
        float loc = Ri[0*3+c]*dv[0] + Ri[1*3+c]*dv[1] + Ri[2*3+c]*dv[2];
        f[16 + c] = loc * inv;
    }
    #pragma unroll
    for (int ee = 0; ee < 3; ee++)
        #pragma unroll
        for (int ff = 0; ff < 3; ff++)
            f[19 + ee*3 + ff] = Ri[0*3+ee]*Rj[0*3+ff] + Ri[1*3+ee]*Rj[1*3+ff] + Ri[2*3+ee]*Rj[2*3+ff];
    f[28] = f[29] = f[30] = f[31] = 0.0f;

    __half2* op = (__half2*)(g_featr + (size_t)e*32);
    #pragma unroll
    for (int q = 0; q < 16; q++)
        op[q] = __floats2half2_rn(f[2*q], f[2*q+1]);
}

// ---------------- helpers ----------------
__global__ void zero_ksum_kernel()
{
    float4* p = (float4*)g_ksum;
    for (int i = blockIdx.x*blockDim.x + threadIdx.x; i < NNODE*DN/4; i += gridDim.x*blockDim.x)
        p[i] = make_float4(0.f, 0.f, 0.f, 0.f);
}
__global__ void round_ksum_kernel()
{
    for (int i = blockIdx.x*blockDim.x + threadIdx.x; i < NNODE*DN; i += gridDim.x*blockDim.x)
        g_ksumh[i] = __float2half_rn(g_ksum[i]);
}
__global__ void copy_tail_kernel(float* __restrict__ out)
{
    const int S2 = ETOT, S3 = NNODE;
    const int TOT = ETOT + NNODE + ETOT;
    for (int i = blockIdx.x*blockDim.x + threadIdx.x; i < TOT; i += gridDim.x*blockDim.x) {
        float v;
        if (i < S2)           v = (float)g_eidx[i];
        else if (i < S2+S3)   v = g_maski[i - S2];
        else                  v = g_maskij[i - S2 - S3];
        out[i] = v;
    }
}

// ---------------- 4) fp16 TC GEMM: ldmatrix + BK=32, 3-stage cp.async ----------------
// A [M x KD] fp16 row-major; W = W^T [n x KD] fp16. fp32 accumulate.
// MODE 2: edge_h = (edge_h + A@W + bias)*maskij  [FLG: + fp16 shadow]
// MODE 3: node_h = (node_h + (A@W + cnt*bias)/denom)*mask_i [FLG: + shadow]
// MODE 4: edge_h init = (A@W + bias)*maskij -> out fp32 + outh fp16
// MODE 6: node precompute cat: cols<256 -> out(Ym)[z], cols>=256 -> out2(Ye)[z]
// MODE 7: fused stage-1: n0<256 -> masked softplus -> smem reduce -> atomic ksum
//                        n0==256 -> softplus -> outh(t2h)
#define MM_ST 3
#define MM_AH (128*40)                    // halfs per A stage (32 + 8 pad)
#define MM_BH (128*40)
#define MM_SMEM 66560                     // >= 3*(AH+BH)*2 = 61440, = 128*130*4

template<int KD, int MODE, int FLG>
__global__ __launch_bounds__(256, 2) void mm_tc(
    const __half* __restrict__ A, const __half* __restrict__ W,
    const float* __restrict__ bias,
    const float* __restrict__ Yi, const float* __restrict__ Zj,
    float* __restrict__ out, float* __restrict__ out2, __half* __restrict__ outh)
{
    constexpr int CH = KD / 32;           // 32-k superchunks
    extern __shared__ float smem_dyn[];
    __half* Asm = (__half*)smem_dyn;
    __half* Bsm = Asm + MM_ST*MM_AH;

    const int tid  = threadIdx.x;
    const int lane = tid & 31;
    const int wid  = tid >> 5;
    const int wm   = wid & 1;
    const int wn   = wid >> 1;

    const int rowBase = blockIdx.x * 128;
    const int n0 = blockIdx.y * 128;

    const __half* Wp = W;
    if (MODE == 6) Wp = W + (size_t)blockIdx.z * 384 * 256;

    // global->smem loader: each thread owns half a row (16 halfs = 2x16B)
    const int laR = tid >> 1, laK = (tid & 1) * 16;
    const __half* Ag = A  + (size_t)(rowBase + laR) * KD + laK;
    const __half* Wg = Wp + (size_t)(n0 + laR) * KD + laK;
    const unsigned sa = (unsigned)__cvta_generic_to_shared(Asm) + (laR*40 + laK)*2;
    const unsigned sb = (unsigned)__cvta_generic_to_shared(Bsm) + (laR*40 + laK)*2;

    // ldmatrix fragment base addresses
    const unsigned aF = (unsigned)__cvta_generic_to_shared(Asm)
        + (((wm*64 + (lane & 15))*40 + (lane >> 4)*8) * 2);
    const unsigned bF = (unsigned)__cvta_generic_to_shared(Bsm)
        + (((wn*32 + (lane & 7) + ((lane >> 4) & 1)*8)*40 + ((lane >> 3) & 1)*8) * 2);

    #pragma unroll
    for (int s = 0; s < MM_ST-1; s++) {
        if (s < CH) {
            cp16(sa + s*MM_AH*2,      Ag + s*32);
            cp16(sa + s*MM_AH*2 + 16, Ag + s*32 + 8);
            cp16(sb + s*MM_BH*2,      Wg + s*32);
            cp16(sb + s*MM_BH*2 + 16, Wg + s*32 + 8);
        }
        CP_COMMIT();
    }

    float acc[4][4][4];
    #pragma unroll
    for (int i = 0; i < 4; i++)
        #pragma unroll
        for (int j = 0; j < 4; j++)
            #pragma unroll
            for (int q = 0; q < 4; q++) acc[i][j][q] = 0.0f;

    #pragma unroll 1
    for (int c = 0; c < CH; c++) {
        CP_WAIT1();
        __syncthreads();

        if (c + MM_ST-1 < CH) {
            const int slot = (c + MM_ST-1) % MM_ST;
            const int cc = c + MM_ST-1;
            cp16(sa + slot*MM_AH*2,      Ag + cc*32);
            cp16(sa + slot*MM_AH*2 + 16, Ag + cc*32 + 8);
            cp16(sb + slot*MM_BH*2,      Wg + cc*32);
            cp16(sb + slot*MM_BH*2 + 16, Wg + cc*32 + 8);
        }
        CP_COMMIT();

        const unsigned aS = aF + (c % MM_ST)*MM_AH*2;
        const unsigned bS = bF + (c % MM_ST)*MM_BH*2;

        #pragma unroll
        for (int kk = 0; kk < 2; kk++) {
            const int kb = kk * 16;
            unsigned a[4][4], bq[4][2];
            #pragma unroll
            for (int mt = 0; mt < 4; mt++)
                ldsm4(a[mt][0], a[mt][1], a[mt][2], a[mt][3],
                      aS + (mt*16*40 + kb)*2);
            #pragma unroll
            for (int np = 0; np < 2; np++)
                ldsm4(bq[2*np][0], bq[2*np][1], bq[2*np+1][0], bq[2*np+1][1],
                      bS + (np*16*40 + kb)*2);
            #pragma unroll
            for (int mt = 0; mt < 4; mt++)
                #pragma unroll
                for (int nt = 0; nt < 4; nt++)
                    mma16(acc[mt][nt], a[mt], bq[nt]);
        }
    }

    // ---------------- epilogue ----------------
    float* sred = smem_dyn;
    const bool mred = (MODE == 7) && (n0 < 256);
    if (mred) __syncthreads();            // uniform per block

    #pragma unroll
    for (int mt = 0; mt < 4; mt++) {
        #pragma unroll
        for (int h = 0; h < 2; h++) {
            const int r = wm*64 + mt*16 + (lane >> 2) + h*8;
            const int grow = rowBase + r;

            const float* yip = nullptr; const float* zjp = nullptr;
            float mij = 0.f, dn = 1.f, mi = 0.f, cn = 0.f;
            const float* nhp = nullptr; const float* ehp = nullptr;
            if (MODE == 7) {
                int nlin = grow / KNB;
                int b = nlin >> 11;
                int jlin = b*NN + g_eidx[grow];
                if (n0 < 256) {
                    yip = Yi + (size_t)nlin * DN + n0;
                    zjp = Yi + (size_t)NNODE*DN + (size_t)jlin * DN + n0;
                    mij = g_maskij[grow];
                } else {
                    yip = Zj + (size_t)nlin * DE;
                    zjp = Zj + (size_t)NNODE*DE + (size_t)jlin * DE;
                }
            } else if (MODE == 2) {
                mij = g_maskij[grow];
                ehp = g_edgeh + (size_t)grow * DE + n0;
            } else if (MODE == 3) {
                dn = g_denom[grow]; mi = g_maski[grow]; cn = g_cnt[grow];
                nhp = g_nodeh + (size_t)grow * DN + n0;
            } else if (MODE == 4) {
                mij = g_maskij[grow];
            }

            #pragma unroll
            for (int nt = 0; nt < 4; nt++) {
                const int c0 = wn*32 + nt*8 + 2*(lane & 3);
                float v0 = acc[mt][nt][h*2 + 0];
                float v1 = acc[mt][nt][h*2 + 1];
                if (MODE == 6) {
                    float* op;
                    if (n0 < 256) op = out  + (size_t)blockIdx.z*NNODE*DN + (size_t)grow*DN + n0;
                    else          op = out2 + (size_t)blockIdx.z*NNODE*DE + (size_t)grow*DE + (n0-256);
                    *(float2*)(op + c0) = make_float2(v0, v1);
                } else if (MODE == 7) {
                    float2 bsv = *(const float2*)(bias + n0 + c0);
                    float2 yv  = *(const float2*)(yip + c0);
                    float2 zv  = *(const float2*)(zjp + c0);
                    if (n0 < 256) {
                        v0 = softplus_f(v0 + bsv.x + yv.x + zv.x) * mij;
                        v1 = softplus_f(v1 + bsv.y + yv.y + zv.y) * mij;
                        sred[r*130 + c0]     = v0;
                        sred[r*130 + c0 + 1] = v1;
                    } else {
                        v0 = softplus_f(v0 + bsv.x + yv.x + zv.x);
                        v1 = softplus_f(v1 + bsv.y + yv.y + zv.y);
                        *(__half2*)(outh + (size_t)grow*DE + c0) = __floats2half2_rn(v0, v1);
                    }
                } else if (MODE == 4) {
                    float2 bsv = *(const float2*)(bias + n0 + c0);
                    v0 = (v0 + bsv.x) * mij;
                    v1 = (v1 + bsv.y) * mij;
                    *(float2*)(out + (size_t)grow*DE + n0 + c0) = make_float2(v0, v1);
                    *(__half2*)(outh + (size_t)grow*DE + n0 + c0) = __floats2half2_rn(v0, v1);
                } else if (MODE == 2) {
                    float2 bsv = *(const float2*)(bias + n0 + c0);
                    float2 ev  = *(const float2*)(ehp + c0);
                    v0 = (ev.x + v0 + bsv.x) * mij;
                    v1 = (ev.y + v1 + bsv.y) * mij;
                    *(float2*)(out + (size_t)grow*DE + n0 + c0) = make_float2(v0, v1);
                    if (FLG) *(__half2*)(outh + (size_t)grow*DE + n0 + c0) = __floats2half2_rn(v0, v1);
                } else { // MODE 3
                    float2 bsv = *(const float2*)(bias + n0 + c0);
                    float2 nv  = *(const float2*)(nhp + c0);
                    v0 = (nv.x + (v0 + cn*bsv.x) / dn) * mi;
                    v1 = (nv.y + (v1 + cn*bsv.y) / dn) * mi;
                    *(float2*)(out + (size_t)grow*DN + n0 + c0) = make_float2(v0, v1);
                    if (FLG) *(__half2*)(outh + (size_t)grow*DN + n0 + c0) = __floats2half2_rn(v0, v1);
                }
            }
        }
    }

    if (mred) {
        __syncthreads();
        if (tid < 128) {
            const int c = tid;
            const int nfirst = rowBase / KNB;
            const int nlast  = (rowBase + 127) / KNB;
            for (int n = nfirst; n <= nlast; n++) {
                int r0 = n*KNB - rowBase;
                int r1 = r0 + KNB;
                r0 = r0 < 0 ? 0 : r0;
                r1 = r1 > 128 ? 128 : r1;
                float s = 0.0f;
                for (int r = r0; r < r1; r++) s += sred[r*130 + c];
                atomicAdd(&g_ksum[(size_t)n*DN + n0 + c], s);
            }
        }
    }
}

// ---------------- launch ----------------
extern "C" void kernel_launch(void* const* d_in, const int* in_sizes, int n_in,
                              void* d_out, int out_size)
{
    const float* X    = (const float*)d_in[0];
    const int*   C    = (const int*)  d_in[1];
    const float* Wn   = (const float*)d_in[2];
    const float* bn   = (const float*)d_in[3];
    const float* We   = (const float*)d_in[4];
    const float* be   = (const float*)d_in[5];
    const float* Wm1  = (const float*)d_in[6];
    const float* bm1  = (const float*)d_in[7];
    const float* Wm2  = (const float*)d_in[8];
    const float* bm2  = (const float*)d_in[9];
    const float* Wue1 = (const float*)d_in[10];
    const float* bue1 = (const float*)d_in[11];
    const float* Wue2 = (const float*)d_in[12];
    const float* bue2 = (const float*)d_in[13];
    float* out = (float*)d_out;

    cudaFuncSetAttribute(mm_tc<32, 4,0>, cudaFuncAttributeMaxDynamicSharedMemorySize, MM_SMEM);
    cudaFuncSetAttribute(mm_tc<256,6,0>, cudaFuncAttributeMaxDynamicSharedMemorySize, MM_SMEM);
    cudaFuncSetAttribute(mm_tc<128,7,0>, cudaFuncAttributeMaxDynamicSharedMemorySize, MM_SMEM);
    cudaFuncSetAttribute(mm_tc<256,3,1>, cudaFuncAttributeMaxDynamicSharedMemorySize, MM_SMEM);
    cudaFuncSetAttribute(mm_tc<256,3,0>, cudaFuncAttributeMaxDynamicSharedMemorySize, MM_SMEM);
    cudaFuncSetAttribute(mm_tc<128,2,1>, cudaFuncAttributeMaxDynamicSharedMemorySize, MM_SMEM);
    cudaFuncSetAttribute(mm_tc<128,2,0>, cudaFuncAttributeMaxDynamicSharedMemorySize, MM_SMEM);

    float*  Ym;  cudaGetSymbolAddress((void**)&Ym,  g_Ym);
    float*  Ye;  cudaGetSymbolAddress((void**)&Ye,  g_Ye);
    __half* T2;  cudaGetSymbolAddress((void**)&T2,  g_t2h);
    float*  Eh;  cudaGetSymbolAddress((void**)&Eh,  g_edgeh);
    __half* Ehr; cudaGetSymbolAddress((void**)&Ehr, g_edgehr);
    float*  Nh;  cudaGetSymbolAddress((void**)&Nh,  g_nodeh);
    __half* Nhr; cudaGetSymbolAddress((void**)&Nhr, g_nodehr);
    __half* Ksh; cudaGetSymbolAddress((void**)&Ksh, g_ksumh);
    __half* Wh;  cudaGetSymbolAddress((void**)&Wh,  g_Wh);
    __half* Ft;  cudaGetSymbolAddress((void**)&Ft,  g_featr);
    float*  Bc;  cudaGetSymbolAddress((void**)&Bc,  g_bcat);

    round_w_kernel<<<512, 256>>>(Wm1, Wue1, Wm2, Wue2, We, bm1, bue1);
    frame_kernel<<<NNODE/8, 256>>>(X, C, Wn, bn);
    knn_kernel<<<NNODE/4, 128>>>(C);
    feat_kernel<<<ETOT/128, 128>>>();
    // edge_h init as GEMM: feat[ETOT x 32] @ We[32 x 128]
    mm_tc<32, 4, 0><<<dim3(ETOT/128, 1), 256, MM_SMEM>>>(
        Ft, Wh + WT_WE, be, nullptr, nullptr, Eh, nullptr, Ehr);

    for (int l = 0; l < NL; l++) {
        const __half* W1cat = Wh + WT_CAT + (size_t)l*2*384*256;
        const __half* W1e   = Wh + WT_E1  + (size_t)l*384*128;
        const __half* Wm2l  = Wh + WT_M2  + (size_t)l*256*256;
        const __half* Wue2l = Wh + WT_UE2 + (size_t)l*128*128;
        const bool last = (l == NL-1);

        zero_ksum_kernel<<<256, 256>>>();
        // node precompute (Ym + Ye fused)
        mm_tc<256, 6, 0><<<dim3(NNODE/128, 3, 2), 256, MM_SMEM>>>(
            Nhr, W1cat, nullptr, nullptr, nullptr, Ym, Ye, nullptr);
        // fused stage-1: m-path (n0<256, ksum) + e-path (n0=256, t2h)
        mm_tc<128, 7, 0><<<dim3(ETOT/128, 3), 256, MM_SMEM>>>(
            Ehr, W1e, Bc + l*384, Ym, Ye, nullptr, nullptr, T2);
        round_ksum_kernel<<<256, 256>>>();
        // node update
        if (!last)
            mm_tc<256, 3, 1><<<dim3(NNODE/128, 2), 256, MM_SMEM>>>(
                Ksh, Wm2l, bm2 + l*DN, nullptr, nullptr, Nh, nullptr, Nhr);
        else
            mm_tc<256, 3, 0><<<dim3(NNODE/128, 2), 256, MM_SMEM>>>(
                Ksh, Wm2l, bm2 + l*DN, nullptr, nullptr, out, nullptr, nullptr);
        // edge update
        if (!last)
            mm_tc<128, 2, 1><<<dim3(ETOT/128, 1), 256, MM_SMEM>>>(
                T2, Wue2l, bue2 + l*DE, nullptr, nullptr, Eh, nullptr, Ehr);
        else
            mm_tc<128, 2, 0><<<dim3(ETOT/128, 1), 256, MM_SMEM>>>(
                T2, Wue2l, bue2 + l*DE, nullptr, nullptr, out + S0OUT, nullptr, nullptr);
    }

    copy_tail_kernel<<<512, 256>>>(out + S0OUT + S1OUT);
}

// round 9
// speedup vs baseline: 1.1381x; 1.1381x over previous
#include <cuda_runtime.h>
#include <cuda_fp16.h>
#include <math.h>

// ---------------- problem constants ----------------
#define BB   2
#define NN   2048
#define KNB  30
#define DN   256
#define DE   128
#define NL   3
#define NFI  12
#define EFI  28
#define ETOT (BB*NN*KNB)  // 122880
#define NNODE (BB*NN)     // 4096
#define EPSF 1e-6f
#define BIGF 1e9f
#define FLTMAX 3.402823466e38f

#define S0OUT (NNODE*DN)
#define S1OUT (ETOT*DE)

// ---------------- scratch ----------------
__device__ float  g_nodeh [NNODE*DN];
__device__ __half g_nodehr[NNODE*DN];
__device__ float  g_edgeh [ETOT*DE];
__device__ __half g_edgehr[ETOT*DE];
__device__ int    g_eidx [ETOT];
__device__ float  g_maski[NNODE];
__device__ float  g_maskij[ETOT];
__device__ float  g_denom[NNODE];
__device__ float  g_cnt  [NNODE];
__device__ float  g_R  [NNODE*9];
__device__ float  g_Xc [NNODE*3];
__device__ __half g_t2h[ETOT*DE];
__device__ float  g_Ym [2*NNODE*DN];
__device__ float  g_Ye [2*NNODE*DE];
__device__ float  g_ksum [NNODE*DN];       // fp32 atomic accum
__device__ __half g_ksumh[NNODE*DN];       // rounded copy (MMA input)
__device__ __half g_featr[ETOT*32];

// transposed fp16 weight arena: W^T[n][k]
#define WT_CAT 0
#define WT_E1M (3*2*384*256)            // 589824
#define WT_E1E (WT_E1M + 3*256*128)     // 688128
#define WT_M2  (WT_E1E + 3*128*128)     // 737280
#define WT_UE2 (WT_M2  + 3*256*256)     // 933888
#define WT_WE  (WT_UE2 + 3*128*128)     // 983040
#define WT_TOT (WT_WE  + 128*32)        // 987136
__device__ __half g_Wh[WT_TOT];

__device__ __forceinline__ float softplus_f(float x) {
    return fmaxf(x, 0.0f) + log1pf(expf(-fabsf(x)));
}
__device__ __forceinline__ void mma16(float* c, const unsigned* a, const unsigned* b) {
    asm volatile(
        "mma.sync.aligned.m16n8k16.row.col.f32.f16.f16.f32 "
        "{%0,%1,%2,%3},{%4,%5,%6,%7},{%8,%9},{%0,%1,%2,%3};"
        : "+f"(c[0]), "+f"(c[1]), "+f"(c[2]), "+f"(c[3])
        : "r"(a[0]), "r"(a[1]), "r"(a[2]), "r"(a[3]), "r"(b[0]), "r"(b[1]));
}
__device__ __forceinline__ void ldsm4(unsigned& r0, unsigned& r1, unsigned& r2, unsigned& r3,
                                      unsigned addr) {
    asm volatile("ldmatrix.sync.aligned.m8n8.x4.shared.b16 {%0,%1,%2,%3}, [%4];"
        : "=r"(r0), "=r"(r1), "=r"(r2), "=r"(r3) : "r"(addr));
}
__device__ __forceinline__ void cp16(unsigned dst, const void* src) {
    asm volatile("cp.async.cg.shared.global [%0], [%1], 16;" :: "r"(dst), "l"(src));
}
#define CP_COMMIT() asm volatile("cp.async.commit_group;")
#define CP_WAIT2()  asm volatile("cp.async.wait_group 2;")

// ---------------- 0) round + transpose + repack all weights to fp16 ----------------
__global__ void round_w_kernel(const float* __restrict__ Wm1, const float* __restrict__ Wue1,
                               const float* __restrict__ Wm2, const float* __restrict__ Wue2,
                               const float* __restrict__ We)
{
    for (int i = blockIdx.x*blockDim.x + threadIdx.x; i < WT_TOT; i += gridDim.x*blockDim.x) {
        float v;
        if (i < WT_E1M) {                       // [l][z][n<384][k<256]
            int l = i / 196608, r = i % 196608;
            int z = r / 98304,  q = r % 98304;
            int n = q / 256,    k = q % 256;
            v = (n < 256) ? Wm1 [((size_t)l*640 + z*256 + k)*256 + n]
                          : Wue1[((size_t)l*640 + z*256 + k)*128 + (n - 256)];
        } else if (i < WT_E1E) {                // [l][n<256][k<128]
            int r = i - WT_E1M;
            int l = r / 32768, q = r % 32768;
            int n = q / 128,   k = q % 128;
            v = Wm1[((size_t)l*640 + 512 + k)*256 + n];
        } else if (i < WT_M2) {                 // [l][n<128][k<128]
            int r = i - WT_E1E;
            int l = r / 16384, q = r % 16384;
            int n = q / 128,   k = q % 128;
            v = Wue1[((size_t)l*640 + 512 + k)*128 + n];
        } else if (i < WT_UE2) {                // [l][n<256][k<256]
            int r = i - WT_M2;
            int l = r / 65536, q = r % 65536;
            int n = q / 256,   k = q % 256;
            v = Wm2[((size_t)l*256 + k)*256 + n];
        } else if (i < WT_WE) {                 // [l][n<128][k<128]
            int r = i - WT_UE2;
            int l = r / 16384, q = r % 16384;
            int n = q / 128,   k = q % 128;
            v = Wue2[((size_t)l*128 + k)*128 + n];
        } else {                                // [n<128][k<32]
            int r = i - WT_WE;
            int n = r / 32, k = r % 32;
            v = (k < EFI) ? We[k*128 + n] : 0.0f;
        }
        g_Wh[i] = __float2half_rn(v);
    }
}

// ---------------- 1) per-node frame, features, node_h init ----------------
__global__ void frame_kernel(const float* __restrict__ X, const int* __restrict__ C,
                             const float* __restrict__ Wn, const float* __restrict__ bn)
{
    __shared__ float s_feat[8][12];
    __shared__ float s_mask[8];
    int warp = threadIdx.x >> 5;
    int lane = threadIdx.x & 31;
    int nlin = blockIdx.x * 8 + warp;

    if (lane == 0) {
        const float* xr = X + (size_t)nlin * 12;
        float Na[3], CA[3], Ct[3], Oa[3];
        #pragma unroll
        for (int d = 0; d < 3; d++) { Na[d]=xr[d]; CA[d]=xr[3+d]; Ct[d]=xr[6+d]; Oa[d]=xr[9+d]; }
        #pragma unroll
        for (int d = 0; d < 3; d++) {
            float s = __fadd_rn(__fadd_rn(__fadd_rn(Na[d], CA[d]), Ct[d]), Oa[d]);
            g_Xc[nlin*3 + d] = __fmul_rn(s, 0.25f);
        }
        float b1[3], b2[3], b3[3], v0[3];
        #pragma unroll
        for (int d = 0; d < 3; d++) {
            b1[d] = CA[d] - Na[d];
            b2[d] = Ct[d] - CA[d];
            b3[d] = Oa[d] - Ct[d];
            v0[d] = Na[d] - CA[d];
        }
        float nb2 = sqrtf(b2[0]*b2[0] + b2[1]*b2[1] + b2[2]*b2[2]);
        float u[3];
        #pragma unroll
        for (int d = 0; d < 3; d++) u[d] = b2[d] / (nb2 + EPSF);
        float dotv = v0[0]*u[0] + v0[1]*u[1] + v0[2]*u[2];
        float t[3];
        #pragma unroll
        for (int d = 0; d < 3; d++) t[d] = v0[d] - dotv * u[d];
        float nt = sqrtf(t[0]*t[0] + t[1]*t[1] + t[2]*t[2]);
        float v[3];
        #pragma unroll
        for (int d = 0; d < 3; d++) v[d] = t[d] / (nt + EPSF);
        float w[3];
        w[0] = u[1]*v[2] - u[2]*v[1];
        w[1] = u[2]*v[0] - u[0]*v[2];
        w[2] = u[0]*v[1] - u[1]*v[0];
        #pragma unroll
        for (int d = 0; d < 3; d++) {
            g_R[nlin*9 + d*3 + 0] = u[d];
            g_R[nlin*9 + d*3 + 1] = v[d];
            g_R[nlin*9 + d*3 + 2] = w[d];
        }
        float nb1 = sqrtf(b1[0]*b1[0] + b1[1]*b1[1] + b1[2]*b1[2]);
        float nb3 = sqrtf(b3[0]*b3[0] + b3[1]*b3[1] + b3[2]*b3[2]);
        #pragma unroll
        for (int d = 0; d < 3; d++) {
            s_feat[warp][0 + d] = b1[d] / (nb1 + EPSF);
            s_feat[warp][4 + d] = b2[d] / (nb2 + EPSF);
            s_feat[warp][8 + d] = b3[d] / (nb3 + EPSF);
        }
        s_feat[warp][3]  = logf(nb1 + EPSF);
        s_feat[warp][7]  = logf(nb2 + EPSF);
        s_feat[warp][11] = logf(nb3 + EPSF);
        float mk = (C[nlin] > 0) ? 1.0f : 0.0f;
        s_mask[warp] = mk;
        g_maski[nlin] = mk;
    }
    __syncwarp();

    float f[12];
    #pragma unroll
    for (int i = 0; i < 12; i++) f[i] = s_feat[warp][i];
    float mk = s_mask[warp];
    #pragma unroll
    for (int r = 0; r < 8; r++) {
        int c = lane + r * 32;
        float acc = bn[c];
        #pragma unroll
        for (int ff = 0; ff < NFI; ff++) acc += f[ff] * Wn[ff*DN + c];
        float v = acc * mk;
        g_nodeh [(size_t)nlin*DN + c] = v;
        g_nodehr[(size_t)nlin*DN + c] = __float2half_rn(v);
    }
}

// ---------------- 2) kNN: warp-per-node, exact semantics ----------------
__global__ __launch_bounds__(128) void knn_kernel(const int* __restrict__ C)
{
    __shared__ float s_d2[4][NN];
    int wid = threadIdx.x >> 5;
    int lane = threadIdx.x & 31;
    int nlin = blockIdx.x * 4 + wid;
    int b = nlin >> 11;
    int n = nlin & (NN - 1);

    float xi0 = g_Xc[nlin*3+0], xi1 = g_Xc[nlin*3+1], xi2 = g_Xc[nlin*3+2];
    const int* Cb = C + b*NN;
    for (int j = lane; j < NN; j += 32) {
        float dx = __fadd_rn(xi0, -g_Xc[(size_t)(b*NN + j)*3 + 0]);
        float dy = __fadd_rn(xi1, -g_Xc[(size_t)(b*NN + j)*3 + 1]);
        float dz = __fadd_rn(xi2, -g_Xc[(size_t)(b*NN + j)*3 + 2]);
        float d2 = __fadd_rn(__fadd_rn(__fmul_rn(dx,dx), __fmul_rn(dy,dy)), __fmul_rn(dz,dz));
        if (Cb[j] <= 0) d2 = __fadd_rn(d2, BIGF);
        if (j == n)     d2 = __fadd_rn(d2, BIGF);
        s_d2[wid][j] = d2;
    }
    __syncwarp();

    float mi = g_maski[nlin];
    float cnt = 0.0f;
    for (int kk = 0; kk < KNB; kk++) {
        float bv = FLTMAX; int bi = 0x7fffffff;
        #pragma unroll 4
        for (int j = lane; j < NN; j += 32) {
            float v = s_d2[wid][j];
            if (v < bv || (v == bv && j < bi)) { bv = v; bi = j; }
        }
        #pragma unroll
        for (int off = 16; off > 0; off >>= 1) {
            float v2 = __shfl_down_sync(0xffffffffu, bv, off);
            int   i2 = __shfl_down_sync(0xffffffffu, bi, off);
            if (v2 < bv || (v2 == bv && i2 < bi)) { bv = v2; bi = i2; }
        }
        bi = __shfl_sync(0xffffffffu, bi, 0);
        if (lane == 0) {
            int e = nlin*KNB + kk;
            g_eidx[e] = bi;
            float mj = (Cb[bi] > 0) ? 1.0f : 0.0f;
            float mij = mi * mj;
            g_maskij[e] = mij;
            cnt += mij;
            s_d2[wid][bi] = FLTMAX;
        }
        __syncwarp();
    }
    if (lane == 0) { g_cnt[nlin] = cnt; g_denom[nlin] = cnt + EPSF; }
}

// ---------------- 3) edge features -> g_featr (fp16, padded to 32) ----------------
__global__ __launch_bounds__(128) void feat_kernel()
{
    int e = blockIdx.x * 128 + threadIdx.x;
    int nlin = e / KNB;
    int b = nlin >> 11;
    int j = g_eidx[e];
    int jl = b*NN + j;

    float dv[3];
    #pragma unroll
    for (int d = 0; d < 3; d++) dv[d] = g_Xc[jl*3+d] - g_Xc[nlin*3+d];
    float dist = sqrtf(dv[0]*dv[0] + dv[1]*dv[1] + dv[2]*dv[2]);
    float Ri[9], Rj[9];
    #pragma unroll
    for (int q = 0; q < 9; q++) { Ri[q] = g_R[nlin*9+q]; Rj[q] = g_R[jl*9+q]; }

    float f[32];
    #pragma unroll
    for (int mc = 0; mc < 16; mc++) {
        float cm = (float)(20.0 * mc / 15.0);
        float z = (dist - cm) * 0.8f;
        f[mc] = expf(-z*z);
    }
    float inv = 1.0f / (dist + EPSF);
    #pragma unroll
    for (int c = 0; c < 3; c++) {
        float loc = Ri[0*3+c]*dv[0] + Ri[1*3+c]*dv[1] + Ri[2*3+c]*dv[2];
        f[16 + c] = loc * inv;
    }
    #pragma unroll
    for (int ee = 0; ee < 3; ee++)
        #pragma unroll
        for (int ff = 0; ff < 3; ff++)
            f[19 + ee*3 + ff] = Ri[0*3+ee]*Rj[0*3+ff] + Ri[1*3+ee]*Rj[1*3+ff] + Ri[2*3+ee]*Rj[2*3+ff];
    f[28] = f[29] = f[30] = f[31] = 0.0f;

    __half2* op = (__half2*)(g_featr + (size_t)e*32);
    #pragma unroll
    for (int q = 0; q < 16; q++)
        op[q] = __floats2half2_rn(f[2*q], f[2*q+1]);
}

// ---------------- helpers ----------------
__global__ void zero_ksum_kernel()
{
    float4* p = (float4*)g_ksum;
    for (int i = blockIdx.x*blockDim.x + threadIdx.x; i < NNODE*DN/4; i += gridDim.x*blockDim.x)
        p[i] = make_float4(0.f, 0.f, 0.f, 0.f);
}
__global__ void round_ksum_kernel()
{
    for (int i = blockIdx.x*blockDim.x + threadIdx.x; i < NNODE*DN; i += gridDim.x*blockDim.x)
        g_ksumh[i] = __float2half_rn(g_ksum[i]);
}
__global__ void copy_tail_kernel(float* __restrict__ out)
{
    const int S2 = ETOT, S3 = NNODE;
    const int TOT = ETOT + NNODE + ETOT;
    for (int i = blockIdx.x*blockDim.x + threadIdx.x; i < TOT; i += gridDim.x*blockDim.x) {
        float v;
        if (i < S2)           v = (float)g_eidx[i];
        else if (i < S2+S3)   v = g_maski[i - S2];
        else                  v = g_maskij[i - S2 - S3];
        out[i] = v;
    }
}

// ---------------- 4) fp16 TC GEMM (m16n8k16), 4-stage cp.async + ldmatrix ----------------
// A [M x KD] fp16 row-major; W = W^T [NF x KD] fp16 (n-major). Acc fp32.
// MODE 1: t2h = h(softplus(A@W + bias + Yi + Zj))
// MODE 2: edge_h = (edge_h + A@W + bias)*maskij  [FLG: + fp16 shadow]
// MODE 3: node_h = (node_h + (A@W + cnt*bias)/denom)*mask_i [FLG: + shadow]
// MODE 4: edge_h init = (A@W + bias)*maskij -> out fp32 + outh fp16
// MODE 5: m-path stage-1: masked softplus -> smem reduce -> atomic g_ksum
// MODE 6: node precompute cat: cols<256 -> out(Ym)[z], cols>=256 -> out2(Ye)[z]
#define MM_ST 4
#define MM_AS (128*24)                    // halfs per A stage (pad 16->24)
#define MM_BS (128*24)                    // halfs per B stage
#define MM_SMEM 66560                     // max(4*(AS+BS)*2 = 49152, 128*130*4)

template<int KD, int NF, int MODE, int FLG>
__global__ __launch_bounds__(256, 2) void mm_tc(
    const __half* __restrict__ A, const __half* __restrict__ W,
    const float* __restrict__ bias,
    const float* __restrict__ Yi, const float* __restrict__ Zj,
    float* __restrict__ out, float* __restrict__ out2, __half* __restrict__ outh)
{
    constexpr int CH = KD / 16;
    extern __shared__ float smem_dyn[];
    __half* Asm = (__half*)smem_dyn;
    __half* Bsm = Asm + MM_ST*MM_AS;

    const int tid  = threadIdx.x;
    const int lane = tid & 31;
    const int wid  = tid >> 5;
    const int wm   = wid & 1;
    const int wn   = wid >> 1;

    const int rowBase = blockIdx.x * 128;
    const int n0 = blockIdx.y * 128;

    const __half* Wp = W;
    if (MODE == 6) Wp = W + (size_t)blockIdx.z * 384 * 256;

    const int laR = tid >> 1, laK = (tid & 1) * 8;
    const __half* Ag = A  + (size_t)(rowBase + laR) * KD + laK;
    const __half* Wg = Wp + (size_t)(n0 + laR) * KD + laK;

    const unsigned sa = (unsigned)__cvta_generic_to_shared(Asm) + (laR*24 + laK)*2;
    const unsigned sb = (unsigned)__cvta_generic_to_shared(Bsm) + (laR*24 + laK)*2;

    // ldmatrix fragment base addresses (x4 tiles; stride 24 halfs, conflict-free)
    const unsigned aF = (unsigned)__cvta_generic_to_shared(Asm)
        + (((wm*64 + (lane & 15))*24 + (lane >> 4)*8) * 2);
    const unsigned bF = (unsigned)__cvta_generic_to_shared(Bsm)
        + (((wn*32 + (lane & 7) + ((lane >> 4) & 1)*8)*24 + ((lane >> 3) & 1)*8) * 2);

    #pragma unroll
    for (int s = 0; s < MM_ST-1; s++) {
        if (s < CH) {
            cp16(sa + s*MM_AS*2, Ag + s*16);
            cp16(sb + s*MM_BS*2, Wg + s*16);
        }
        CP_COMMIT();
    }

    float acc[4][4][4];
    #pragma unroll
    for (int i = 0; i < 4; i++)
        #pragma unroll
        for (int j = 0; j < 4; j++)
            #pragma unroll
            for (int q = 0; q < 4; q++) acc[i][j][q] = 0.0f;

    #pragma unroll 1
    for (int c = 0; c < CH; c++) {
        CP_WAIT2();
        __syncthreads();

        if (c + MM_ST-1 < CH) {
            const int slot = (c + MM_ST-1) & (MM_ST-1);
            const int cc = c + MM_ST-1;
            cp16(sa + slot*MM_AS*2, Ag + cc*16);
            cp16(sb + slot*MM_BS*2, Wg + cc*16);
        }
        CP_COMMIT();

        const unsigned aS = aF + (c & (MM_ST-1))*MM_AS*2;
        const unsigned bS = bF + (c & (MM_ST-1))*MM_BS*2;

        unsigned a[4][4], bq[4][2];
        #pragma unroll
        for (int mt = 0; mt < 4; mt++)
            ldsm4(a[mt][0], a[mt][1], a[mt][2], a[mt][3], aS + (mt*16*24)*2);
        #pragma unroll
        for (int np = 0; np < 2; np++)
            ldsm4(bq[2*np][0], bq[2*np][1], bq[2*np+1][0], bq[2*np+1][1],
                  bS + (np*16*24)*2);
        #pragma unroll
        for (int mt = 0; mt < 4; mt++)
            #pragma unroll
            for (int nt = 0; nt < 4; nt++)
                mma16(acc[mt][nt], a[mt], bq[nt]);
    }

    // ---------------- epilogue ----------------
    float* sred = smem_dyn;
    if (MODE == 5) __syncthreads();

    #pragma unroll
    for (int mt = 0; mt < 4; mt++) {
        #pragma unroll
        for (int h = 0; h < 2; h++) {
            const int r = wm*64 + mt*16 + (lane >> 2) + h*8;
            const int grow = rowBase + r;

            const float* yip = nullptr; const float* zjp = nullptr;
            float mij = 0.f, dn = 1.f, mi = 0.f, cn = 0.f;
            const float* nhp = nullptr; const float* ehp = nullptr;
            if (MODE == 1 || MODE == 5) {
                int nlin = grow / KNB;
                int b = nlin >> 11;
                yip = Yi + (size_t)nlin * NF + n0;
                zjp = Zj + (size_t)(b*NN + g_eidx[grow]) * NF + n0;
                if (MODE == 5) mij = g_maskij[grow];
            } else if (MODE == 2) {
                mij = g_maskij[grow];
                ehp = g_edgeh + (size_t)grow * DE + n0;
            } else if (MODE == 3) {
                dn = g_denom[grow]; mi = g_maski[grow]; cn = g_cnt[grow];
                nhp = g_nodeh + (size_t)grow * DN + n0;
            } else if (MODE == 4) {
                mij = g_maskij[grow];
            }

            #pragma unroll
            for (int nt = 0; nt < 4; nt++) {
                const int c0 = wn*32 + nt*8 + 2*(lane & 3);
                float v0 = acc[mt][nt][h*2 + 0];
                float v1 = acc[mt][nt][h*2 + 1];
                if (MODE == 6) {
                    float* op;
                    if (n0 < 256) op = out  + (size_t)blockIdx.z*NNODE*DN + (size_t)grow*DN + n0;
                    else          op = out2 + (size_t)blockIdx.z*NNODE*DE + (size_t)grow*DE + (n0-256);
                    *(float2*)(op + c0) = make_float2(v0, v1);
                } else if (MODE == 1) {
                    float2 bsv = *(const float2*)(bias + n0 + c0);
                    float2 yv  = *(const float2*)(yip + c0);
                    float2 zv  = *(const float2*)(zjp + c0);
                    v0 = softplus_f(v0 + bsv.x + yv.x + zv.x);
                    v1 = softplus_f(v1 + bsv.y + yv.y + zv.y);
                    *(__half2*)(outh + (size_t)grow*NF + n0 + c0) = __floats2half2_rn(v0, v1);
                } else if (MODE == 5) {
                    float2 bsv = *(const float2*)(bias + n0 + c0);
                    float2 yv  = *(const float2*)(yip + c0);
                    float2 zv  = *(const float2*)(zjp + c0);
                    v0 = softplus_f(v0 + bsv.x + yv.x + zv.x) * mij;
                    v1 = softplus_f(v1 + bsv.y + yv.y + zv.y) * mij;
                    sred[r*130 + c0]     = v0;
                    sred[r*130 + c0 + 1] = v1;
                } else if (MODE == 4) {
                    float2 bsv = *(const float2*)(bias + n0 + c0);
                    v0 = (v0 + bsv.x) * mij;
                    v1 = (v1 + bsv.y) * mij;
                    *(float2*)(out + (size_t)grow*NF + n0 + c0) = make_float2(v0, v1);
                    *(__half2*)(outh + (size_t)grow*NF + n0 + c0) = __floats2half2_rn(v0, v1);
                } else if (MODE == 2) {
                    float2 bsv = *(const float2*)(bias + n0 + c0);
                    float2 ev  = *(const float2*)(ehp + c0);
                    v0 = (ev.x + v0 + bsv.x) * mij;
                    v1 = (ev.y + v1 + bsv.y) * mij;
                    *(float2*)(out + (size_t)grow*NF + n0 + c0) = make_float2(v0, v1);
                    if (FLG) *(__half2*)(outh + (size_t)grow*NF + n0 + c0) = __floats2half2_rn(v0, v1);
                } else { // MODE 3
                    float2 bsv = *(const float2*)(bias + n0 + c0);
                    float2 nv  = *(const float2*)(nhp + c0);
                    v0 = (nv.x + (v0 + cn*bsv.x) / dn) * mi;
                    v1 = (nv.y + (v1 + cn*bsv.y) / dn) * mi;
                    *(float2*)(out + (size_t)grow*NF + n0 + c0) = make_float2(v0, v1);
                    if (FLG) *(__half2*)(outh + (size_t)grow*NF + n0 + c0) = __floats2half2_rn(v0, v1);
                }
            }
        }
    }

    if (MODE == 5) {
        __syncthreads();
        if (tid < 128) {
            const int c = tid;
            const int nfirst = rowBase / KNB;
            const int nlast  = (rowBase + 127) / KNB;
            for (int n = nfirst; n <= nlast; n++) {
                int r0 = n*KNB - rowBase;
                int r1 = r0 + KNB;
                r0 = r0 < 0 ? 0 : r0;
                r1 = r1 > 128 ? 128 : r1;
                float s = 0.0f;
                for (int r = r0; r < r1; r++) s += sred[r*130 + c];
                atomicAdd(&g_ksum[(size_t)n*DN + n0 + c], s);
            }
        }
    }
}

// ---------------- launch ----------------
extern "C" void kernel_launch(void* const* d_in, const int* in_sizes, int n_in,
                              void* d_out, int out_size)
{
    const float* X    = (const float*)d_in[0];
    const int*   C    = (const int*)  d_in[1];
    const float* Wn   = (const float*)d_in[2];
    const float* bn   = (const float*)d_in[3];
    const float* We   = (const float*)d_in[4];
    const float* be   = (const float*)d_in[5];
    const float* Wm1  = (const float*)d_in[6];
    const float* bm1  = (const float*)d_in[7];
    const float* Wm2  = (const float*)d_in[8];
    const float* bm2  = (const float*)d_in[9];
    const float* Wue1 = (const float*)d_in[10];
    const float* bue1 = (const float*)d_in[11];
    const float* Wue2 = (const float*)d_in[12];
    const float* bue2 = (const float*)d_in[13];
    float* out = (float*)d_out;

    cudaFuncSetAttribute(mm_tc<32, 128,4,0>, cudaFuncAttributeMaxDynamicSharedMemorySize, MM_SMEM);
    cudaFuncSetAttribute(mm_tc<256,384,6,0>, cudaFuncAttributeMaxDynamicSharedMemorySize, MM_SMEM);
    cudaFuncSetAttribute(mm_tc<128,256,5,0>, cudaFuncAttributeMaxDynamicSharedMemorySize, MM_SMEM);
    cudaFuncSetAttribute(mm_tc<128,128,1,0>, cudaFuncAttributeMaxDynamicSharedMemorySize, MM_SMEM);
    cudaFuncSetAttribute(mm_tc<256,256,3,1>, cudaFuncAttributeMaxDynamicSharedMemorySize, MM_SMEM);
    cudaFuncSetAttribute(mm_tc<256,256,3,0>, cudaFuncAttributeMaxDynamicSharedMemorySize, MM_SMEM);
    cudaFuncSetAttribute(mm_tc<128,128,2,1>, cudaFuncAttributeMaxDynamicSharedMemorySize, MM_SMEM);
    cudaFuncSetAttribute(mm_tc<128,128,2,0>, cudaFuncAttributeMaxDynamicSharedMemorySize, MM_SMEM);

    float*  Ym;  cudaGetSymbolAddress((void**)&Ym,  g_Ym);
    float*  Ye;  cudaGetSymbolAddress((void**)&Ye,  g_Ye);
    __half* T2;  cudaGetSymbolAddress((void**)&T2,  g_t2h);
    float*  Eh;  cudaGetSymbolAddress((void**)&Eh,  g_edgeh);
    __half* Ehr; cudaGetSymbolAddress((void**)&Ehr, g_edgehr);
    float*  Nh;  cudaGetSymbolAddress((void**)&Nh,  g_nodeh);
    __half* Nhr; cudaGetSymbolAddress((void**)&Nhr, g_nodehr);
    __half* Ksh; cudaGetSymbolAddress((void**)&Ksh, g_ksumh);
    __half* Wh;  cudaGetSymbolAddress((void**)&Wh,  g_Wh);
    __half* Ft;  cudaGetSymbolAddress((void**)&Ft,  g_featr);

    round_w_kernel<<<512, 256>>>(Wm1, Wue1, Wm2, Wue2, We);
    frame_kernel<<<NNODE/8, 256>>>(X, C, Wn, bn);
    knn_kernel<<<NNODE/4, 128>>>(C);
    feat_kernel<<<ETOT/128, 128>>>();
    // edge_h init as GEMM: feat[ETOT x 32] @ We[32 x 128]
    mm_tc<32, 128, 4, 0><<<dim3(ETOT/128, 1), 256, MM_SMEM>>>(
        Ft, Wh + WT_WE, be, nullptr, nullptr, Eh, nullptr, Ehr);

    for (int l = 0; l < NL; l++) {
        const __half* W1cat = Wh + WT_CAT + (size_t)l*2*384*256;
        const __half* W1me  = Wh + WT_E1M + (size_t)l*256*128;
        const __half* W1ue  = Wh + WT_E1E + (size_t)l*128*128;
        const __half* Wm2l  = Wh + WT_M2  + (size_t)l*256*256;
        const __half* Wue2l = Wh + WT_UE2 + (size_t)l*128*128;
        const bool last = (l == NL-1);

        zero_ksum_kernel<<<256, 256>>>();
        // node precompute (Ym + Ye fused)
        mm_tc<256, 384, 6, 0><<<dim3(NNODE/128, 3, 2), 256, MM_SMEM>>>(
            Nhr, W1cat, nullptr, nullptr, nullptr, Ym, Ye, nullptr);
        // m-path stage-1 with fused masked k-reduction into g_ksum
        mm_tc<128, 256, 5, 0><<<dim3(ETOT/128, 2), 256, MM_SMEM>>>(
            Ehr, W1me, bm1 + l*DN, Ym, Ym + (size_t)NNODE*DN, nullptr, nullptr, nullptr);
        // e-path stage-1 -> t2h
        mm_tc<128, 128, 1, 0><<<dim3(ETOT/128, 1), 256, MM_SMEM>>>(
            Ehr, W1ue, bue1 + l*DE, Ye, Ye + (size_t)NNODE*DE, nullptr, nullptr, T2);
        round_ksum_kernel<<<256, 256>>>();
        // node update
        if (!last)
            mm_tc<256, 256, 3, 1><<<dim3(NNODE/128, 2), 256, MM_SMEM>>>(
                Ksh, Wm2l, bm2 + l*DN, nullptr, nullptr, Nh, nullptr, Nhr);
        else
            mm_tc<256, 256, 3, 0><<<dim3(NNODE/128, 2), 256, MM_SMEM>>>(
                Ksh, Wm2l, bm2 + l*DN, nullptr, nullptr, out, nullptr, nullptr);
        // edge update
        if (!last)
            mm_tc<128, 128, 2, 1><<<dim3(ETOT/128, 1), 256, MM_SMEM>>>(
                T2, Wue2l, bue2 + l*DE, nullptr, nullptr, Eh, nullptr, Ehr);
        else
            mm_tc<128, 128, 2, 0><<<dim3(ETOT/128, 1), 256, MM_SMEM>>>(
                T2, Wue2l, bue2 + l*DE, nullptr, nullptr, out + S0OUT, nullptr, nullptr);
    }

    copy_tail_kernel<<<512, 256>>>(out + S0OUT + S1OUT);
}

// round 11
// speedup vs baseline: 1.1723x; 1.0300x over previous
#include <cuda_runtime.h>
#include <cuda_fp16.h>
#include <math.h>

// ---------------- problem constants ----------------
#define BB   2
#define NN   2048
#define KNB  30
#define DN   256
#define DE   128
#define NL   3
#define NFI  12
#define EFI  28
#define ETOT (BB*NN*KNB)  // 122880
#define NNODE (BB*NN)     // 4096
#define EPSF 1e-6f
#define BIGF 1e9f
#define FLTMAX 3.402823466e38f

#define S0OUT (NNODE*DN)
#define S1OUT (ETOT*DE)

// ---------------- scratch ----------------
__device__ float  g_nodeh [NNODE*DN];
__device__ __half g_nodehr[NNODE*DN];
__device__ float  g_edgeh [ETOT*DE];
__device__ __half g_edgehr[ETOT*DE];
__device__ int    g_eidx [ETOT];
__device__ float  g_maski[NNODE];
__device__ float  g_maskij[ETOT];
__device__ float  g_denom[NNODE];
__device__ float  g_cnt  [NNODE];
__device__ float  g_R  [NNODE*9];
__device__ float  g_Xc [NNODE*3];
__device__ float  g_Ym [2*NNODE*DN];
__device__ float  g_Ye [2*NNODE*DE];
__device__ float  g_ksum [NNODE*DN];       // fp32 atomic accum
__device__ __half g_ksumh[NNODE*DN];       // rounded copy (MMA input)
__device__ __half g_featr[ETOT*32];

// transposed fp16 weight arena: W^T[n][k]
#define WT_CAT 0
#define WT_E1M (3*2*384*256)            // 589824
#define WT_E1E (WT_E1M + 3*256*128)     // 688128
#define WT_M2  (WT_E1E + 3*128*128)     // 737280
#define WT_UE2 (WT_M2  + 3*256*256)     // 933888
#define WT_WE  (WT_UE2 + 3*128*128)     // 983040
#define WT_TOT (WT_WE  + 128*32)        // 987136
__device__ __half g_Wh[WT_TOT];

__device__ __forceinline__ float softplus_f(float x) {
    return fmaxf(x, 0.0f) + log1pf(expf(-fabsf(x)));
}
__device__ __forceinline__ void mma16(float* c, const unsigned* a, const unsigned* b) {
    asm volatile(
        "mma.sync.aligned.m16n8k16.row.col.f32.f16.f16.f32 "
        "{%0,%1,%2,%3},{%4,%5,%6,%7},{%8,%9},{%0,%1,%2,%3};"
        : "+f"(c[0]), "+f"(c[1]), "+f"(c[2]), "+f"(c[3])
        : "r"(a[0]), "r"(a[1]), "r"(a[2]), "r"(a[3]), "r"(b[0]), "r"(b[1]));
}
__device__ __forceinline__ void ldsm4(unsigned& r0, unsigned& r1, unsigned& r2, unsigned& r3,
                                      unsigned addr) {
    asm volatile("ldmatrix.sync.aligned.m8n8.x4.shared.b16 {%0,%1,%2,%3}, [%4];"
        : "=r"(r0), "=r"(r1), "=r"(r2), "=r"(r3) : "r"(addr));
}
__device__ __forceinline__ void cp16(unsigned dst, const void* src) {
    asm volatile("cp.async.cg.shared.global [%0], [%1], 16;" :: "r"(dst), "l"(src));
}
#define CP_COMMIT() asm volatile("cp.async.commit_group;")
#define CP_WAIT2()  asm volatile("cp.async.wait_group 2;")

// ---------------- 0) round + transpose + repack all weights to fp16 ----------------
__global__ void round_w_kernel(const float* __restrict__ Wm1, const float* __restrict__ Wue1,
                               const float* __restrict__ Wm2, const float* __restrict__ Wue2,
                               const float* __restrict__ We)
{
    for (int i = blockIdx.x*blockDim.x + threadIdx.x; i < WT_TOT; i += gridDim.x*blockDim.x) {
        float v;
        if (i < WT_E1M) {                       // [l][z][n<384][k<256]
            int l = i / 196608, r = i % 196608;
            int z = r / 98304,  q = r % 98304;
            int n = q / 256,    k = q % 256;
            v = (n < 256) ? Wm1 [((size_t)l*640 + z*256 + k)*256 + n]
                          : Wue1[((size_t)l*640 + z*256 + k)*128 + (n - 256)];
        } else if (i < WT_E1E) {                // [l][n<256][k<128]
            int r = i - WT_E1M;
            int l = r / 32768, q = r % 32768;
            int n = q / 128,   k = q % 128;
            v = Wm1[((size_t)l*640 + 512 + k)*256 + n];
        } else if (i < WT_M2) {                 // [l][n<128][k<128]
            int r = i - WT_E1E;
            int l = r / 16384, q = r % 16384;
            int n = q / 128,   k = q % 128;
            v = Wue1[((size_t)l*640 + 512 + k)*128 + n];
        } else if (i < WT_UE2) {                // [l][n<256][k<256]
            int r = i - WT_M2;
            int l = r / 65536, q = r % 65536;
            int n = q / 256,   k = q % 256;
            v = Wm2[((size_t)l*256 + k)*256 + n];
        } else if (i < WT_WE) {                 // [l][n<128][k<128]
            int r = i - WT_UE2;
            int l = r / 16384, q = r % 16384;
            int n = q / 128,   k = q % 128;
            v = Wue2[((size_t)l*128 + k)*128 + n];
        } else {                                // [n<128][k<32]
            int r = i - WT_WE;
            int n = r / 32, k = r % 32;
            v = (k < EFI) ? We[k*128 + n] : 0.0f;
        }
        g_Wh[i] = __float2half_rn(v);
    }
}

// ---------------- 1) per-node frame, features, node_h init ----------------
__global__ void frame_kernel(const float* __restrict__ X, const int* __restrict__ C,
                             const float* __restrict__ Wn, const float* __restrict__ bn)
{
    __shared__ float s_feat[8][12];
    __shared__ float s_mask[8];
    int warp = threadIdx.x >> 5;
    int lane = threadIdx.x & 31;
    int nlin = blockIdx.x * 8 + warp;

    if (lane == 0) {
        const float* xr = X + (size_t)nlin * 12;
        float Na[3], CA[3], Ct[3], Oa[3];
        #pragma unroll
        for (int d = 0; d < 3; d++) { Na[d]=xr[d]; CA[d]=xr[3+d]; Ct[d]=xr[6+d]; Oa[d]=xr[9+d]; }
        #pragma unroll
        for (int d = 0; d < 3; d++) {
            float s = __fadd_rn(__fadd_rn(__fadd_rn(Na[d], CA[d]), Ct[d]), Oa[d]);
            g_Xc[nlin*3 + d] = __fmul_rn(s, 0.25f);
        }
        float b1[3], b2[3], b3[3], v0[3];
        #pragma unroll
        for (int d = 0; d < 3; d++) {
            b1[d] = CA[d] - Na[d];
            b2[d] = Ct[d] - CA[d];
            b3[d] = Oa[d] - Ct[d];
            v0[d] = Na[d] - CA[d];
        }
        float nb2 = sqrtf(b2[0]*b2[0] + b2[1]*b2[1] + b2[2]*b2[2]);
        float u[3];
        #pragma unroll
        for (int d = 0; d < 3; d++) u[d] = b2[d] / (nb2 + EPSF);
        float dotv = v0[0]*u[0] + v0[1]*u[1] + v0[2]*u[2];
        float t[3];
        #pragma unroll
        for (int d = 0; d < 3; d++) t[d] = v0[d] - dotv * u[d];
        float nt = sqrtf(t[0]*t[0] + t[1]*t[1] + t[2]*t[2]);
        float v[3];
        #pragma unroll
        for (int d = 0; d < 3; d++) v[d] = t[d] / (nt + EPSF);
        float w[3];
        w[0] = u[1]*v[2] - u[2]*v[1];
        w[1] = u[2]*v[0] - u[0]*v[2];
        w[2] = u[0]*v[1] - u[1]*v[0];
        #pragma unroll
        for (int d = 0; d < 3; d++) {
            g_R[nlin*9 + d*3 + 0] = u[d];
            g_R[nlin*9 + d*3 + 1] = v[d];
            g_R[nlin*9 + d*3 + 2] = w[d];
        }
        float nb1 = sqrtf(b1[0]*b1[0] + b1[1]*b1[1] + b1[2]*b1[2]);
        float nb3 = sqrtf(b3[0]*b3[0] + b3[1]*b3[1] + b3[2]*b3[2]);
        #pragma unroll
        for (int d = 0; d < 3; d++) {
            s_feat[warp][0 + d] = b1[d] / (nb1 + EPSF);
            s_feat[warp][4 + d] = b2[d] / (nb2 + EPSF);
            s_feat[warp][8 + d] = b3[d] / (nb3 + EPSF);
        }
        s_feat[warp][3]  = logf(nb1 + EPSF);
        s_feat[warp][7]  = logf(nb2 + EPSF);
        s_feat[warp][11] = logf(nb3 + EPSF);
        float mk = (C[nlin] > 0) ? 1.0f : 0.0f;
        s_mask[warp] = mk;
        g_maski[nlin] = mk;
    }
    __syncwarp();

    float f[12];
    #pragma unroll
    for (int i = 0; i < 12; i++) f[i] = s_feat[warp][i];
    float mk = s_mask[warp];
    #pragma unroll
    for (int r = 0; r < 8; r++) {
        int c = lane + r * 32;
        float acc = bn[c];
        #pragma unroll
        for (int ff = 0; ff < NFI; ff++) acc += f[ff] * Wn[ff*DN + c];
        float v = acc * mk;
        g_nodeh [(size_t)nlin*DN + c] = v;
        g_nodehr[(size_t)nlin*DN + c] = __float2half_rn(v);
    }
}

// ---------------- 2) kNN: warp-per-node, exact semantics ----------------
__global__ __launch_bounds__(128) void knn_kernel(const int* __restrict__ C)
{
    __shared__ float s_d2[4][NN];
    int wid = threadIdx.x >> 5;
    int lane = threadIdx.x & 31;
    int nlin = blockIdx.x * 4 + wid;
    int b = nlin >> 11;
    int n = nlin & (NN - 1);

    float xi0 = g_Xc[nlin*3+0], xi1 = g_Xc[nlin*3+1], xi2 = g_Xc[nlin*3+2];
    const int* Cb = C + b*NN;
    for (int j = lane; j < NN; j += 32) {
        float dx = __fadd_rn(xi0, -g_Xc[(size_t)(b*NN + j)*3 + 0]);
        float dy = __fadd_rn(xi1, -g_Xc[(size_t)(b*NN + j)*3 + 1]);
        float dz = __fadd_rn(xi2, -g_Xc[(size_t)(b*NN + j)*3 + 2]);
        float d2 = __fadd_rn(__fadd_rn(__fmul_rn(dx,dx), __fmul_rn(dy,dy)), __fmul_rn(dz,dz));
        if (Cb[j] <= 0) d2 = __fadd_rn(d2, BIGF);
        if (j == n)     d2 = __fadd_rn(d2, BIGF);
        s_d2[wid][j] = d2;
    }
    __syncwarp();

    float mi = g_maski[nlin];
    float cnt = 0.0f;
    for (int kk = 0; kk < KNB; kk++) {
        float bv = FLTMAX; int bi = 0x7fffffff;
        #pragma unroll 4
        for (int j = lane; j < NN; j += 32) {
            float v = s_d2[wid][j];
            if (v < bv || (v == bv && j < bi)) { bv = v; bi = j; }
        }
        #pragma unroll
        for (int off = 16; off > 0; off >>= 1) {
            float v2 = __shfl_down_sync(0xffffffffu, bv, off);
            int   i2 = __shfl_down_sync(0xffffffffu, bi, off);
            if (v2 < bv || (v2 == bv && i2 < bi)) { bv = v2; bi = i2; }
        }
        bi = __shfl_sync(0xffffffffu, bi, 0);
        if (lane == 0) {
            int e = nlin*KNB + kk;
            g_eidx[e] = bi;
            float mj = (Cb[bi] > 0) ? 1.0f : 0.0f;
            float mij = mi * mj;
            g_maskij[e] = mij;
            cnt += mij;
            s_d2[wid][bi] = FLTMAX;
        }
        __syncwarp();
    }
    if (lane == 0) { g_cnt[nlin] = cnt; g_denom[nlin] = cnt + EPSF; }
}

// ---------------- 3) edge features -> g_featr (fp16, padded to 32) ----------------
__global__ __launch_bounds__(128) void feat_kernel()
{
    int e = blockIdx.x * 128 + threadIdx.x;
    int nlin = e / KNB;
    int b = nlin >> 11;
    int j = g_eidx[e];
    int jl = b*NN + j;

    float dv[3];
    #pragma unroll
    for (int d = 0; d < 3; d++) dv[d] = g_Xc[jl*3+d] - g_Xc[nlin*3+d];
    float dist = sqrtf(dv[0]*dv[0] + dv[1]*dv[1] + dv[2]*dv[2]);
    float Ri[9], Rj[9];
    #pragma unroll
    for (int q = 0; q < 9; q++) { Ri[q] = g_R[nlin*9+q]; Rj[q] = g_R[jl*9+q]; }

    float f[32];
    #pragma unroll
    for (int mc = 0; mc < 16; mc++) {
        float cm = (float)(20.0 * mc / 15.0);
        float z = (dist - cm) * 0.8f;
        f[mc] = expf(-z*z);
    }
    float inv = 1.0f / (dist + EPSF);
    #pragma unroll
    for (int c = 0; c < 3; c++) {
        float loc = Ri[0*3+c]*dv[0] + Ri[1*3+c]*dv[1] + Ri[2*3+c]*dv[2];
        f[16 + c] = loc * inv;
    }
    #pragma unroll
    for (int ee = 0; ee < 3; ee++)
        #pragma unroll
        for (int ff = 0; ff < 3; ff++)
            f[19 + ee*3 + ff] = Ri[0*3+ee]*Rj[0*3+ff] + Ri[1*3+ee]*Rj[1*3+ff] + Ri[2*3+ee]*Rj[2*3+ff];
    f[28] = f[29] = f[30] = f[31] = 0.0f;

    __half2* op = (__half2*)(g_featr + (size_t)e*32);
    #pragma unroll
    for (int q = 0; q < 16; q++)
        op[q] = __floats2half2_rn(f[2*q], f[2*q+1]);
}

// ---------------- helpers ----------------
__global__ void zero_ksum_kernel()
{
    float4* p = (float4*)g_ksum;
    for (int i = blockIdx.x*blockDim.x + threadIdx.x; i < NNODE*DN/4; i += gridDim.x*blockDim.x)
        p[i] = make_float4(0.f, 0.f, 0.f, 0.f);
}
__global__ void round_ksum_kernel()
{
    for (int i = blockIdx.x*blockDim.x + threadIdx.x; i < NNODE*DN; i += gridDim.x*blockDim.x)
        g_ksumh[i] = __float2half_rn(g_ksum[i]);
}
__global__ void copy_tail_kernel(float* __restrict__ out)
{
    const int S2 = ETOT, S3 = NNODE;
    const int TOT = ETOT + NNODE + ETOT;
    for (int i = blockIdx.x*blockDim.x + threadIdx.x; i < TOT; i += gridDim.x*blockDim.x) {
        float v;
        if (i < S2)           v = (float)g_eidx[i];
        else if (i < S2+S3)   v = g_maski[i - S2];
        else                  v = g_maskij[i - S2 - S3];
        out[i] = v;
    }
}

// ---------------- 4) fp16 TC GEMM (m16n8k16), 4-stage cp.async + ldmatrix ----------------
// MODE 3: node_h = (node_h + (A@W + cnt*bias)/denom)*mask_i [FLG: + shadow]
// MODE 4: edge_h init = (A@W + bias)*maskij -> out fp32 + outh fp16
// MODE 5: m-path stage-1: masked softplus -> smem reduce -> atomic g_ksum
// MODE 6: node precompute cat: cols<256 -> out(Ym)[z], cols>=256 -> out2(Ye)[z]
#define MM_ST 4
#define MM_AS (128*24)                    // halfs per A stage (pad 16->24)
#define MM_BS (128*24)                    // halfs per B stage
#define MM_SMEM 66560                     // max(4*(AS+BS)*2 = 49152, 128*130*4)

template<int KD, int NF, int MODE, int FLG>
__global__ __launch_bounds__(256, 2) void mm_tc(
    const __half* __restrict__ A, const __half* __restrict__ W,
    const float* __restrict__ bias,
    const float* __restrict__ Yi, const float* __restrict__ Zj,
    float* __restrict__ out, float* __restrict__ out2, __half* __restrict__ outh)
{
    constexpr int CH = KD / 16;
    extern __shared__ float smem_dyn[];
    __half* Asm = (__half*)smem_dyn;
    __half* Bsm = Asm + MM_ST*MM_AS;

    const int tid  = threadIdx.x;
    const int lane = tid & 31;
    const int wid  = tid >> 5;
    const int wm   = wid & 1;
    const int wn   = wid >> 1;

    const int rowBase = blockIdx.x * 128;
    const int n0 = blockIdx.y * 128;

    const __half* Wp = W;
    if (MODE == 6) Wp = W + (size_t)blockIdx.z * 384 * 256;

    const int laR = tid >> 1, laK = (tid & 1) * 8;
    const __half* Ag = A  + (size_t)(rowBase + laR) * KD + laK;
    const __half* Wg = Wp + (size_t)(n0 + laR) * KD + laK;

    const unsigned sa = (unsigned)__cvta_generic_to_shared(Asm) + (laR*24 + laK)*2;
    const unsigned sb = (unsigned)__cvta_generic_to_shared(Bsm) + (laR*24 + laK)*2;

    const unsigned aF = (unsigned)__cvta_generic_to_shared(Asm)
        + (((wm*64 + (lane & 15))*24 + (lane >> 4)*8) * 2);
    const unsigned bF = (unsigned)__cvta_generic_to_shared(Bsm)
        + (((wn*32 + (lane & 7) + ((lane >> 4) & 1)*8)*24 + ((lane >> 3) & 1)*8) * 2);

    #pragma unroll
    for (int s = 0; s < MM_ST-1; s++) {
        if (s < CH) {
            cp16(sa + s*MM_AS*2, Ag + s*16);
            cp16(sb + s*MM_BS*2, Wg + s*16);
        }
        CP_COMMIT();
    }

    float acc[4][4][4];
    #pragma unroll
    for (int i = 0; i < 4; i++)
        #pragma unroll
        for (int j = 0; j < 4; j++)
            #pragma unroll
            for (int q = 0; q < 4; q++) acc[i][j][q] = 0.0f;

    #pragma unroll 1
    for (int c = 0; c < CH; c++) {
        CP_WAIT2();
        __syncthreads();

        if (c + MM_ST-1 < CH) {
            const int slot = (c + MM_ST-1) & (MM_ST-1);
            const int cc = c + MM_ST-1;
            cp16(sa + slot*MM_AS*2, Ag + cc*16);
            cp16(sb + slot*MM_BS*2, Wg + cc*16);
        }
        CP_COMMIT();

        const unsigned aS = aF + (c & (MM_ST-1))*MM_AS*2;
        const unsigned bS = bF + (c & (MM_ST-1))*MM_BS*2;

        unsigned a[4][4], bq[4][2];
        #pragma unroll
        for (int mt = 0; mt < 4; mt++)
            ldsm4(a[mt][0], a[mt][1], a[mt][2], a[mt][3], aS + (mt*16*24)*2);
        #pragma unroll
        for (int np = 0; np < 2; np++)
            ldsm4(bq[2*np][0], bq[2*np][1], bq[2*np+1][0], bq[2*np+1][1],
                  bS + (np*16*24)*2);
        #pragma unroll
        for (int mt = 0; mt < 4; mt++)
            #pragma unroll
            for (int nt = 0; nt < 4; nt++)
                mma16(acc[mt][nt], a[mt], bq[nt]);
    }

    // ---------------- epilogue ----------------
    float* sred = smem_dyn;
    if (MODE == 5) __syncthreads();

    #pragma unroll
    for (int mt = 0; mt < 4; mt++) {
        #pragma unroll
        for (int h = 0; h < 2; h++) {
            const int r = wm*64 + mt*16 + (lane >> 2) + h*8;
            const int grow = rowBase + r;

            const float* yip = nullptr; const float* zjp = nullptr;
            float mij = 0.f, dn = 1.f, mi = 0.f, cn = 0.f;
            const float* nhp = nullptr;
            if (MODE == 5) {
                int nlin = grow / KNB;
                int b = nlin >> 11;
                yip = Yi + (size_t)nlin * NF + n0;
                zjp = Zj + (size_t)(b*NN + g_eidx[grow]) * NF + n0;
                mij = g_maskij[grow];
            } else if (MODE == 3) {
                dn = g_denom[grow]; mi = g_maski[grow]; cn = g_cnt[grow];
                nhp = g_nodeh + (size_t)grow * DN + n0;
            } else if (MODE == 4) {
                mij = g_maskij[grow];
            }

            #pragma unroll
            for (int nt = 0; nt < 4; nt++) {
                const int c0 = wn*32 + nt*8 + 2*(lane & 3);
                float v0 = acc[mt][nt][h*2 + 0];
                float v1 = acc[mt][nt][h*2 + 1];
                if (MODE == 6) {
                    float* op;
                    if (n0 < 256) op = out  + (size_t)blockIdx.z*NNODE*DN + (size_t)grow*DN + n0;
                    else          op = out2 + (size_t)blockIdx.z*NNODE*DE + (size_t)grow*DE + (n0-256);
                    *(float2*)(op + c0) = make_float2(v0, v1);
                } else if (MODE == 5) {
                    float2 bsv = *(const float2*)(bias + n0 + c0);
                    float2 yv  = *(const float2*)(yip + c0);
                    float2 zv  = *(const float2*)(zjp + c0);
                    v0 = softplus_f(v0 + bsv.x + yv.x + zv.x) * mij;
                    v1 = softplus_f(v1 + bsv.y + yv.y + zv.y) * mij;
                    sred[r*130 + c0]     = v0;
                    sred[r*130 + c0 + 1] = v1;
                } else if (MODE == 4) {
                    float2 bsv = *(const float2*)(bias + n0 + c0);
                    v0 = (v0 + bsv.x) * mij;
                    v1 = (v1 + bsv.y) * mij;
                    *(float2*)(out + (size_t)grow*NF + n0 + c0) = make_float2(v0, v1);
                    *(__half2*)(outh + (size_t)grow*NF + n0 + c0) = __floats2half2_rn(v0, v1);
                } else { // MODE 3
                    float2 bsv = *(const float2*)(bias + n0 + c0);
                    float2 nv  = *(const float2*)(nhp + c0);
                    v0 = (nv.x + (v0 + cn*bsv.x) / dn) * mi;
                    v1 = (nv.y + (v1 + cn*bsv.y) / dn) * mi;
                    *(float2*)(out + (size_t)grow*NF + n0 + c0) = make_float2(v0, v1);
                    if (FLG) *(__half2*)(outh + (size_t)grow*NF + n0 + c0) = __floats2half2_rn(v0, v1);
                }
            }
        }
    }

    if (MODE == 5) {
        __syncthreads();
        if (tid < 128) {
            const int c = tid;
            const int nfirst = rowBase / KNB;
            const int nlast  = (rowBase + 127) / KNB;
            for (int n = nfirst; n <= nlast; n++) {
                int r0 = n*KNB - rowBase;
                int r1 = r0 + KNB;
                r0 = r0 < 0 ? 0 : r0;
                r1 = r1 > 128 ? 128 : r1;
                float s = 0.0f;
                for (int r = r0; r < r1; r++) s += sred[r*130 + c];
                atomicAdd(&g_ksum[(size_t)n*DN + n0 + c], s);
            }
        }
    }
}

// ---------------- 5) fused e-path: t2 = softplus(A@W1 + b1 + Yi + Zj) in smem,
//                    then edge_h = (edge_h + t2@W2 + b2)*maskij  [FLG: +fp16 shadow]
// smem: [0 .. 8*MM_AS) = GEMM1 A/B stages, aliased by T buffer (8 chunk slots)
//       [8*MM_AS .. )  = GEMM2 B stages (4 slots)
#define FE_SMEM ((8*MM_AS + 4*MM_BS)*2)   // 73728

template<int FLG>
__global__ __launch_bounds__(256, 2) void fused_edge(
    const __half* __restrict__ A, const __half* __restrict__ W1,
    const float* __restrict__ bia1,
    const float* __restrict__ Yi, const float* __restrict__ Zj,
    const __half* __restrict__ W2, const float* __restrict__ bia2,
    float* __restrict__ out, __half* __restrict__ outh)
{
    constexpr int KD = 128, CH = 8;
    extern __shared__ float smem_dyn[];
    __half* Asm  = (__half*)smem_dyn;           // GEMM1 A stages (slots 0..3)
    __half* Bsm  = Asm + MM_ST*MM_AS;           // GEMM1 B stages (slots 0..3)
    __half* Tm   = Asm;                         // T buffer: 8 slots of MM_AS (aliases stages)
    __half* B2sm = Asm + 8*MM_AS;               // GEMM2 B stages (slots 0..3)

    const int tid  = threadIdx.x;
    const int lane = tid & 31;
    const int wid  = tid >> 5;
    const int wm   = wid & 1;
    const int wn   = wid >> 1;
    const int rowBase = blockIdx.x * 128;

    const int laR = tid >> 1, laK = (tid & 1) * 8;
    const __half* Ag  = A  + (size_t)(rowBase + laR) * KD + laK;
    const __half* W1g = W1 + (size_t)laR * KD + laK;
    const __half* W2g = W2 + (size_t)laR * KD + laK;

    const unsigned sa  = (unsigned)__cvta_generic_to_shared(Asm)  + (laR*24 + laK)*2;
    const unsigned sb  = (unsigned)__cvta_generic_to_shared(Bsm)  + (laR*24 + laK)*2;
    const unsigned sb2 = (unsigned)__cvta_generic_to_shared(B2sm) + (laR*24 + laK)*2;

    const unsigned aF = (unsigned)__cvta_generic_to_shared(Asm)
        + (((wm*64 + (lane & 15))*24 + (lane >> 4)*8) * 2);
    const unsigned bF = (unsigned)__cvta_generic_to_shared(Bsm)
        + (((wn*32 + (lane & 7) + ((lane >> 4) & 1)*8)*24 + ((lane >> 3) & 1)*8) * 2);
    const unsigned bF2 = (unsigned)__cvta_generic_to_shared(B2sm)
        + (((wn*32 + (lane & 7) + ((lane >> 4) & 1)*8)*24 + ((lane >> 3) & 1)*8) * 2);

    // ---- GEMM1 prologue ----
    #pragma unroll
    for (int s = 0; s < MM_ST-1; s++) {
        cp16(sa + s*MM_AS*2, Ag + s*16);
        cp16(sb + s*MM_BS*2, W1g + s*16);
        CP_COMMIT();
    }

    float acc[4][4][4];
    #pragma unroll
    for (int i = 0; i < 4; i++)
        #pragma unroll
        for (int j = 0; j < 4; j++)
            #pragma unroll
            for (int q = 0; q < 4; q++) acc[i][j][q] = 0.0f;

    // ---- GEMM1 mainloop ----
    #pragma unroll 1
    for (int c = 0; c < CH; c++) {
        CP_WAIT2();
        __syncthreads();
        if (c + MM_ST-1 < CH) {
            const int slot = (c + MM_ST-1) & (MM_ST-1);
            const int cc = c + MM_ST-1;
            cp16(sa + slot*MM_AS*2, Ag + cc*16);
            cp16(sb + slot*MM_BS*2, W1g + cc*16);
        }
        CP_COMMIT();

        const unsigned aS = aF + (c & (MM_ST-1))*MM_AS*2;
        const unsigned bS = bF + (c & (MM_ST-1))*MM_BS*2;
        unsigned a[4][4], bq[4][2];
        #pragma unroll
        for (int mt = 0; mt < 4; mt++)
            ldsm4(a[mt][0], a[mt][1], a[mt][2], a[mt][3], aS + (mt*16*24)*2);
        #pragma unroll
        for (int np = 0; np < 2; np++)
            ldsm4(bq[2*np][0], bq[2*np][1], bq[2*np+1][0], bq[2*np+1][1],
                  bS + (np*16*24)*2);
        #pragma unroll
        for (int mt = 0; mt < 4; mt++)
            #pragma unroll
            for (int nt = 0; nt < 4; nt++)
                mma16(acc[mt][nt], a[mt], bq[nt]);
    }

    __syncthreads();   // all warps done reading stage buffers (T may now alias them)

    // ---- GEMM2 B prologue (into disjoint B2 region; overlaps epilogue1 math) ----
    #pragma unroll
    for (int s = 0; s < MM_ST-1; s++) {
        cp16(sb2 + s*MM_BS*2, W2g + s*16);
        CP_COMMIT();
    }

    // ---- epilogue1: t2 = softplus(acc + b1 + Yi + Zj) -> T (fp16, ldmatrix layout) ----
    #pragma unroll
    for (int mt = 0; mt < 4; mt++) {
        #pragma unroll
        for (int h = 0; h < 2; h++) {
            const int r = wm*64 + mt*16 + (lane >> 2) + h*8;
            const int grow = rowBase + r;
            int nlin = grow / KNB;
            int b = nlin >> 11;
            const float* yip = Yi + (size_t)nlin * DE;
            const float* zjp = Zj + (size_t)(b*NN + g_eidx[grow]) * DE;
            #pragma unroll
            for (int nt = 0; nt < 4; nt++) {
                const int c0 = wn*32 + nt*8 + 2*(lane & 3);
                float2 bsv = *(const float2*)(bia1 + c0);
                float2 yv  = *(const float2*)(yip + c0);
                float2 zv  = *(const float2*)(zjp + c0);
                float v0 = softplus_f(acc[mt][nt][h*2 + 0] + bsv.x + yv.x + zv.x);
                float v1 = softplus_f(acc[mt][nt][h*2 + 1] + bsv.y + yv.y + zv.y);
                *(__half2*)(Tm + (c0 >> 4)*MM_AS + r*24 + (c0 & 15)) =
                    __floats2half2_rn(v0, v1);
            }
        }
    }

    // ---- reset accumulators ----
    #pragma unroll
    for (int i = 0; i < 4; i++)
        #pragma unroll
        for (int j = 0; j < 4; j++)
            #pragma unroll
            for (int q = 0; q < 4; q++) acc[i][j][q] = 0.0f;

    // ---- GEMM2 mainloop: A = T (smem-resident, 8 slots), B staged ----
    #pragma unroll 1
    for (int c = 0; c < CH; c++) {
        CP_WAIT2();
        __syncthreads();
        if (c + MM_ST-1 < CH) {
            const int slot = (c + MM_ST-1) & (MM_ST-1);
            cp16(sb2 + slot*MM_BS*2, W2g + (c + MM_ST-1)*16);
        }
        CP_COMMIT();

        const unsigned aS = aF + c*MM_AS*2;                      // T slot c (0..7)
        const unsigned bS = bF2 + (c & (MM_ST-1))*MM_BS*2;
        unsigned a[4][4], bq[4][2];
        #pragma unroll
        for (int mt = 0; mt < 4; mt++)
            ldsm4(a[mt][0], a[mt][1], a[mt][2], a[mt][3], aS + (mt*16*24)*2);
        #pragma unroll
        for (int np = 0; np < 2; np++)
            ldsm4(bq[2*np][0], bq[2*np][1], bq[2*np+1][0], bq[2*np+1][1],
                  bS + (np*16*24)*2);
        #pragma unroll
        for (int mt = 0; mt < 4; mt++)
            #pragma unroll
            for (int nt = 0; nt < 4; nt++)
                mma16(acc[mt][nt], a[mt], bq[nt]);
    }

    // ---- epilogue2: edge_h = (edge_h + acc + b2)*maskij ----
    #pragma unroll
    for (int mt = 0; mt < 4; mt++) {
        #pragma unroll
        for (int h = 0; h < 2; h++) {
            const int r = wm*64 + mt*16 + (lane >> 2) + h*8;
            const int grow = rowBase + r;
            float mij = g_maskij[grow];
            const float* ehp = g_edgeh + (size_t)grow * DE;
            #pragma unroll
            for (int nt = 0; nt < 4; nt++) {
                const int c0 = wn*32 + nt*8 + 2*(lane & 3);
                float2 bsv = *(const float2*)(bia2 + c0);
                float2 ev  = *(const float2*)(ehp + c0);
                float v0 = (ev.x + acc[mt][nt][h*2 + 0] + bsv.x) * mij;
                float v1 = (ev.y + acc[mt][nt][h*2 + 1] + bsv.y) * mij;
                *(float2*)(out + (size_t)grow*DE + c0) = make_float2(v0, v1);
                if (FLG) *(__half2*)(outh + (size_t)grow*DE + c0) = __floats2half2_rn(v0, v1);
            }
        }
    }
}

// ---------------- launch ----------------
extern "C" void kernel_launch(void* const* d_in, const int* in_sizes, int n_in,
                              void* d_out, int out_size)
{
    const float* X    = (const float*)d_in[0];
    const int*   C    = (const int*)  d_in[1];
    const float* Wn   = (const float*)d_in[2];
    const float* bn   = (const float*)d_in[3];
    const float* We   = (const float*)d_in[4];
    const float* be   = (const float*)d_in[5];
    const float* Wm1  = (const float*)d_in[6];
    const float* bm1  = (const float*)d_in[7];
    const float* Wm2  = (const float*)d_in[8];
    const float* bm2  = (const float*)d_in[9];
    const float* Wue1 = (const float*)d_in[10];
    const float* bue1 = (const float*)d_in[11];
    const float* Wue2 = (const float*)d_in[12];
    const float* bue2 = (const float*)d_in[13];
    float* out = (float*)d_out;

    cudaFuncSetAttribute(mm_tc<32, 128,4,0>, cudaFuncAttributeMaxDynamicSharedMemorySize, MM_SMEM);
    cudaFuncSetAttribute(mm_tc<256,384,6,0>, cudaFuncAttributeMaxDynamicSharedMemorySize, MM_SMEM);
    cudaFuncSetAttribute(mm_tc<128,256,5,0>, cudaFuncAttributeMaxDynamicSharedMemorySize, MM_SMEM);
    cudaFuncSetAttribute(mm_tc<256,256,3,1>, cudaFuncAttributeMaxDynamicSharedMemorySize, MM_SMEM);
    cudaFuncSetAttribute(mm_tc<256,256,3,0>, cudaFuncAttributeMaxDynamicSharedMemorySize, MM_SMEM);
    cudaFuncSetAttribute(fused_edge<1>, cudaFuncAttributeMaxDynamicSharedMemorySize, FE_SMEM);
    cudaFuncSetAttribute(fused_edge<0>, cudaFuncAttributeMaxDynamicSharedMemorySize, FE_SMEM);

    float*  Ym;  cudaGetSymbolAddress((void**)&Ym,  g_Ym);
    float*  Ye;  cudaGetSymbolAddress((void**)&Ye,  g_Ye);
    float*  Eh;  cudaGetSymbolAddress((void**)&Eh,  g_edgeh);
    __half* Ehr; cudaGetSymbolAddress((void**)&Ehr, g_edgehr);
    float*  Nh;  cudaGetSymbolAddress((void**)&Nh,  g_nodeh);
    __half* Nhr; cudaGetSymbolAddress((void**)&Nhr, g_nodehr);
    __half* Ksh; cudaGetSymbolAddress((void**)&Ksh, g_ksumh);
    __half* Wh;  cudaGetSymbolAddress((void**)&Wh,  g_Wh);
    __half* Ft;  cudaGetSymbolAddress((void**)&Ft,  g_featr);

    round_w_kernel<<<512, 256>>>(Wm1, Wue1, Wm2, Wue2, We);
    frame_kernel<<<NNODE/8, 256>>>(X, C, Wn, bn);
    knn_kernel<<<NNODE/4, 128>>>(C);
    feat_kernel<<<ETOT/128, 128>>>();
    // edge_h init as GEMM: feat[ETOT x 32] @ We[32 x 128]
    mm_tc<32, 128, 4, 0><<<dim3(ETOT/128, 1), 256, MM_SMEM>>>(
        Ft, Wh + WT_WE, be, nullptr, nullptr, Eh, nullptr, Ehr);

    for (int l = 0; l < NL; l++) {
        const __half* W1cat = Wh + WT_CAT + (size_t)l*2*384*256;
        const __half* W1me  = Wh + WT_E1M + (size_t)l*256*128;
        const __half* W1ue  = Wh + WT_E1E + (size_t)l*128*128;
        const __half* Wm2l  = Wh + WT_M2  + (size_t)l*256*256;
        const __half* Wue2l = Wh + WT_UE2 + (size_t)l*128*128;
        const bool last = (l == NL-1);

        zero_ksum_kernel<<<256, 256>>>();
        // node precompute (Ym + Ye fused)
        mm_tc<256, 384, 6, 0><<<dim3(NNODE/128, 3, 2), 256, MM_SMEM>>>(
            Nhr, W1cat, nullptr, nullptr, nullptr, Ym, Ye, nullptr);
        // m-path stage-1 with fused masked k-reduction into g_ksum (reads Ehr)
        mm_tc<128, 256, 5, 0><<<dim3(ETOT/128, 2), 256, MM_SMEM>>>(
            Ehr, W1me, bm1 + l*DN, Ym, Ym + (size_t)NNODE*DN, nullptr, nullptr, nullptr);
        // fused e-path stage-1 + edge update (t2 kept in smem; writes Eh/Ehr or final out)
        if (!last)
            fused_edge<1><<<ETOT/128, 256, FE_SMEM>>>(
                Ehr, W1ue, bue1 + l*DE, Ye, Ye + (size_t)NNODE*DE,
                Wue2l, bue2 + l*DE, Eh, Ehr);
        else
            fused_edge<0><<<ETOT/128, 256, FE_SMEM>>>(
                Ehr, W1ue, bue1 + l*DE, Ye, Ye + (size_t)NNODE*DE,
                Wue2l, bue2 + l*DE, out + S0OUT, nullptr);
        round_ksum_kernel<<<256, 256>>>();
        // node update
        if (!last)
            mm_tc<256, 256, 3, 1><<<dim3(NNODE/128, 2), 256, MM_SMEM>>>(
                Ksh, Wm2l, bm2 + l*DN, nullptr, nullptr, Nh, nullptr, Nhr);
        else
            mm_tc<256, 256, 3, 0><<<dim3(NNODE/128, 2), 256, MM_SMEM>>>(
                Ksh, Wm2l, bm2 + l*DN, nullptr, nullptr, out, nullptr, nullptr);
    }

    copy_tail_kernel<<<512, 256>>>(out + S0OUT + S1OUT);
}

// round 12
// speedup vs baseline: 1.1889x; 1.0141x over previous
#include <cuda_runtime.h>
#include <cuda_fp16.h>
#include <math.h>

// ---------------- problem constants ----------------
#define BB   2
#define NN   2048
#define KNB  30
#define DN   256
#define DE   128
#define NL   3
#define NFI  12
#define EFI  28
#define ETOT (BB*NN*KNB)  // 122880
#define NNODE (BB*NN)     // 4096
#define EPSF 1e-6f
#define BIGF 1e9f
#define FLTMAX 3.402823466e38f

#define S0OUT (NNODE*DN)
#define S1OUT (ETOT*DE)

// ---------------- scratch ----------------
__device__ float  g_nodeh [NNODE*DN];
__device__ __half g_nodehr[NNODE*DN];
__device__ float  g_edgeh [ETOT*DE];
__device__ __half g_edgehr[ETOT*DE];
__device__ int    g_eidx [ETOT];
__device__ float  g_maski[NNODE];
__device__ float  g_maskij[ETOT];
__device__ float  g_denom[NNODE];
__device__ float  g_cnt  [NNODE];
__device__ float  g_R  [NNODE*9];
__device__ float  g_Xc [NNODE*3];
__device__ float  g_Ym [2*NNODE*DN];
__device__ float  g_Ye [2*NNODE*DE];
__device__ float  g_ksum [NNODE*DN];       // fp32 atomic accum (MODE3 converts on load)

// transposed fp16 weight arena: W^T[n][k]
#define WT_CAT 0
#define WT_E1M (3*2*384*256)            // 589824
#define WT_E1E (WT_E1M + 3*256*128)     // 688128
#define WT_M2  (WT_E1E + 3*128*128)     // 737280
#define WT_UE2 (WT_M2  + 3*256*256)     // 933888
#define WT_WE  (WT_UE2 + 3*128*128)     // 983040
#define WT_TOT (WT_WE  + 128*32)        // 987136
__device__ __half g_Wh[WT_TOT];

__device__ __forceinline__ float softplus_f(float x) {
    return fmaxf(x, 0.0f) + log1pf(expf(-fabsf(x)));
}
__device__ __forceinline__ void mma16(float* c, const unsigned* a, const unsigned* b) {
    asm volatile(
        "mma.sync.aligned.m16n8k16.row.col.f32.f16.f16.f32 "
        "{%0,%1,%2,%3},{%4,%5,%6,%7},{%8,%9},{%0,%1,%2,%3};"
        : "+f"(c[0]), "+f"(c[1]), "+f"(c[2]), "+f"(c[3])
        : "r"(a[0]), "r"(a[1]), "r"(a[2]), "r"(a[3]), "r"(b[0]), "r"(b[1]));
}
__device__ __forceinline__ void ldsm4(unsigned& r0, unsigned& r1, unsigned& r2, unsigned& r3,
                                      unsigned addr) {
    asm volatile("ldmatrix.sync.aligned.m8n8.x4.shared.b16 {%0,%1,%2,%3}, [%4];"
        : "=r"(r0), "=r"(r1), "=r"(r2), "=r"(r3) : "r"(addr));
}
__device__ __forceinline__ void cp16(unsigned dst, const void* src) {
    asm volatile("cp.async.cg.shared.global [%0], [%1], 16;" :: "r"(dst), "l"(src));
}
#define CP_COMMIT() asm volatile("cp.async.commit_group;")
#define CP_WAIT2()  asm volatile("cp.async.wait_group 2;")
#define CP_WAIT0()  asm volatile("cp.async.wait_group 0;")

// ---------------- 0) round + transpose + repack all weights to fp16 ----------------
__global__ void round_w_kernel(const float* __restrict__ Wm1, const float* __restrict__ Wue1,
                               const float* __restrict__ Wm2, const float* __restrict__ Wue2,
                               const float* __restrict__ We)
{
    for (int i = blockIdx.x*blockDim.x + threadIdx.x; i < WT_TOT; i += gridDim.x*blockDim.x) {
        float v;
        if (i < WT_E1M) {                       // [l][z][n<384][k<256]
            int l = i / 196608, r = i % 196608;
            int z = r / 98304,  q = r % 98304;
            int n = q / 256,    k = q % 256;
            v = (n < 256) ? Wm1 [((size_t)l*640 + z*256 + k)*256 + n]
                          : Wue1[((size_t)l*640 + z*256 + k)*128 + (n - 256)];
        } else if (i < WT_E1E) {                // [l][n<256][k<128]
            int r = i - WT_E1M;
            int l = r / 32768, q = r % 32768;
            int n = q / 128,   k = q % 128;
            v = Wm1[((size_t)l*640 + 512 + k)*256 + n];
        } else if (i < WT_M2) {                 // [l][n<128][k<128]
            int r = i - WT_E1E;
            int l = r / 16384, q = r % 16384;
            int n = q / 128,   k = q % 128;
            v = Wue1[((size_t)l*640 + 512 + k)*128 + n];
        } else if (i < WT_UE2) {                // [l][n<256][k<256]
            int r = i - WT_M2;
            int l = r / 65536, q = r % 65536;
            int n = q / 256,   k = q % 256;
            v = Wm2[((size_t)l*256 + k)*256 + n];
        } else if (i < WT_WE) {                 // [l][n<128][k<128]
            int r = i - WT_UE2;
            int l = r / 16384, q = r % 16384;
            int n = q / 128,   k = q % 128;
            v = Wue2[((size_t)l*128 + k)*128 + n];
        } else {                                // [n<128][k<32]
            int r = i - WT_WE;
            int n = r / 32, k = r % 32;
            v = (k < EFI) ? We[k*128 + n] : 0.0f;
        }
        g_Wh[i] = __float2half_rn(v);
    }
}

// ---------------- 1) per-node frame, features, node_h init ----------------
__global__ void frame_kernel(const float* __restrict__ X, const int* __restrict__ C,
                             const float* __restrict__ Wn, const float* __restrict__ bn)
{
    __shared__ float s_feat[8][12];
    __shared__ float s_mask[8];
    int warp = threadIdx.x >> 5;
    int lane = threadIdx.x & 31;
    int nlin = blockIdx.x * 8 + warp;

    if (lane == 0) {
        const float* xr = X + (size_t)nlin * 12;
        float Na[3], CA[3], Ct[3], Oa[3];
        #pragma unroll
        for (int d = 0; d < 3; d++) { Na[d]=xr[d]; CA[d]=xr[3+d]; Ct[d]=xr[6+d]; Oa[d]=xr[9+d]; }
        #pragma unroll
        for (int d = 0; d < 3; d++) {
            float s = __fadd_rn(__fadd_rn(__fadd_rn(Na[d], CA[d]), Ct[d]), Oa[d]);
            g_Xc[nlin*3 + d] = __fmul_rn(s, 0.25f);
        }
        float b1[3], b2[3], b3[3], v0[3];
        #pragma unroll
        for (int d = 0; d < 3; d++) {
            b1[d] = CA[d] - Na[d];
            b2[d] = Ct[d] - CA[d];
            b3[d] = Oa[d] - Ct[d];
            v0[d] = Na[d] - CA[d];
        }
        float nb2 = sqrtf(b2[0]*b2[0] + b2[1]*b2[1] + b2[2]*b2[2]);
        float u[3];
        #pragma unroll
        for (int d = 0; d < 3; d++) u[d] = b2[d] / (nb2 + EPSF);
        float dotv = v0[0]*u[0] + v0[1]*u[1] + v0[2]*u[2];
        float t[3];
        #pragma unroll
        for (int d = 0; d < 3; d++) t[d] = v0[d] - dotv * u[d];
        float nt = sqrtf(t[0]*t[0] + t[1]*t[1] + t[2]*t[2]);
        float v[3];
        #pragma unroll
        for (int d = 0; d < 3; d++) v[d] = t[d] / (nt + EPSF);
        float w[3];
        w[0] = u[1]*v[2] - u[2]*v[1];
        w[1] = u[2]*v[0] - u[0]*v[2];
        w[2] = u[0]*v[1] - u[1]*v[0];
        #pragma unroll
        for (int d = 0; d < 3; d++) {
            g_R[nlin*9 + d*3 + 0] = u[d];
            g_R[nlin*9 + d*3 + 1] = v[d];
            g_R[nlin*9 + d*3 + 2] = w[d];
        }
        float nb1 = sqrtf(b1[0]*b1[0] + b1[1]*b1[1] + b1[2]*b1[2]);
        float nb3 = sqrtf(b3[0]*b3[0] + b3[1]*b3[1] + b3[2]*b3[2]);
        #pragma unroll
        for (int d = 0; d < 3; d++) {
            s_feat[warp][0 + d] = b1[d] / (nb1 + EPSF);
            s_feat[warp][4 + d] = b2[d] / (nb2 + EPSF);
            s_feat[warp][8 + d] = b3[d] / (nb3 + EPSF);
        }
        s_feat[warp][3]  = logf(nb1 + EPSF);
        s_feat[warp][7]  = logf(nb2 + EPSF);
        s_feat[warp][11] = logf(nb3 + EPSF);
        float mk = (C[nlin] > 0) ? 1.0f : 0.0f;
        s_mask[warp] = mk;
        g_maski[nlin] = mk;
    }
    __syncwarp();

    float f[12];
    #pragma unroll
    for (int i = 0; i < 12; i++) f[i] = s_feat[warp][i];
    float mk = s_mask[warp];
    #pragma unroll
    for (int r = 0; r < 8; r++) {
        int c = lane + r * 32;
        float acc = bn[c];
        #pragma unroll
        for (int ff = 0; ff < NFI; ff++) acc += f[ff] * Wn[ff*DN + c];
        float v = acc * mk;
        g_nodeh [(size_t)nlin*DN + c] = v;
        g_nodehr[(size_t)nlin*DN + c] = __float2half_rn(v);
    }
}

// ---------------- 2) kNN: warp-per-node, exact semantics ----------------
__global__ __launch_bounds__(128) void knn_kernel(const int* __restrict__ C)
{
    __shared__ float s_d2[4][NN];
    int wid = threadIdx.x >> 5;
    int lane = threadIdx.x & 31;
    int nlin = blockIdx.x * 4 + wid;
    int b = nlin >> 11;
    int n = nlin & (NN - 1);

    float xi0 = g_Xc[nlin*3+0], xi1 = g_Xc[nlin*3+1], xi2 = g_Xc[nlin*3+2];
    const int* Cb = C + b*NN;
    for (int j = lane; j < NN; j += 32) {
        float dx = __fadd_rn(xi0, -g_Xc[(size_t)(b*NN + j)*3 + 0]);
        float dy = __fadd_rn(xi1, -g_Xc[(size_t)(b*NN + j)*3 + 1]);
        float dz = __fadd_rn(xi2, -g_Xc[(size_t)(b*NN + j)*3 + 2]);
        float d2 = __fadd_rn(__fadd_rn(__fmul_rn(dx,dx), __fmul_rn(dy,dy)), __fmul_rn(dz,dz));
        if (Cb[j] <= 0) d2 = __fadd_rn(d2, BIGF);
        if (j == n)     d2 = __fadd_rn(d2, BIGF);
        s_d2[wid][j] = d2;
    }
    __syncwarp();

    float mi = g_maski[nlin];
    float cnt = 0.0f;
    for (int kk = 0; kk < KNB; kk++) {
        float bv = FLTMAX; int bi = 0x7fffffff;
        #pragma unroll 4
        for (int j = lane; j < NN; j += 32) {
            float v = s_d2[wid][j];
            if (v < bv || (v == bv && j < bi)) { bv = v; bi = j; }
        }
        #pragma unroll
        for (int off = 16; off > 0; off >>= 1) {
            float v2 = __shfl_down_sync(0xffffffffu, bv, off);
            int   i2 = __shfl_down_sync(0xffffffffu, bi, off);
            if (v2 < bv || (v2 == bv && i2 < bi)) { bv = v2; bi = i2; }
        }
        bi = __shfl_sync(0xffffffffu, bi, 0);
        if (lane == 0) {
            int e = nlin*KNB + kk;
            g_eidx[e] = bi;
            float mj = (Cb[bi] > 0) ? 1.0f : 0.0f;
            float mij = mi * mj;
            g_maskij[e] = mij;
            cnt += mij;
            s_d2[wid][bi] = FLTMAX;
        }
        __syncwarp();
    }
    if (lane == 0) { g_cnt[nlin] = cnt; g_denom[nlin] = cnt + EPSF; }
}

// ---------------- helpers ----------------
__global__ void zero_ksum_kernel()
{
    float4* p = (float4*)g_ksum;
    for (int i = blockIdx.x*blockDim.x + threadIdx.x; i < NNODE*DN/4; i += gridDim.x*blockDim.x)
        p[i] = make_float4(0.f, 0.f, 0.f, 0.f);
}
__global__ void copy_tail_kernel(float* __restrict__ out)
{
    const int S2 = ETOT, S3 = NNODE;
    const int TOT = ETOT + NNODE + ETOT;
    for (int i = blockIdx.x*blockDim.x + threadIdx.x; i < TOT; i += gridDim.x*blockDim.x) {
        float v;
        if (i < S2)           v = (float)g_eidx[i];
        else if (i < S2+S3)   v = g_maski[i - S2];
        else                  v = g_maskij[i - S2 - S3];
        out[i] = v;
    }
}

#define MM_ST 4
#define MM_AS (128*24)                    // halfs per A stage (pad 16->24)
#define MM_BS (128*24)                    // halfs per B stage
#define MM_SMEM 66560                     // max(4*(AS+BS)*2 = 49152, 128*130*4)

// ---------------- 3) fused edge-init: features computed in-kernel, GEMM vs We ----------------
// edge_h = (feat@We + be)*maskij -> out fp32 + outh fp16 (rounding identical to old path)
#define EI_SMEM (4*MM_AS*2)               // 2 A slots + 2 B slots = 24576

__global__ __launch_bounds__(256, 2) void edge_init_kernel(
    const __half* __restrict__ W, const float* __restrict__ bias,
    float* __restrict__ out, __half* __restrict__ outh)
{
    extern __shared__ float smem_dyn[];
    __half* Asm = (__half*)smem_dyn;        // 2 slots [128][24]
    __half* Bsm = Asm + 2*MM_AS;            // 2 slots [128][24]

    const int tid  = threadIdx.x;
    const int lane = tid & 31;
    const int wid  = tid >> 5;
    const int wm   = wid & 1;
    const int wn   = wid >> 1;
    const int rowBase = blockIdx.x * 128;

    // B loader: W^T[128][32]; chunk s covers k in [16s, 16s+16)
    const int laR = tid >> 1, laK = (tid & 1) * 8;
    const unsigned sb = (unsigned)__cvta_generic_to_shared(Bsm) + (laR*24 + laK)*2;
    cp16(sb + 0*MM_BS*2, W + laR*32 + laK);
    cp16(sb + 1*MM_BS*2, W + laR*32 + 16 + laK);
    CP_COMMIT();

    // features: threads 0..127, one edge each, rounded to fp16 (identical to old feat_kernel)
    if (tid < 128) {
        int e = rowBase + tid;
        int nlin = e / KNB;
        int b = nlin >> 11;
        int j = g_eidx[e];
        int jl = b*NN + j;

        float dv[3];
        #pragma unroll
        for (int d = 0; d < 3; d++) dv[d] = g_Xc[jl*3+d] - g_Xc[nlin*3+d];
        float dist = sqrtf(dv[0]*dv[0] + dv[1]*dv[1] + dv[2]*dv[2]);
        float Ri[9], Rj[9];
        #pragma unroll
        for (int q = 0; q < 9; q++) { Ri[q] = g_R[nlin*9+q]; Rj[q] = g_R[jl*9+q]; }

        float f[32];
        #pragma unroll
        for (int mc = 0; mc < 16; mc++) {
            float cm = (float)(20.0 * mc / 15.0);
            float z = (dist - cm) * 0.8f;
            f[mc] = expf(-z*z);
        }
        float inv = 1.0f / (dist + EPSF);
        #pragma unroll
        for (int c = 0; c < 3; c++) {
            float loc = Ri[0*3+c]*dv[0] + Ri[1*3+c]*dv[1] + Ri[2*3+c]*dv[2];
            f[16 + c] = loc * inv;
        }
        #pragma unroll
        for (int ee = 0; ee < 3; ee++)
            #pragma unroll
            for (int ff = 0; ff < 3; ff++)
                f[19 + ee*3 + ff] = Ri[0*3+ee]*Rj[0*3+ff] + Ri[1*3+ee]*Rj[1*3+ff] + Ri[2*3+ee]*Rj[2*3+ff];
        f[28] = f[29] = f[30] = f[31] = 0.0f;

        // chunk 0: cols 0..15 ; chunk 1: cols 16..31 (local 0..15)
        #pragma unroll
        for (int q = 0; q < 8; q++)
            *(__half2*)(Asm + 0*MM_AS + tid*24 + 2*q) = __floats2half2_rn(f[2*q], f[2*q+1]);
        #pragma unroll
        for (int q = 8; q < 16; q++)
            *(__half2*)(Asm + 1*MM_AS + tid*24 + (2*q - 16)) = __floats2half2_rn(f[2*q], f[2*q+1]);
    }
    CP_WAIT0();
    __syncthreads();

    const unsigned aF = (unsigned)__cvta_generic_to_shared(Asm)
        + (((wm*64 + (lane & 15))*24 + (lane >> 4)*8) * 2);
    const unsigned bF = (unsigned)__cvta_generic_to_shared(Bsm)
        + (((wn*32 + (lane & 7) + ((lane >> 4) & 1)*8)*24 + ((lane >> 3) & 1)*8) * 2);

    float acc[4][4][4];
    #pragma unroll
    for (int i = 0; i < 4; i++)
        #pragma unroll
        for (int j = 0; j < 4; j++)
            #pragma unroll
            for (int q = 0; q < 4; q++) acc[i][j][q] = 0.0f;

    #pragma unroll
    for (int c = 0; c < 2; c++) {
        const unsigned aS = aF + c*MM_AS*2;
        const unsigned bS = bF + c*MM_BS*2;
        unsigned a[4][4], bq[4][2];
        #pragma unroll
        for (int mt = 0; mt < 4; mt++)
            ldsm4(a[mt][0], a[mt][1], a[mt][2], a[mt][3], aS + (mt*16*24)*2);
        #pragma unroll
        for (int np = 0; np < 2; np++)
            ldsm4(bq[2*np][0], bq[2*np][1], bq[2*np+1][0], bq[2*np+1][1],
                  bS + (np*16*24)*2);
        #pragma unroll
        for (int mt = 0; mt < 4; mt++)
            #pragma unroll
            for (int nt = 0; nt < 4; nt++)
                mma16(acc[mt][nt], a[mt], bq[nt]);
    }

    #pragma unroll
    for (int mt = 0; mt < 4; mt++) {
        #pragma unroll
        for (int h = 0; h < 2; h++) {
            const int r = wm*64 + mt*16 + (lane >> 2) + h*8;
            const int grow = rowBase + r;
            float mij = g_maskij[grow];
            #pragma unroll
            for (int nt = 0; nt < 4; nt++) {
                const int c0 = wn*32 + nt*8 + 2*(lane & 3);
                float2 bsv = *(const float2*)(bias + c0);
                float v0 = (acc[mt][nt][h*2 + 0] + bsv.x) * mij;
                float v1 = (acc[mt][nt][h*2 + 1] + bsv.y) * mij;
                *(float2*)(out + (size_t)grow*DE + c0) = make_float2(v0, v1);
                *(__half2*)(outh + (size_t)grow*DE + c0) = __floats2half2_rn(v0, v1);
            }
        }
    }
}

// ---------------- 4) fp16 TC GEMM (m16n8k16), 4-stage cp.async + ldmatrix ----------------
// MODE 3: node_h = (node_h + (A@W + cnt*bias)/denom)*mask_i [FLG: + shadow]
//         (A32=1: A is fp32, converted in loader with __float2half_rn)
// MODE 5: m-path stage-1: masked softplus -> smem reduce -> atomic g_ksum
// MODE 6: node precompute cat: cols<256 -> out(Ym)[z], cols>=256 -> out2(Ye)[z]
template<int KD, int NF, int MODE, int FLG, int A32>
__global__ __launch_bounds__(256, 2) void mm_tc(
    const __half* __restrict__ A, const __half* __restrict__ W,
    const float* __restrict__ bias,
    const float* __restrict__ Yi, const float* __restrict__ Zj,
    float* __restrict__ out, float* __restrict__ out2, __half* __restrict__ outh)
{
    constexpr int CH = KD / 16;
    extern __shared__ float smem_dyn[];
    __half* Asm = (__half*)smem_dyn;
    __half* Bsm = Asm + MM_ST*MM_AS;

    const int tid  = threadIdx.x;
    const int lane = tid & 31;
    const int wid  = tid >> 5;
    const int wm   = wid & 1;
    const int wn   = wid >> 1;

    const int rowBase = blockIdx.x * 128;
    const int n0 = blockIdx.y * 128;

    const __half* Wp = W;
    if (MODE == 6) Wp = W + (size_t)blockIdx.z * 384 * 256;

    const int laR = tid >> 1, laK = (tid & 1) * 8;
    const __half* Ag  = A + (size_t)(rowBase + laR) * KD + laK;
    const float*  Agf = (const float*)A + (size_t)(rowBase + laR) * KD + laK;
    const __half* Wg = Wp + (size_t)(n0 + laR) * KD + laK;

    const unsigned sa = (unsigned)__cvta_generic_to_shared(Asm) + (laR*24 + laK)*2;
    const unsigned sb = (unsigned)__cvta_generic_to_shared(Bsm) + (laR*24 + laK)*2;
    __half* AsmT = Asm + laR*24 + laK;

    const unsigned aF = (unsigned)__cvta_generic_to_shared(Asm)
        + (((wm*64 + (lane & 15))*24 + (lane >> 4)*8) * 2);
    const unsigned bF = (unsigned)__cvta_generic_to_shared(Bsm)
        + (((wn*32 + (lane & 7) + ((lane >> 4) & 1)*8)*24 + ((lane >> 3) & 1)*8) * 2);

    #pragma unroll
    for (int s = 0; s < MM_ST-1; s++) {
        if (s < CH) {
            if (A32) {
                float4 f0 = *(const float4*)(Agf + s*16);
                float4 f1 = *(const float4*)(Agf + s*16 + 4);
                __half2 hh[4] = {__floats2half2_rn(f0.x,f0.y), __floats2half2_rn(f0.z,f0.w),
                                 __floats2half2_rn(f1.x,f1.y), __floats2half2_rn(f1.z,f1.w)};
                *(uint4*)(AsmT + s*MM_AS) = *(uint4*)hh;
            } else {
                cp16(sa + s*MM_AS*2, Ag + s*16);
            }
            cp16(sb + s*MM_BS*2, Wg + s*16);
        }
        CP_COMMIT();
    }

    float acc[4][4][4];
    #pragma unroll
    for (int i = 0; i < 4; i++)
        #pragma unroll
        for (int j = 0; j < 4; j++)
            #pragma unroll
            for (int q = 0; q < 4; q++) acc[i][j][q] = 0.0f;

    #pragma unroll 1
    for (int c = 0; c < CH; c++) {
        CP_WAIT2();
        __syncthreads();

        if (c + MM_ST-1 < CH) {
            const int slot = (c + MM_ST-1) & (MM_ST-1);
            const int cc = c + MM_ST-1;
            if (A32) {
                float4 f0 = *(const float4*)(Agf + cc*16);
                float4 f1 = *(const float4*)(Agf + cc*16 + 4);
                __half2 hh[4] = {__floats2half2_rn(f0.x,f0.y), __floats2half2_rn(f0.z,f0.w),
                                 __floats2half2_rn(f1.x,f1.y), __floats2half2_rn(f1.z,f1.w)};
                *(uint4*)(AsmT + slot*MM_AS) = *(uint4*)hh;
            } else {
                cp16(sa + slot*MM_AS*2, Ag + cc*16);
            }
            cp16(sb + slot*MM_BS*2, Wg + cc*16);
        }
        CP_COMMIT();

        const unsigned aS = aF + (c & (MM_ST-1))*MM_AS*2;
        const unsigned bS = bF + (c & (MM_ST-1))*MM_BS*2;

        unsigned a[4][4], bq[4][2];
        #pragma unroll
        for (int mt = 0; mt < 4; mt++)
            ldsm4(a[mt][0], a[mt][1], a[mt][2], a[mt][3], aS + (mt*16*24)*2);
        #pragma unroll
        for (int np = 0; np < 2; np++)
            ldsm4(bq[2*np][0], bq[2*np][1], bq[2*np+1][0], bq[2*np+1][1],
                  bS + (np*16*24)*2);
        #pragma unroll
        for (int mt = 0; mt < 4; mt++)
            #pragma unroll
            for (int nt = 0; nt < 4; nt++)
                mma16(acc[mt][nt], a[mt], bq[nt]);
    }

    // ---------------- epilogue ----------------
    float* sred = smem_dyn;
    if (MODE == 5) __syncthreads();

    #pragma unroll
    for (int mt = 0; mt < 4; mt++) {
        #pragma unroll
        for (int h = 0; h < 2; h++) {
            const int r = wm*64 + mt*16 + (lane >> 2) + h*8;
            const int grow = rowBase + r;

            const float* yip = nullptr; const float* zjp = nullptr;
            float mij = 0.f, dn = 1.f, mi = 0.f, cn = 0.f;
            const float* nhp = nullptr;
            if (MODE == 5) {
                int nlin = grow / KNB;
                int b = nlin >> 11;
                yip = Yi + (size_t)nlin * NF + n0;
                zjp = Zj + (size_t)(b*NN + g_eidx[grow]) * NF + n0;
                mij = g_maskij[grow];
            } else if (MODE == 3) {
                dn = g_denom[grow]; mi = g_maski[grow]; cn = g_cnt[grow];
                nhp = g_nodeh + (size_t)grow * DN + n0;
            }

            #pragma unroll
            for (int nt = 0; nt < 4; nt++) {
                const int c0 = wn*32 + nt*8 + 2*(lane & 3);
                float v0 = acc[mt][nt][h*2 + 0];
                float v1 = acc[mt][nt][h*2 + 1];
                if (MODE == 6) {
                    float* op;
                    if (n0 < 256) op = out  + (size_t)blockIdx.z*NNODE*DN + (size_t)grow*DN + n0;
                    else          op = out2 + (size_t)blockIdx.z*NNODE*DE + (size_t)grow*DE + (n0-256);
                    *(float2*)(op + c0) = make_float2(v0, v1);
                } else if (MODE == 5) {
                    float2 bsv = *(const float2*)(bias + n0 + c0);
                    float2 yv  = *(const float2*)(yip + c0);
                    float2 zv  = *(const float2*)(zjp + c0);
                    v0 = softplus_f(v0 + bsv.x + yv.x + zv.x) * mij;
                    v1 = softplus_f(v1 + bsv.y + yv.y + zv.y) * mij;
                    sred[r*130 + c0]     = v0;
                    sred[r*130 + c0 + 1] = v1;
                } else { // MODE 3
                    float2 bsv = *(const float2*)(bias + n0 + c0);
                    float2 nv  = *(const float2*)(nhp + c0);
                    v0 = (nv.x + (v0 + cn*bsv.x) / dn) * mi;
                    v1 = (nv.y + (v1 + cn*bsv.y) / dn) * mi;
                    *(float2*)(out + (size_t)grow*NF + n0 + c0) = make_float2(v0, v1);
                    if (FLG) *(__half2*)(outh + (size_t)grow*NF + n0 + c0) = __floats2half2_rn(v0, v1);
                }
            }
        }
    }

    if (MODE == 5) {
        __syncthreads();
        if (tid < 128) {
            const int c = tid;
            const int nfirst = rowBase / KNB;
            const int nlast  = (rowBase + 127) / KNB;
            for (int n = nfirst; n <= nlast; n++) {
                int r0 = n*KNB - rowBase;
                int r1 = r0 + KNB;
                r0 = r0 < 0 ? 0 : r0;
                r1 = r1 > 128 ? 128 : r1;
                float s = 0.0f;
                for (int r = r0; r < r1; r++) s += sred[r*130 + c];
                atomicAdd(&g_ksum[(size_t)n*DN + n0 + c], s);
            }
        }
    }
}

// ---------------- 5) fused e-path: t2 = softplus(A@W1 + b1 + Yi + Zj) in smem,
//                    then edge_h = (edge_h + t2@W2 + b2)*maskij  [FLG: +fp16 shadow]
#define FE_SMEM ((8*MM_AS + 4*MM_BS)*2)   // 73728

template<int FLG>
__global__ __launch_bounds__(256, 2) void fused_edge(
    const __half* __restrict__ A, const __half* __restrict__ W1,
    const float* __restrict__ bia1,
    const float* __restrict__ Yi, const float* __restrict__ Zj,
    const __half* __restrict__ W2, const float* __restrict__ bia2,
    float* __restrict__ out, __half* __restrict__ outh)
{
    constexpr int KD = 128, CH = 8;
    extern __shared__ float smem_dyn[];
    __half* Asm  = (__half*)smem_dyn;           // GEMM1 A stages (slots 0..3)
    __half* Bsm  = Asm + MM_ST*MM_AS;           // GEMM1 B stages (slots 0..3)
    __half* Tm   = Asm;                         // T buffer: 8 slots of MM_AS (aliases stages)
    __half* B2sm = Asm + 8*MM_AS;               // GEMM2 B stages (slots 0..3)

    const int tid  = threadIdx.x;
    const int lane = tid & 31;
    const int wid  = tid >> 5;
    const int wm   = wid & 1;
    const int wn   = wid >> 1;
    const int rowBase = blockIdx.x * 128;

    const int laR = tid >> 1, laK = (tid & 1) * 8;
    const __half* Ag  = A  + (size_t)(rowBase + laR) * KD + laK;
    const __half* W1g = W1 + (size_t)laR * KD + laK;
    const __half* W2g = W2 + (size_t)laR * KD + laK;

    const unsigned sa  = (unsigned)__cvta_generic_to_shared(Asm)  + (laR*24 + laK)*2;
    const unsigned sb  = (unsigned)__cvta_generic_to_shared(Bsm)  + (laR*24 + laK)*2;
    const unsigned sb2 = (unsigned)__cvta_generic_to_shared(B2sm) + (laR*24 + laK)*2;

    const unsigned aF = (unsigned)__cvta_generic_to_shared(Asm)
        + (((wm*64 + (lane & 15))*24 + (lane >> 4)*8) * 2);
    const unsigned bF = (unsigned)__cvta_generic_to_shared(Bsm)
        + (((wn*32 + (lane & 7) + ((lane >> 4) & 1)*8)*24 + ((lane >> 3) & 1)*8) * 2);
    const unsigned bF2 = (unsigned)__cvta_generic_to_shared(B2sm)
        + (((wn*32 + (lane & 7) + ((lane >> 4) & 1)*8)*24 + ((lane >> 3) & 1)*8) * 2);

    // ---- GEMM1 prologue ----
    #pragma unroll
    for (int s = 0; s < MM_ST-1; s++) {
        cp16(sa + s*MM_AS*2, Ag + s*16);
        cp16(sb + s*MM_BS*2, W1g + s*16);
        CP_COMMIT();
    }

    float acc[4][4][4];
    #pragma unroll
    for (int i = 0; i < 4; i++)
        #pragma unroll
        for (int j = 0; j < 4; j++)
            #pragma unroll
            for (int q = 0; q < 4; q++) acc[i][j][q] = 0.0f;

    // ---- GEMM1 mainloop ----
    #pragma unroll 1
    for (int c = 0; c < CH; c++) {
        CP_WAIT2();
        __syncthreads();
        if (c + MM_ST-1 < CH) {
            const int slot = (c + MM_ST-1) & (MM_ST-1);
            const int cc = c + MM_ST-1;
            cp16(sa + slot*MM_AS*2, Ag + cc*16);
            cp16(sb + slot*MM_BS*2, W1g + cc*16);
        }
        CP_COMMIT();

        const unsigned aS = aF + (c & (MM_ST-1))*MM_AS*2;
        const unsigned bS = bF + (c & (MM_ST-1))*MM_BS*2;
        unsigned a[4][4], bq[4][2];
        #pragma unroll
        for (int mt = 0; mt < 4; mt++)
            ldsm4(a[mt][0], a[mt][1], a[mt][2], a[mt][3], aS + (mt*16*24)*2);
        #pragma unroll
        for (int np = 0; np < 2; np++)
            ldsm4(bq[2*np][0], bq[2*np][1], bq[2*np+1][0], bq[2*np+1][1],
                  bS + (np*16*24)*2);
        #pragma unroll
        for (int mt = 0; mt < 4; mt++)
            #pragma unroll
            for (int nt = 0; nt < 4; nt++)
                mma16(acc[mt][nt], a[mt], bq[nt]);
    }

    __syncthreads();   // all warps done reading stage buffers (T may now alias them)

    // ---- GEMM2 B prologue (into disjoint B2 region; overlaps epilogue1 math) ----
    #pragma unroll
    for (int s = 0; s < MM_ST-1; s++) {
        cp16(sb2 + s*MM_BS*2, W2g + s*16);
        CP_COMMIT();
    }

    // ---- epilogue1: t2 = softplus(acc + b1 + Yi + Zj) -> T (fp16, ldmatrix layout) ----
    #pragma unroll
    for (int mt = 0; mt < 4; mt++) {
        #pragma unroll
        for (int h = 0; h < 2; h++) {
            const int r = wm*64 + mt*16 + (lane >> 2) + h*8;
            const int grow = rowBase + r;
            int nlin = grow / KNB;
            int b = nlin >> 11;
            const float* yip = Yi + (size_t)nlin * DE;
            const float* zjp = Zj + (size_t)(b*NN + g_eidx[grow]) * DE;
            #pragma unroll
            for (int nt = 0; nt < 4; nt++) {
                const int c0 = wn*32 + nt*8 + 2*(lane & 3);
                float2 bsv = *(const float2*)(bia1 + c0);
                float2 yv  = *(const float2*)(yip + c0);
                float2 zv  = *(const float2*)(zjp + c0);
                float v0 = softplus_f(acc[mt][nt][h*2 + 0] + bsv.x + yv.x + zv.x);
                float v1 = softplus_f(acc[mt][nt][h*2 + 1] + bsv.y + yv.y + zv.y);
                *(__half2*)(Tm + (c0 >> 4)*MM_AS + r*24 + (c0 & 15)) =
                    __floats2half2_rn(v0, v1);
            }
        }
    }

    // ---- reset accumulators ----
    #pragma unroll
    for (int i = 0; i < 4; i++)
        #pragma unroll
        for (int j = 0; j < 4; j++)
            #pragma unroll
            for (int q = 0; q < 4; q++) acc[i][j][q] = 0.0f;

    // ---- GEMM2 mainloop: A = T (smem-resident, 8 slots), B staged ----
    #pragma unroll 1
    for (int c = 0; c < CH; c++) {
        CP_WAIT2();
        __syncthreads();
        if (c + MM_ST-1 < CH) {
            const int slot = (c + MM_ST-1) & (MM_ST-1);
            cp16(sb2 + slot*MM_BS*2, W2g + (c + MM_ST-1)*16);
        }
        CP_COMMIT();

        const unsigned aS = aF + c*MM_AS*2;                      // T slot c (0..7)
        const unsigned bS = bF2 + (c & (MM_ST-1))*MM_BS*2;
        unsigned a[4][4], bq[4][2];
        #pragma unroll
        for (int mt = 0; mt < 4; mt++)
            ldsm4(a[mt][0], a[mt][1], a[mt][2], a[mt][3], aS + (mt*16*24)*2);
        #pragma unroll
        for (int np = 0; np < 2; np++)
            ldsm4(bq[2*np][0], bq[2*np][1], bq[2*np+1][0], bq[2*np+1][1],
                  bS + (np*16*24)*2);
        #pragma unroll
        for (int mt = 0; mt < 4; mt++)
            #pragma unroll
            for (int nt = 0; nt < 4; nt++)
                mma16(acc[mt][nt], a[mt], bq[nt]);
    }

    // ---- epilogue2: edge_h = (edge_h + acc + b2)*maskij ----
    #pragma unroll
    for (int mt = 0; mt < 4; mt++) {
        #pragma unroll
        for (int h = 0; h < 2; h++) {
            const int r = wm*64 + mt*16 + (lane >> 2) + h*8;
            const int grow = rowBase + r;
            float mij = g_maskij[grow];
            const float* ehp = g_edgeh + (size_t)grow * DE;
            #pragma unroll
            for (int nt = 0; nt < 4; nt++) {
                const int c0 = wn*32 + nt*8 + 2*(lane & 3);
                float2 bsv = *(const float2*)(bia2 + c0);
                float2 ev  = *(const float2*)(ehp + c0);
                float v0 = (ev.x + acc[mt][nt][h*2 + 0] + bsv.x) * mij;
                float v1 = (ev.y + acc[mt][nt][h*2 + 1] + bsv.y) * mij;
                *(float2*)(out + (size_t)grow*DE + c0) = make_float2(v0, v1);
                if (FLG) *(__half2*)(outh + (size_t)grow*DE + c0) = __floats2half2_rn(v0, v1);
            }
        }
    }
}

// ---------------- launch ----------------
extern "C" void kernel_launch(void* const* d_in, const int* in_sizes, int n_in,
                              void* d_out, int out_size)
{
    const float* X    = (const float*)d_in[0];
    const int*   C    = (const int*)  d_in[1];
    const float* Wn   = (const float*)d_in[2];
    const float* bn   = (const float*)d_in[3];
    const float* We   = (const float*)d_in[4];
    const float* be   = (const float*)d_in[5];
    const float* Wm1  = (const float*)d_in[6];
    const float* bm1  = (const float*)d_in[7];
    const float* Wm2  = (const float*)d_in[8];
    const float* bm2  = (const float*)d_in[9];
    const float* Wue1 = (const float*)d_in[10];
    const float* bue1 = (const float*)d_in[11];
    const float* Wue2 = (const float*)d_in[12];
    const float* bue2 = (const float*)d_in[13];
    float* out = (float*)d_out;

    cudaFuncSetAttribute(mm_tc<256,384,6,0,0>, cudaFuncAttributeMaxDynamicSharedMemorySize, MM_SMEM);
    cudaFuncSetAttribute(mm_tc<128,256,5,0,0>, cudaFuncAttributeMaxDynamicSharedMemorySize, MM_SMEM);
    cudaFuncSetAttribute(mm_tc<256,256,3,1,1>, cudaFuncAttributeMaxDynamicSharedMemorySize, MM_SMEM);
    cudaFuncSetAttribute(mm_tc<256,256,3,0,1>, cudaFuncAttributeMaxDynamicSharedMemorySize, MM_SMEM);
    cudaFuncSetAttribute(fused_edge<1>, cudaFuncAttributeMaxDynamicSharedMemorySize, FE_SMEM);
    cudaFuncSetAttribute(fused_edge<0>, cudaFuncAttributeMaxDynamicSharedMemorySize, FE_SMEM);
    cudaFuncSetAttribute(edge_init_kernel, cudaFuncAttributeMaxDynamicSharedMemorySize, EI_SMEM);

    float*  Ym;  cudaGetSymbolAddress((void**)&Ym,  g_Ym);
    float*  Ye;  cudaGetSymbolAddress((void**)&Ye,  g_Ye);
    float*  Eh;  cudaGetSymbolAddress((void**)&Eh,  g_edgeh);
    __half* Ehr; cudaGetSymbolAddress((void**)&Ehr, g_edgehr);
    float*  Nh;  cudaGetSymbolAddress((void**)&Nh,  g_nodeh);
    __half* Nhr; cudaGetSymbolAddress((void**)&Nhr, g_nodehr);
    float*  Ks;  cudaGetSymbolAddress((void**)&Ks,  g_ksum);
    __half* Wh;  cudaGetSymbolAddress((void**)&Wh,  g_Wh);

    round_w_kernel<<<512, 256>>>(Wm1, Wue1, Wm2, Wue2, We);
    frame_kernel<<<NNODE/8, 256>>>(X, C, Wn, bn);
    knn_kernel<<<NNODE/4, 128>>>(C);
    // fused edge features + init GEMM
    edge_init_kernel<<<ETOT/128, 256, EI_SMEM>>>(Wh + WT_WE, be, Eh, Ehr);

    for (int l = 0; l < NL; l++) {
        const __half* W1cat = Wh + WT_CAT + (size_t)l*2*384*256;
        const __half* W1me  = Wh + WT_E1M + (size_t)l*256*128;
        const __half* W1ue  = Wh + WT_E1E + (size_t)l*128*128;
        const __half* Wm2l  = Wh + WT_M2  + (size_t)l*256*256;
        const __half* Wue2l = Wh + WT_UE2 + (size_t)l*128*128;
        const bool last = (l == NL-1);

        zero_ksum_kernel<<<256, 256>>>();
        // node precompute (Ym + Ye fused)
        mm_tc<256, 384, 6, 0, 0><<<dim3(NNODE/128, 3, 2), 256, MM_SMEM>>>(
            Nhr, W1cat, nullptr, nullptr, nullptr, Ym, Ye, nullptr);
        // m-path stage-1 with fused masked k-reduction into g_ksum (reads Ehr)
        mm_tc<128, 256, 5, 0, 0><<<dim3(ETOT/128, 2), 256, MM_SMEM>>>(
            Ehr, W1me, bm1 + l*DN, Ym, Ym + (size_t)NNODE*DN, nullptr, nullptr, nullptr);
        // fused e-path stage-1 + edge update (t2 kept in smem; writes Eh/Ehr or final out)
        if (!last)
            fused_edge<1><<<ETOT/128, 256, FE_SMEM>>>(
                Ehr, W1ue, bue1 + l*DE, Ye, Ye + (size_t)NNODE*DE,
                Wue2l, bue2 + l*DE, Eh, Ehr);
        else
            fused_edge<0><<<ETOT/128, 256, FE_SMEM>>>(
                Ehr, W1ue, bue1 + l*DE, Ye, Ye + (size_t)NNODE*DE,
                Wue2l, bue2 + l*DE, out + S0OUT, nullptr);
        // node update (A = fp32 g_ksum, converted in loader — replaces round_ksum)
        if (!last)
            mm_tc<256, 256, 3, 1, 1><<<dim3(NNODE/128, 2), 256, MM_SMEM>>>(
                (const __half*)Ks, Wm2l, bm2 + l*DN, nullptr, nullptr, Nh, nullptr, Nhr);
        else
            mm_tc<256, 256, 3, 0, 1><<<dim3(NNODE/128, 2), 256, MM_SMEM>>>(
                (const __half*)Ks, Wm2l, bm2 + l*DN, nullptr, nullptr, out, nullptr, nullptr);
    }

    copy_tail_kernel<<<512, 256>>>(out + S0OUT + S1OUT);
}

// round 13
// speedup vs baseline: 1.1931x; 1.0036x over previous
#include <cuda_runtime.h>
#include <cuda_fp16.h>
#include <math.h>

// ---------------- problem constants ----------------
#define BB   2
#define NN   2048
#define KNB  30
#define DN   256
#define DE   128
#define NL   3
#define NFI  12
#define EFI  28
#define ETOT (BB*NN*KNB)  // 122880
#define NNODE (BB*NN)     // 4096
#define EPSF 1e-6f
#define BIGF 1e9f
#define FLTMAX 3.402823466e38f

#define S0OUT (NNODE*DN)
#define S1OUT (ETOT*DE)

// ---------------- scratch ----------------
__device__ float  g_nodeh [NNODE*DN];
__device__ __half g_nodehr[NNODE*DN];
__device__ float  g_edgeh [ETOT*DE];
__device__ __half g_edgehr[ETOT*DE];
__device__ int    g_eidx [ETOT];
__device__ float  g_maski[NNODE];
__device__ float  g_maskij[ETOT];
__device__ float  g_denom[NNODE];
__device__ float  g_cnt  [NNODE];
__device__ float  g_R  [NNODE*9];
__device__ float  g_Xc [NNODE*3];
__device__ float  g_Ym [2*NNODE*DN];
__device__ float  g_Ye [2*NNODE*DE];
__device__ float  g_ksum [NNODE*DN];       // fp32 atomic accum (MODE3 converts on load)

// transposed fp16 weight arena: W^T[n][k]
#define WT_CAT 0
#define WT_E1M (3*2*384*256)            // 589824
#define WT_E1E (WT_E1M + 3*256*128)     // 688128
#define WT_M2  (WT_E1E + 3*128*128)     // 737280
#define WT_UE2 (WT_M2  + 3*256*256)     // 933888
#define WT_WE  (WT_UE2 + 3*128*128)     // 983040
#define WT_TOT (WT_WE  + 128*32)        // 987136
__device__ __half g_Wh[WT_TOT];

__device__ __forceinline__ float softplus_f(float x) {
    return fmaxf(x, 0.0f) + log1pf(expf(-fabsf(x)));
}
__device__ __forceinline__ void mma16(float* c, const unsigned* a, const unsigned* b) {
    asm volatile(
        "mma.sync.aligned.m16n8k16.row.col.f32.f16.f16.f32 "
        "{%0,%1,%2,%3},{%4,%5,%6,%7},{%8,%9},{%0,%1,%2,%3};"
        : "+f"(c[0]), "+f"(c[1]), "+f"(c[2]), "+f"(c[3])
        : "r"(a[0]), "r"(a[1]), "r"(a[2]), "r"(a[3]), "r"(b[0]), "r"(b[1]));
}
__device__ __forceinline__ void ldsm4(unsigned& r0, unsigned& r1, unsigned& r2, unsigned& r3,
                                      unsigned addr) {
    asm volatile("ldmatrix.sync.aligned.m8n8.x4.shared.b16 {%0,%1,%2,%3}, [%4];"
        : "=r"(r0), "=r"(r1), "=r"(r2), "=r"(r3) : "r"(addr));
}
__device__ __forceinline__ void cp16(unsigned dst, const void* src) {
    asm volatile("cp.async.cg.shared.global [%0], [%1], 16;" :: "r"(dst), "l"(src));
}
#define CP_COMMIT() asm volatile("cp.async.commit_group;")
#define CP_WAIT2()  asm volatile("cp.async.wait_group 2;")
#define CP_WAIT0()  asm volatile("cp.async.wait_group 0;")

// ---------------- 0) round + transpose + repack all weights to fp16 ----------------
__global__ void round_w_kernel(const float* __restrict__ Wm1, const float* __restrict__ Wue1,
                               const float* __restrict__ Wm2, const float* __restrict__ Wue2,
                               const float* __restrict__ We)
{
    for (int i = blockIdx.x*blockDim.x + threadIdx.x; i < WT_TOT; i += gridDim.x*blockDim.x) {
        float v;
        if (i < WT_E1M) {                       // [l][z][n<384][k<256]
            int l = i / 196608, r = i % 196608;
            int z = r / 98304,  q = r % 98304;
            int n = q / 256,    k = q % 256;
            v = (n < 256) ? Wm1 [((size_t)l*640 + z*256 + k)*256 + n]
                          : Wue1[((size_t)l*640 + z*256 + k)*128 + (n - 256)];
        } else if (i < WT_E1E) {                // [l][n<256][k<128]
            int r = i - WT_E1M;
            int l = r / 32768, q = r % 32768;
            int n = q / 128,   k = q % 128;
            v = Wm1[((size_t)l*640 + 512 + k)*256 + n];
        } else if (i < WT_M2) {                 // [l][n<128][k<128]
            int r = i - WT_E1E;
            int l = r / 16384, q = r % 16384;
            int n = q / 128,   k = q % 128;
            v = Wue1[((size_t)l*640 + 512 + k)*128 + n];
        } else if (i < WT_UE2) {                // [l][n<256][k<256]
            int r = i - WT_M2;
            int l = r / 65536, q = r % 65536;
            int n = q / 256,   k = q % 256;
            v = Wm2[((size_t)l*256 + k)*256 + n];
        } else if (i < WT_WE) {                 // [l][n<128][k<128]
            int r = i - WT_UE2;
            int l = r / 16384, q = r % 16384;
            int n = q / 128,   k = q % 128;
            v = Wue2[((size_t)l*128 + k)*128 + n];
        } else {                                // [n<128][k<32]
            int r = i - WT_WE;
            int n = r / 32, k = r % 32;
            v = (k < EFI) ? We[k*128 + n] : 0.0f;
        }
        g_Wh[i] = __float2half_rn(v);
    }
}

// ---------------- 1) per-node frame, features, node_h init ----------------
__global__ void frame_kernel(const float* __restrict__ X, const int* __restrict__ C,
                             const float* __restrict__ Wn, const float* __restrict__ bn)
{
    __shared__ float s_feat[8][12];
    __shared__ float s_mask[8];
    int warp = threadIdx.x >> 5;
    int lane = threadIdx.x & 31;
    int nlin = blockIdx.x * 8 + warp;

    if (lane == 0) {
        const float* xr = X + (size_t)nlin * 12;
        float Na[3], CA[3], Ct[3], Oa[3];
        #pragma unroll
        for (int d = 0; d < 3; d++) { Na[d]=xr[d]; CA[d]=xr[3+d]; Ct[d]=xr[6+d]; Oa[d]=xr[9+d]; }
        #pragma unroll
        for (int d = 0; d < 3; d++) {
            float s = __fadd_rn(__fadd_rn(__fadd_rn(Na[d], CA[d]), Ct[d]), Oa[d]);
            g_Xc[nlin*3 + d] = __fmul_rn(s, 0.25f);
        }
        float b1[3], b2[3], b3[3], v0[3];
        #pragma unroll
        for (int d = 0; d < 3; d++) {
            b1[d] = CA[d] - Na[d];
            b2[d] = Ct[d] - CA[d];
            b3[d] = Oa[d] - Ct[d];
            v0[d] = Na[d] - CA[d];
        }
        float nb2 = sqrtf(b2[0]*b2[0] + b2[1]*b2[1] + b2[2]*b2[2]);
        float u[3];
        #pragma unroll
        for (int d = 0; d < 3; d++) u[d] = b2[d] / (nb2 + EPSF);
        float dotv = v0[0]*u[0] + v0[1]*u[1] + v0[2]*u[2];
        float t[3];
        #pragma unroll
        for (int d = 0; d < 3; d++) t[d] = v0[d] - dotv * u[d];
        float nt = sqrtf(t[0]*t[0] + t[1]*t[1] + t[2]*t[2]);
        float v[3];
        #pragma unroll
        for (int d = 0; d < 3; d++) v[d] = t[d] / (nt + EPSF);
        float w[3];
        w[0] = u[1]*v[2] - u[2]*v[1];
        w[1] = u[2]*v[0] - u[0]*v[2];
        w[2] = u[0]*v[1] - u[1]*v[0];
        #pragma unroll
        for (int d = 0; d < 3; d++) {
            g_R[nlin*9 + d*3 + 0] = u[d];
            g_R[nlin*9 + d*3 + 1] = v[d];
            g_R[nlin*9 + d*3 + 2] = w[d];
        }
        float nb1 = sqrtf(b1[0]*b1[0] + b1[1]*b1[1] + b1[2]*b1[2]);
        float nb3 = sqrtf(b3[0]*b3[0] + b3[1]*b3[1] + b3[2]*b3[2]);
        #pragma unroll
        for (int d = 0; d < 3; d++) {
            s_feat[warp][0 + d] = b1[d] / (nb1 + EPSF);
            s_feat[warp][4 + d] = b2[d] / (nb2 + EPSF);
            s_feat[warp][8 + d] = b3[d] / (nb3 + EPSF);
        }
        s_feat[warp][3]  = logf(nb1 + EPSF);
        s_feat[warp][7]  = logf(nb2 + EPSF);
        s_feat[warp][11] = logf(nb3 + EPSF);
        float mk = (C[nlin] > 0) ? 1.0f : 0.0f;
        s_mask[warp] = mk;
        g_maski[nlin] = mk;
    }
    __syncwarp();

    float f[12];
    #pragma unroll
    for (int i = 0; i < 12; i++) f[i] = s_feat[warp][i];
    float mk = s_mask[warp];
    #pragma unroll
    for (int r = 0; r < 8; r++) {
        int c = lane + r * 32;
        float acc = bn[c];
        #pragma unroll
        for (int ff = 0; ff < NFI; ff++) acc += f[ff] * Wn[ff*DN + c];
        float v = acc * mk;
        g_nodeh [(size_t)nlin*DN + c] = v;
        g_nodehr[(size_t)nlin*DN + c] = __float2half_rn(v);
    }
}

// ---------------- 2) kNN: warp-per-node + fused tail output ----------------
// out_tail layout: [eidx ETOT][maski NNODE][maskij ETOT]
__global__ __launch_bounds__(128) void knn_kernel(const int* __restrict__ C,
                                                  float* __restrict__ out_tail)
{
    __shared__ float s_d2[4][NN];
    int wid = threadIdx.x >> 5;
    int lane = threadIdx.x & 31;
    int nlin = blockIdx.x * 4 + wid;
    int b = nlin >> 11;
    int n = nlin & (NN - 1);

    float xi0 = g_Xc[nlin*3+0], xi1 = g_Xc[nlin*3+1], xi2 = g_Xc[nlin*3+2];
    const int* Cb = C + b*NN;
    for (int j = lane; j < NN; j += 32) {
        float dx = __fadd_rn(xi0, -g_Xc[(size_t)(b*NN + j)*3 + 0]);
        float dy = __fadd_rn(xi1, -g_Xc[(size_t)(b*NN + j)*3 + 1]);
        float dz = __fadd_rn(xi2, -g_Xc[(size_t)(b*NN + j)*3 + 2]);
        float d2 = __fadd_rn(__fadd_rn(__fmul_rn(dx,dx), __fmul_rn(dy,dy)), __fmul_rn(dz,dz));
        if (Cb[j] <= 0) d2 = __fadd_rn(d2, BIGF);
        if (j == n)     d2 = __fadd_rn(d2, BIGF);
        s_d2[wid][j] = d2;
    }
    __syncwarp();

    float mi = g_maski[nlin];
    float cnt = 0.0f;
    for (int kk = 0; kk < KNB; kk++) {
        float bv = FLTMAX; int bi = 0x7fffffff;
        #pragma unroll 4
        for (int j = lane; j < NN; j += 32) {
            float v = s_d2[wid][j];
            if (v < bv || (v == bv && j < bi)) { bv = v; bi = j; }
        }
        #pragma unroll
        for (int off = 16; off > 0; off >>= 1) {
            float v2 = __shfl_down_sync(0xffffffffu, bv, off);
            int   i2 = __shfl_down_sync(0xffffffffu, bi, off);
            if (v2 < bv || (v2 == bv && i2 < bi)) { bv = v2; bi = i2; }
        }
        bi = __shfl_sync(0xffffffffu, bi, 0);
        if (lane == 0) {
            int e = nlin*KNB + kk;
            g_eidx[e] = bi;
            float mj = (Cb[bi] > 0) ? 1.0f : 0.0f;
            float mij = mi * mj;
            g_maskij[e] = mij;
            cnt += mij;
            s_d2[wid][bi] = FLTMAX;
            out_tail[e] = (float)bi;
            out_tail[ETOT + NNODE + e] = mij;
        }
        __syncwarp();
    }
    if (lane == 0) {
        g_cnt[nlin] = cnt;
        g_denom[nlin] = cnt + EPSF;
        out_tail[ETOT + nlin] = mi;
    }
}

#define MM_ST 4
#define MM_AS (128*24)                    // halfs per A stage (pad 16->24)
#define MM_BS (128*24)                    // halfs per B stage
#define MM_SMEM 66560                     // max(4*(AS+BS)*2 = 49152, 128*130*4)

// ---------------- 3) fused edge-init: features computed in-kernel, GEMM vs We ----------------
// Feature work split: thread t<128 computes edge t's RBF (cols 0..15 -> chunk 0);
// thread t>=128 computes edge (t-128)'s dir+Rrel (cols 16..31 -> chunk 1).
#define EI_SMEM (4*MM_AS*2)               // 2 A slots + 2 B slots = 24576

__global__ __launch_bounds__(256, 2) void edge_init_kernel(
    const __half* __restrict__ W, const float* __restrict__ bias,
    float* __restrict__ out, __half* __restrict__ outh)
{
    extern __shared__ float smem_dyn[];
    __half* Asm = (__half*)smem_dyn;        // 2 slots [128][24]
    __half* Bsm = Asm + 2*MM_AS;            // 2 slots [128][24]

    const int tid  = threadIdx.x;
    const int lane = tid & 31;
    const int wid  = tid >> 5;
    const int wm   = wid & 1;
    const int wn   = wid >> 1;
    const int rowBase = blockIdx.x * 128;

    // B loader: W^T[128][32]; chunk s covers k in [16s, 16s+16)
    const int laR = tid >> 1, laK = (tid & 1) * 8;
    const unsigned sb = (unsigned)__cvta_generic_to_shared(Bsm) + (laR*24 + laK)*2;
    cp16(sb + 0*MM_BS*2, W + laR*32 + laK);
    cp16(sb + 1*MM_BS*2, W + laR*32 + 16 + laK);
    CP_COMMIT();

    // features: 2 threads per edge (identical fp32 math / rounding as before)
    {
        const int eLoc = tid & 127;
        const int half = tid >> 7;
        int e = rowBase + eLoc;
        int nlin = e / KNB;
        int b = nlin >> 11;
        int j = g_eidx[e];
        int jl = b*NN + j;

        float dv[3];
        #pragma unroll
        for (int d = 0; d < 3; d++) dv[d] = g_Xc[jl*3+d] - g_Xc[nlin*3+d];
        float dist = sqrtf(dv[0]*dv[0] + dv[1]*dv[1] + dv[2]*dv[2]);

        if (half == 0) {
            float f[16];
            #pragma unroll
            for (int mc = 0; mc < 16; mc++) {
                float cm = (float)(20.0 * mc / 15.0);
                float z = (dist - cm) * 0.8f;
                f[mc] = expf(-z*z);
            }
            #pragma unroll
            for (int q = 0; q < 8; q++)
                *(__half2*)(Asm + 0*MM_AS + eLoc*24 + 2*q) = __floats2half2_rn(f[2*q], f[2*q+1]);
        } else {
            float Ri[9], Rj[9];
            #pragma unroll
            for (int q = 0; q < 9; q++) { Ri[q] = g_R[nlin*9+q]; Rj[q] = g_R[jl*9+q]; }
            float f[16];
            float inv = 1.0f / (dist + EPSF);
            #pragma unroll
            for (int c = 0; c < 3; c++) {
                float loc = Ri[0*3+c]*dv[0] + Ri[1*3+c]*dv[1] + Ri[2*3+c]*dv[2];
                f[c] = loc * inv;
            }
            #pragma unroll
            for (int ee = 0; ee < 3; ee++)
                #pragma unroll
                for (int ff = 0; ff < 3; ff++)
                    f[3 + ee*3 + ff] = Ri[0*3+ee]*Rj[0*3+ff] + Ri[1*3+ee]*Rj[1*3+ff] + Ri[2*3+ee]*Rj[2*3+ff];
            f[12] = f[13] = f[14] = f[15] = 0.0f;
            #pragma unroll
            for (int q = 0; q < 8; q++)
                *(__half2*)(Asm + 1*MM_AS + eLoc*24 + 2*q) = __floats2half2_rn(f[2*q], f[2*q+1]);
        }
    }
    CP_WAIT0();
    __syncthreads();

    const unsigned aF = (unsigned)__cvta_generic_to_shared(Asm)
        + (((wm*64 + (lane & 15))*24 + (lane >> 4)*8) * 2);
    const unsigned bF = (unsigned)__cvta_generic_to_shared(Bsm)
        + (((wn*32 + (lane & 7) + ((lane >> 4) & 1)*8)*24 + ((lane >> 3) & 1)*8) * 2);

    float acc[4][4][4];
    #pragma unroll
    for (int i = 0; i < 4; i++)
        #pragma unroll
        for (int j = 0; j < 4; j++)
            #pragma unroll
            for (int q = 0; q < 4; q++) acc[i][j][q] = 0.0f;

    #pragma unroll
    for (int c = 0; c < 2; c++) {
        const unsigned aS = aF + c*MM_AS*2;
        const unsigned bS = bF + c*MM_BS*2;
        unsigned a[4][4], bq[4][2];
        #pragma unroll
        for (int mt = 0; mt < 4; mt++)
            ldsm4(a[mt][0], a[mt][1], a[mt][2], a[mt][3], aS + (mt*16*24)*2);
        #pragma unroll
        for (int np = 0; np < 2; np++)
            ldsm4(bq[2*np][0], bq[2*np][1], bq[2*np+1][0], bq[2*np+1][1],
                  bS + (np*16*24)*2);
        #pragma unroll
        for (int mt = 0; mt < 4; mt++)
            #pragma unroll
            for (int nt = 0; nt < 4; nt++)
                mma16(acc[mt][nt], a[mt], bq[nt]);
    }

    #pragma unroll
    for (int mt = 0; mt < 4; mt++) {
        #pragma unroll
        for (int h = 0; h < 2; h++) {
            const int r = wm*64 + mt*16 + (lane >> 2) + h*8;
            const int grow = rowBase + r;
            float mij = g_maskij[grow];
            #pragma unroll
            for (int nt = 0; nt < 4; nt++) {
                const int c0 = wn*32 + nt*8 + 2*(lane & 3);
                float2 bsv = *(const float2*)(bias + c0);
                float v0 = (acc[mt][nt][h*2 + 0] + bsv.x) * mij;
                float v1 = (acc[mt][nt][h*2 + 1] + bsv.y) * mij;
                *(float2*)(out + (size_t)grow*DE + c0) = make_float2(v0, v1);
                *(__half2*)(outh + (size_t)grow*DE + c0) = __floats2half2_rn(v0, v1);
            }
        }
    }
}

// ---------------- 4) fp16 TC GEMM (m16n8k16), 4-stage cp.async + ldmatrix ----------------
// MODE 3: node_h = (node_h + (A@W + cnt*bias)/denom)*mask_i [FLG: + shadow]
//         (A32=1: A is fp32, converted in loader with __float2half_rn)
// MODE 5: m-path stage-1: masked softplus -> smem reduce -> atomic g_ksum
// MODE 6: node precompute cat: cols<256 -> out(Ym)[z], cols>=256 -> out2(Ye)[z]
//         (y==0,z==0 blocks also zero their g_ksum slice)
template<int KD, int NF, int MODE, int FLG, int A32>
__global__ __launch_bounds__(256, 2) void mm_tc(
    const __half* __restrict__ A, const __half* __restrict__ W,
    const float* __restrict__ bias,
    const float* __restrict__ Yi, const float* __restrict__ Zj,
    float* __restrict__ out, float* __restrict__ out2, __half* __restrict__ outh)
{
    constexpr int CH = KD / 16;
    extern __shared__ float smem_dyn[];
    __half* Asm = (__half*)smem_dyn;
    __half* Bsm = Asm + MM_ST*MM_AS;

    const int tid  = threadIdx.x;
    const int lane = tid & 31;
    const int wid  = tid >> 5;
    const int wm   = wid & 1;
    const int wn   = wid >> 1;

    const int rowBase = blockIdx.x * 128;
    const int n0 = blockIdx.y * 128;

    const __half* Wp = W;
    if (MODE == 6) Wp = W + (size_t)blockIdx.z * 384 * 256;

    const int laR = tid >> 1, laK = (tid & 1) * 8;
    const __half* Ag  = A + (size_t)(rowBase + laR) * KD + laK;
    const float*  Agf = (const float*)A + (size_t)(rowBase + laR) * KD + laK;
    const __half* Wg = Wp + (size_t)(n0 + laR) * KD + laK;

    const unsigned sa = (unsigned)__cvta_generic_to_shared(Asm) + (laR*24 + laK)*2;
    const unsigned sb = (unsigned)__cvta_generic_to_shared(Bsm) + (laR*24 + laK)*2;
    __half* AsmT = Asm + laR*24 + laK;

    const unsigned aF = (unsigned)__cvta_generic_to_shared(Asm)
        + (((wm*64 + (lane & 15))*24 + (lane >> 4)*8) * 2);
    const unsigned bF = (unsigned)__cvta_generic_to_shared(Bsm)
        + (((wn*32 + (lane & 7) + ((lane >> 4) & 1)*8)*24 + ((lane >> 3) & 1)*8) * 2);

    #pragma unroll
    for (int s = 0; s < MM_ST-1; s++) {
        if (s < CH) {
            if (A32) {
                float4 f0 = *(const float4*)(Agf + s*16);
                float4 f1 = *(const float4*)(Agf + s*16 + 4);
                __half2 hh[4] = {__floats2half2_rn(f0.x,f0.y), __floats2half2_rn(f0.z,f0.w),
                                 __floats2half2_rn(f1.x,f1.y), __floats2half2_rn(f1.z,f1.w)};
                *(uint4*)(AsmT + s*MM_AS) = *(uint4*)hh;
            } else {
                cp16(sa + s*MM_AS*2, Ag + s*16);
            }
            cp16(sb + s*MM_BS*2, Wg + s*16);
        }
        CP_COMMIT();
    }

    // MODE 6: fused g_ksum zeroing (replaces zero_ksum kernel); overlaps prologue
    if (MODE == 6 && blockIdx.y == 0 && blockIdx.z == 0) {
        float4* p = (float4*)(g_ksum + (size_t)rowBase * DN);
        for (int i = tid; i < 128*DN/4; i += 256)
            p[i] = make_float4(0.f, 0.f, 0.f, 0.f);
    }

    float acc[4][4][4];
    #pragma unroll
    for (int i = 0; i < 4; i++)
        #pragma unroll
        for (int j = 0; j < 4; j++)
            #pragma unroll
            for (int q = 0; q < 4; q++) acc[i][j][q] = 0.0f;

    #pragma unroll 1
    for (int c = 0; c < CH; c++) {
        CP_WAIT2();
        __syncthreads();

        if (c + MM_ST-1 < CH) {
            const int slot = (c + MM_ST-1) & (MM_ST-1);
            const int cc = c + MM_ST-1;
            if (A32) {
                float4 f0 = *(const float4*)(Agf + cc*16);
                float4 f1 = *(const float4*)(Agf + cc*16 + 4);
                __half2 hh[4] = {__floats2half2_rn(f0.x,f0.y), __floats2half2_rn(f0.z,f0.w),
                                 __floats2half2_rn(f1.x,f1.y), __floats2half2_rn(f1.z,f1.w)};
                *(uint4*)(AsmT + slot*MM_AS) = *(uint4*)hh;
            } else {
                cp16(sa + slot*MM_AS*2, Ag + cc*16);
            }
            cp16(sb + slot*MM_BS*2, Wg + cc*16);
        }
        CP_COMMIT();

        const unsigned aS = aF + (c & (MM_ST-1))*MM_AS*2;
        const unsigned bS = bF + (c & (MM_ST-1))*MM_BS*2;

        unsigned a[4][4], bq[4][2];
        #pragma unroll
        for (int mt = 0; mt < 4; mt++)
            ldsm4(a[mt][0], a[mt][1], a[mt][2], a[mt][3], aS + (mt*16*24)*2);
        #pragma unroll
        for (int np = 0; np < 2; np++)
            ldsm4(bq[2*np][0], bq[2*np][1], bq[2*np+1][0], bq[2*np+1][1],
                  bS + (np*16*24)*2);
        #pragma unroll
        for (int mt = 0; mt < 4; mt++)
            #pragma unroll
            for (int nt = 0; nt < 4; nt++)
                mma16(acc[mt][nt], a[mt], bq[nt]);
    }

    // ---------------- epilogue ----------------
    float* sred = smem_dyn;
    if (MODE == 5) __syncthreads();

    #pragma unroll
    for (int mt = 0; mt < 4; mt++) {
        #pragma unroll
        for (int h = 0; h < 2; h++) {
            const int r = wm*64 + mt*16 + (lane >> 2) + h*8;
            const int grow = rowBase + r;

            const float* yip = nullptr; const float* zjp = nullptr;
            float mij = 0.f, dn = 1.f, mi = 0.f, cn = 0.f;
            const float* nhp = nullptr;
            if (MODE == 5) {
                int nlin = grow / KNB;
                int b = nlin >> 11;
                yip = Yi + (size_t)nlin * NF + n0;
                zjp = Zj + (size_t)(b*NN + g_eidx[grow]) * NF + n0;
                mij = g_maskij[grow];
            } else if (MODE == 3) {
                dn = g_denom[grow]; mi = g_maski[grow]; cn = g_cnt[grow];
                nhp = g_nodeh + (size_t)grow * DN + n0;
            }

            #pragma unroll
            for (int nt = 0; nt < 4; nt++) {
                const int c0 = wn*32 + nt*8 + 2*(lane & 3);
                float v0 = acc[mt][nt][h*2 + 0];
                float v1 = acc[mt][nt][h*2 + 1];
                if (MODE == 6) {
                    float* op;
                    if (n0 < 256) op = out  + (size_t)blockIdx.z*NNODE*DN + (size_t)grow*DN + n0;
                    else          op = out2 + (size_t)blockIdx.z*NNODE*DE + (size_t)grow*DE + (n0-256);
                    *(float2*)(op + c0) = make_float2(v0, v1);
                } else if (MODE == 5) {
                    float2 bsv = *(const float2*)(bias + n0 + c0);
                    float2 yv  = *(const float2*)(yip + c0);
                    float2 zv  = *(const float2*)(zjp + c0);
                    v0 = softplus_f(v0 + bsv.x + yv.x + zv.x) * mij;
                    v1 = softplus_f(v1 + bsv.y + yv.y + zv.y) * mij;
                    sred[r*130 + c0]     = v0;
                    sred[r*130 + c0 + 1] = v1;
                } else { // MODE 3
                    float2 bsv = *(const float2*)(bias + n0 + c0);
                    float2 nv  = *(const float2*)(nhp + c0);
                    v0 = (nv.x + (v0 + cn*bsv.x) / dn) * mi;
                    v1 = (nv.y + (v1 + cn*bsv.y) / dn) * mi;
                    *(float2*)(out + (size_t)grow*NF + n0 + c0) = make_float2(v0, v1);
                    if (FLG) *(__half2*)(outh + (size_t)grow*NF + n0 + c0) = __floats2half2_rn(v0, v1);
                }
            }
        }
    }

    if (MODE == 5) {
        __syncthreads();
        if (tid < 128) {
            const int c = tid;
            const int nfirst = rowBase / KNB;
            const int nlast  = (rowBase + 127) / KNB;
            for (int n = nfirst; n <= nlast; n++) {
                int r0 = n*KNB - rowBase;
                int r1 = r0 + KNB;
                r0 = r0 < 0 ? 0 : r0;
                r1 = r1 > 128 ? 128 : r1;
                float s = 0.0f;
                for (int r = r0; r < r1; r++) s += sred[r*130 + c];
                atomicAdd(&g_ksum[(size_t)n*DN + n0 + c], s);
            }
        }
    }
}

// ---------------- 5) fused e-path: t2 = softplus(A@W1 + b1 + Yi + Zj) in smem,
//                    then edge_h = (edge_h + t2@W2 + b2)*maskij  [FLG: +fp16 shadow]
#define FE_SMEM ((8*MM_AS + 4*MM_BS)*2)   // 73728

template<int FLG>
__global__ __launch_bounds__(256, 2) void fused_edge(
    const __half* __restrict__ A, const __half* __restrict__ W1,
    const float* __restrict__ bia1,
    const float* __restrict__ Yi, const float* __restrict__ Zj,
    const __half* __restrict__ W2, const float* __restrict__ bia2,
    float* __restrict__ out, __half* __restrict__ outh)
{
    constexpr int KD = 128, CH = 8;
    extern __shared__ float smem_dyn[];
    __half* Asm  = (__half*)smem_dyn;           // GEMM1 A stages (slots 0..3)
    __half* Bsm  = Asm + MM_ST*MM_AS;           // GEMM1 B stages (slots 0..3)
    __half* Tm   = Asm;                         // T buffer: 8 slots of MM_AS (aliases stages)
    __half* B2sm = Asm + 8*MM_AS;               // GEMM2 B stages (slots 0..3)

    const int tid  = threadIdx.x;
    const int lane = tid & 31;
    const int wid  = tid >> 5;
    const int wm   = wid & 1;
    const int wn   = wid >> 1;
    const int rowBase = blockIdx.x * 128;

    const int laR = tid >> 1, laK = (tid & 1) * 8;
    const __half* Ag  = A  + (size_t)(rowBase + laR) * KD + laK;
    const __half* W1g = W1 + (size_t)laR * KD + laK;
    const __half* W2g = W2 + (size_t)laR * KD + laK;

    const unsigned sa  = (unsigned)__cvta_generic_to_shared(Asm)  + (laR*24 + laK)*2;
    const unsigned sb  = (unsigned)__cvta_generic_to_shared(Bsm)  + (laR*24 + laK)*2;
    const unsigned sb2 = (unsigned)__cvta_generic_to_shared(B2sm) + (laR*24 + laK)*2;

    const unsigned aF = (unsigned)__cvta_generic_to_shared(Asm)
        + (((wm*64 + (lane & 15))*24 + (lane >> 4)*8) * 2);
    const unsigned bF = (unsigned)__cvta_generic_to_shared(Bsm)
        + (((wn*32 + (lane & 7) + ((lane >> 4) & 1)*8)*24 + ((lane >> 3) & 1)*8) * 2);
    const unsigned bF2 = (unsigned)__cvta_generic_to_shared(B2sm)
        + (((wn*32 + (lane & 7) + ((lane >> 4) & 1)*8)*24 + ((lane >> 3) & 1)*8) * 2);

    // ---- GEMM1 prologue ----
    #pragma unroll
    for (int s = 0; s < MM_ST-1; s++) {
        cp16(sa + s*MM_AS*2, Ag + s*16);
        cp16(sb + s*MM_BS*2, W1g + s*16);
        CP_COMMIT();
    }

    float acc[4][4][4];
    #pragma unroll
    for (int i = 0; i < 4; i++)
        #pragma unroll
        for (int j = 0; j < 4; j++)
            #pragma unroll
            for (int q = 0; q < 4; q++) acc[i][j][q] = 0.0f;

    // ---- GEMM1 mainloop ----
    #pragma unroll 1
    for (int c = 0; c < CH; c++) {
        CP_WAIT2();
        __syncthreads();
        if (c + MM_ST-1 < CH) {
            const int slot = (c + MM_ST-1) & (MM_ST-1);
            const int cc = c + MM_ST-1;
            cp16(sa + slot*MM_AS*2, Ag + cc*16);
            cp16(sb + slot*MM_BS*2, W1g + cc*16);
        }
        CP_COMMIT();

        const unsigned aS = aF + (c & (MM_ST-1))*MM_AS*2;
        const unsigned bS = bF + (c & (MM_ST-1))*MM_BS*2;
        unsigned a[4][4], bq[4][2];
        #pragma unroll
        for (int mt = 0; mt < 4; mt++)
            ldsm4(a[mt][0], a[mt][1], a[mt][2], a[mt][3], aS + (mt*16*24)*2);
        #pragma unroll
        for (int np = 0; np < 2; np++)
            ldsm4(bq[2*np][0], bq[2*np][1], bq[2*np+1][0], bq[2*np+1][1],
                  bS + (np*16*24)*2);
        #pragma unroll
        for (int mt = 0; mt < 4; mt++)
            #pragma unroll
            for (int nt = 0; nt < 4; nt++)
                mma16(acc[mt][nt], a[mt], bq[nt]);
    }

    __syncthreads();   // all warps done reading stage buffers (T may now alias them)

    // ---- GEMM2 B prologue (into disjoint B2 region; overlaps epilogue1 math) ----
    #pragma unroll
    for (int s = 0; s < MM_ST-1; s++) {
        cp16(sb2 + s*MM_BS*2, W2g + s*16);
        CP_COMMIT();
    }

    // ---- epilogue1: t2 = softplus(acc + b1 + Yi + Zj) -> T (fp16, ldmatrix layout) ----
    #pragma unroll
    for (int mt = 0; mt < 4; mt++) {
        #pragma unroll
        for (int h = 0; h < 2; h++) {
            const int r = wm*64 + mt*16 + (lane >> 2) + h*8;
            const int grow = rowBase + r;
            int nlin = grow / KNB;
            int b = nlin >> 11;
            const float* yip = Yi + (size_t)nlin * DE;
            const float* zjp = Zj + (size_t)(b*NN + g_eidx[grow]) * DE;
            #pragma unroll
            for (int nt = 0; nt < 4; nt++) {
                const int c0 = wn*32 + nt*8 + 2*(lane & 3);
                float2 bsv = *(const float2*)(bia1 + c0);
                float2 yv  = *(const float2*)(yip + c0);
                float2 zv  = *(const float2*)(zjp + c0);
                float v0 = softplus_f(acc[mt][nt][h*2 + 0] + bsv.x + yv.x + zv.x);
                float v1 = softplus_f(acc[mt][nt][h*2 + 1] + bsv.y + yv.y + zv.y);
                *(__half2*)(Tm + (c0 >> 4)*MM_AS + r*24 + (c0 & 15)) =
                    __floats2half2_rn(v0, v1);
            }
        }
    }

    // ---- reset accumulators ----
    #pragma unroll
    for (int i = 0; i < 4; i++)
        #pragma unroll
        for (int j = 0; j < 4; j++)
            #pragma unroll
            for (int q = 0; q < 4; q++) acc[i][j][q] = 0.0f;

    // ---- GEMM2 mainloop: A = T (smem-resident, 8 slots), B staged ----
    #pragma unroll 1
    for (int c = 0; c < CH; c++) {
        CP_WAIT2();
        __syncthreads();
        if (c + MM_ST-1 < CH) {
            const int slot = (c + MM_ST-1) & (MM_ST-1);
            cp16(sb2 + slot*MM_BS*2, W2g + (c + MM_ST-1)*16);
        }
        CP_COMMIT();

        const unsigned aS = aF + c*MM_AS*2;                      // T slot c (0..7)
        const unsigned bS = bF2 + (c & (MM_ST-1))*MM_BS*2;
        unsigned a[4][4], bq[4][2];
        #pragma unroll
        for (int mt = 0; mt < 4; mt++)
            ldsm4(a[mt][0], a[mt][1], a[mt][2], a[mt][3], aS + (mt*16*24)*2);
        #pragma unroll
        for (int np = 0; np < 2; np++)
            ldsm4(bq[2*np][0], bq[2*np][1], bq[2*np+1][0], bq[2*np+1][1],
                  bS + (np*16*24)*2);
        #pragma unroll
        for (int mt = 0; mt < 4; mt++)
            #pragma unroll
            for (int nt = 0; nt < 4; nt++)
                mma16(acc[mt][nt], a[mt], bq[nt]);
    }

    // ---- epilogue2: edge_h = (edge_h + acc + b2)*maskij ----
    #pragma unroll
    for (int mt = 0; mt < 4; mt++) {
        #pragma unroll
        for (int h = 0; h < 2; h++) {
            const int r = wm*64 + mt*16 + (lane >> 2) + h*8;
            const int grow = rowBase + r;
            float mij = g_maskij[grow];
            const float* ehp = g_edgeh + (size_t)grow * DE;
            #pragma unroll
            for (int nt = 0; nt < 4; nt++) {
                const int c0 = wn*32 + nt*8 + 2*(lane & 3);
                float2 bsv = *(const float2*)(bia2 + c0);
                float2 ev  = *(const float2*)(ehp + c0);
                float v0 = (ev.x + acc[mt][nt][h*2 + 0] + bsv.x) * mij;
                float v1 = (ev.y + acc[mt][nt][h*2 + 1] + bsv.y) * mij;
                *(float2*)(out + (size_t)grow*DE + c0) = make_float2(v0, v1);
                if (FLG) *(__half2*)(outh + (size_t)grow*DE + c0) = __floats2half2_rn(v0, v1);
            }
        }
    }
}

// ---------------- launch ----------------
extern "C" void kernel_launch(void* const* d_in, const int* in_sizes, int n_in,
                              void* d_out, int out_size)
{
    const float* X    = (const float*)d_in[0];
    const int*   C    = (const int*)  d_in[1];
    const float* Wn   = (const float*)d_in[2];
    const float* bn   = (const float*)d_in[3];
    const float* We   = (const float*)d_in[4];
    const float* be   = (const float*)d_in[5];
    const float* Wm1  = (const float*)d_in[6];
    const float* bm1  = (const float*)d_in[7];
    const float* Wm2  = (const float*)d_in[8];
    const float* bm2  = (const float*)d_in[9];
    const float* Wue1 = (const float*)d_in[10];
    const float* bue1 = (const float*)d_in[11];
    const float* Wue2 = (const float*)d_in[12];
    const float* bue2 = (const float*)d_in[13];
    float* out = (float*)d_out;

    cudaFuncSetAttribute(mm_tc<256,384,6,0,0>, cudaFuncAttributeMaxDynamicSharedMemorySize, MM_SMEM);
    cudaFuncSetAttribute(mm_tc<128,256,5,0,0>, cudaFuncAttributeMaxDynamicSharedMemorySize, MM_SMEM);
    cudaFuncSetAttribute(mm_tc<256,256,3,1,1>, cudaFuncAttributeMaxDynamicSharedMemorySize, MM_SMEM);
    cudaFuncSetAttribute(mm_tc<256,256,3,0,1>, cudaFuncAttributeMaxDynamicSharedMemorySize, MM_SMEM);
    cudaFuncSetAttribute(fused_edge<1>, cudaFuncAttributeMaxDynamicSharedMemorySize, FE_SMEM);
    cudaFuncSetAttribute(fused_edge<0>, cudaFuncAttributeMaxDynamicSharedMemorySize, FE_SMEM);
    cudaFuncSetAttribute(edge_init_kernel, cudaFuncAttributeMaxDynamicSharedMemorySize, EI_SMEM);

    float*  Ym;  cudaGetSymbolAddress((void**)&Ym,  g_Ym);
    float*  Ye;  cudaGetSymbolAddress((void**)&Ye,  g_Ye);
    float*  Eh;  cudaGetSymbolAddress((void**)&Eh,  g_edgeh);
    __half* Ehr; cudaGetSymbolAddress((void**)&Ehr, g_edgehr);
    float*  Nh;  cudaGetSymbolAddress((void**)&Nh,  g_nodeh);
    __half* Nhr; cudaGetSymbolAddress((void**)&Nhr, g_nodehr);
    float*  Ks;  cudaGetSymbolAddress((void**)&Ks,  g_ksum);
    __half* Wh;  cudaGetSymbolAddress((void**)&Wh,  g_Wh);

    round_w_kernel<<<512, 256>>>(Wm1, Wue1, Wm2, Wue2, We);
    frame_kernel<<<NNODE/8, 256>>>(X, C, Wn, bn);
    // kNN + fused tail outputs (eidx/maski/maskij written once, final)
    knn_kernel<<<NNODE/4, 128>>>(C, out + S0OUT + S1OUT);
    // fused edge features + init GEMM
    edge_init_kernel<<<ETOT/128, 256, EI_SMEM>>>(Wh + WT_WE, be, Eh, Ehr);

    for (int l = 0; l < NL; l++) {
        const __half* W1cat = Wh + WT_CAT + (size_t)l*2*384*256;
        const __half* W1me  = Wh + WT_E1M + (size_t)l*256*128;
        const __half* W1ue  = Wh + WT_E1E + (size_t)l*128*128;
        const __half* Wm2l  = Wh + WT_M2  + (size_t)l*256*256;
        const __half* Wue2l = Wh + WT_UE2 + (size_t)l*128*128;
        const bool last = (l == NL-1);

        // node precompute (Ym + Ye fused) + fused g_ksum zeroing
        mm_tc<256, 384, 6, 0, 0><<<dim3(NNODE/128, 3, 2), 256, MM_SMEM>>>(
            Nhr, W1cat, nullptr, nullptr, nullptr, Ym, Ye, nullptr);
        // m-path stage-1 with fused masked k-reduction into g_ksum (reads Ehr)
        mm_tc<128, 256, 5, 0, 0><<<dim3(ETOT/128, 2), 256, MM_SMEM>>>(
            Ehr, W1me, bm1 + l*DN, Ym, Ym + (size_t)NNODE*DN, nullptr, nullptr, nullptr);
        // fused e-path stage-1 + edge update (t2 kept in smem; writes Eh/Ehr or final out)
        if (!last)
            fused_edge<1><<<ETOT/128, 256, FE_SMEM>>>(
                Ehr, W1ue, bue1 + l*DE, Ye, Ye + (size_t)NNODE*DE,
                Wue2l, bue2 + l*DE, Eh, Ehr);
        else
            fused_edge<0><<<ETOT/128, 256, FE_SMEM>>>(
                Ehr, W1ue, bue1 + l*DE, Ye, Ye + (size_t)NNODE*DE,
                Wue2l, bue2 + l*DE, out + S0OUT, nullptr);
        // node update (A = fp32 g_ksum, converted in loader)
        if (!last)
            mm_tc<256, 256, 3, 1, 1><<<dim3(NNODE/128, 2), 256, MM_SMEM>>>(
                (const __half*)Ks, Wm2l, bm2 + l*DN, nullptr, nullptr, Nh, nullptr, Nhr);
        else
            mm_tc<256, 256, 3, 0, 1><<<dim3(NNODE/128, 2), 256, MM_SMEM>>>(
                (const __half*)Ks, Wm2l, bm2 + l*DN, nullptr, nullptr, out, nullptr, nullptr);
    }
}

// round 14
// speedup vs baseline: 1.2813x; 1.0739x over previous
#include <cuda_runtime.h>
#include <cuda_fp16.h>
#include <math.h>

// ---------------- problem constants ----------------
#define BB   2
#define NN   2048
#define KNB  30
#define DN   256
#define DE   128
#define NL   3
#define NFI  12
#define EFI  28
#define ETOT (BB*NN*KNB)  // 122880
#define NNODE (BB*NN)     // 4096
#define EPSF 1e-6f
#define BIGF 1e9f
#define FLTMAX 3.402823466e38f

#define S0OUT (NNODE*DN)
#define S1OUT (ETOT*DE)

// ---------------- scratch ----------------
__device__ float  g_nodeh [NNODE*DN];
__device__ __half g_nodehr[NNODE*DN];
__device__ float  g_edgeh [ETOT*DE];
__device__ __half g_edgehr[ETOT*DE];
__device__ int    g_eidx [ETOT];
__device__ float  g_maski[NNODE];
__device__ float  g_maskij[ETOT];
__device__ float  g_denom[NNODE];
__device__ float  g_cnt  [NNODE];
__device__ float  g_R  [NNODE*9];
__device__ float  g_Xc [NNODE*3];
__device__ float  g_Ym [2*NNODE*DN];
__device__ float  g_Ye [2*NNODE*DE];
__device__ float  g_ksum [NNODE*DN];       // fp32 atomic accum

// transposed fp16 weight arena: W^T[n][k]
#define WT_CAT 0
#define WT_E1M (3*2*384*256)            // 589824
#define WT_E1E (WT_E1M + 3*256*128)     // 688128
#define WT_M2  (WT_E1E + 3*128*128)     // 737280
#define WT_UE2 (WT_M2  + 3*256*256)     // 933888
#define WT_WE  (WT_UE2 + 3*128*128)     // 983040
#define WT_TOT (WT_WE  + 128*32)        // 987136
__device__ __half g_Wh[WT_TOT];

__device__ __forceinline__ float softplus_f(float x) {
    return fmaxf(x, 0.0f) + log1pf(expf(-fabsf(x)));
}
__device__ __forceinline__ void mma16(float* c, const unsigned* a, const unsigned* b) {
    asm volatile(
        "mma.sync.aligned.m16n8k16.row.col.f32.f16.f16.f32 "
        "{%0,%1,%2,%3},{%4,%5,%6,%7},{%8,%9},{%0,%1,%2,%3};"
        : "+f"(c[0]), "+f"(c[1]), "+f"(c[2]), "+f"(c[3])
        : "r"(a[0]), "r"(a[1]), "r"(a[2]), "r"(a[3]), "r"(b[0]), "r"(b[1]));
}
__device__ __forceinline__ void ldsm4(unsigned& r0, unsigned& r1, unsigned& r2, unsigned& r3,
                                      unsigned addr) {
    asm volatile("ldmatrix.sync.aligned.m8n8.x4.shared.b16 {%0,%1,%2,%3}, [%4];"
        : "=r"(r0), "=r"(r1), "=r"(r2), "=r"(r3) : "r"(addr));
}
__device__ __forceinline__ void cp16(unsigned dst, const void* src) {
    asm volatile("cp.async.cg.shared.global [%0], [%1], 16;" :: "r"(dst), "l"(src));
}
#define CP_COMMIT() asm volatile("cp.async.commit_group;")
#define CP_WAIT2()  asm volatile("cp.async.wait_group 2;")
#define CP_WAIT0()  asm volatile("cp.async.wait_group 0;")

// ---------------- 0) round + transpose + repack all weights to fp16 ----------------
__global__ void round_w_kernel(const float* __restrict__ Wm1, const float* __restrict__ Wue1,
                               const float* __restrict__ Wm2, const float* __restrict__ Wue2,
                               const float* __restrict__ We)
{
    for (int i = blockIdx.x*blockDim.x + threadIdx.x; i < WT_TOT; i += gridDim.x*blockDim.x) {
        float v;
        if (i < WT_E1M) {                       // [l][z][n<384][k<256]
            int l = i / 196608, r = i % 196608;
            int z = r / 98304,  q = r % 98304;
            int n = q / 256,    k = q % 256;
            v = (n < 256) ? Wm1 [((size_t)l*640 + z*256 + k)*256 + n]
                          : Wue1[((size_t)l*640 + z*256 + k)*128 + (n - 256)];
        } else if (i < WT_E1E) {                // [l][n<256][k<128]
            int r = i - WT_E1M;
            int l = r / 32768, q = r % 32768;
            int n = q / 128,   k = q % 128;
            v = Wm1[((size_t)l*640 + 512 + k)*256 + n];
        } else if (i < WT_M2) {                 // [l][n<128][k<128]
            int r = i - WT_E1E;
            int l = r / 16384, q = r % 16384;
            int n = q / 128,   k = q % 128;
            v = Wue1[((size_t)l*640 + 512 + k)*128 + n];
        } else if (i < WT_UE2) {                // [l][n<256][k<256]
            int r = i - WT_M2;
            int l = r / 65536, q = r % 65536;
            int n = q / 256,   k = q % 256;
            v = Wm2[((size_t)l*256 + k)*256 + n];
        } else if (i < WT_WE) {                 // [l][n<128][k<128]
            int r = i - WT_UE2;
            int l = r / 16384, q = r % 16384;
            int n = q / 128,   k = q % 128;
            v = Wue2[((size_t)l*128 + k)*128 + n];
        } else {                                // [n<128][k<32]
            int r = i - WT_WE;
            int n = r / 32, k = r % 32;
            v = (k < EFI) ? We[k*128 + n] : 0.0f;
        }
        g_Wh[i] = __float2half_rn(v);
    }
}

// ---------------- 1) per-node frame, features, node_h init ----------------
__global__ void frame_kernel(const float* __restrict__ X, const int* __restrict__ C,
                             const float* __restrict__ Wn, const float* __restrict__ bn)
{
    __shared__ float s_feat[8][12];
    __shared__ float s_mask[8];
    int warp = threadIdx.x >> 5;
    int lane = threadIdx.x & 31;
    int nlin = blockIdx.x * 8 + warp;

    if (lane == 0) {
        const float* xr = X + (size_t)nlin * 12;
        float Na[3], CA[3], Ct[3], Oa[3];
        #pragma unroll
        for (int d = 0; d < 3; d++) { Na[d]=xr[d]; CA[d]=xr[3+d]; Ct[d]=xr[6+d]; Oa[d]=xr[9+d]; }
        #pragma unroll
        for (int d = 0; d < 3; d++) {
            float s = __fadd_rn(__fadd_rn(__fadd_rn(Na[d], CA[d]), Ct[d]), Oa[d]);
            g_Xc[nlin*3 + d] = __fmul_rn(s, 0.25f);
        }
        float b1[3], b2[3], b3[3], v0[3];
        #pragma unroll
        for (int d = 0; d < 3; d++) {
            b1[d] = CA[d] - Na[d];
            b2[d] = Ct[d] - CA[d];
            b3[d] = Oa[d] - Ct[d];
            v0[d] = Na[d] - CA[d];
        }
        float nb2 = sqrtf(b2[0]*b2[0] + b2[1]*b2[1] + b2[2]*b2[2]);
        float u[3];
        #pragma unroll
        for (int d = 0; d < 3; d++) u[d] = b2[d] / (nb2 + EPSF);
        float dotv = v0[0]*u[0] + v0[1]*u[1] + v0[2]*u[2];
        float t[3];
        #pragma unroll
        for (int d = 0; d < 3; d++) t[d] = v0[d] - dotv * u[d];
        float nt = sqrtf(t[0]*t[0] + t[1]*t[1] + t[2]*t[2]);
        float v[3];
        #pragma unroll
        for (int d = 0; d < 3; d++) v[d] = t[d] / (nt + EPSF);
        float w[3];
        w[0] = u[1]*v[2] - u[2]*v[1];
        w[1] = u[2]*v[0] - u[0]*v[2];
        w[2] = u[0]*v[1] - u[1]*v[0];
        #pragma unroll
        for (int d = 0; d < 3; d++) {
            g_R[nlin*9 + d*3 + 0] = u[d];
            g_R[nlin*9 + d*3 + 1] = v[d];
            g_R[nlin*9 + d*3 + 2] = w[d];
        }
        float nb1 = sqrtf(b1[0]*b1[0] + b1[1]*b1[1] + b1[2]*b1[2]);
        float nb3 = sqrtf(b3[0]*b3[0] + b3[1]*b3[1] + b3[2]*b3[2]);
        #pragma unroll
        for (int d = 0; d < 3; d++) {
            s_feat[warp][0 + d] = b1[d] / (nb1 + EPSF);
            s_feat[warp][4 + d] = b2[d] / (nb2 + EPSF);
            s_feat[warp][8 + d] = b3[d] / (nb3 + EPSF);
        }
        s_feat[warp][3]  = logf(nb1 + EPSF);
        s_feat[warp][7]  = logf(nb2 + EPSF);
        s_feat[warp][11] = logf(nb3 + EPSF);
        float mk = (C[nlin] > 0) ? 1.0f : 0.0f;
        s_mask[warp] = mk;
        g_maski[nlin] = mk;
    }
    __syncwarp();

    float f[12];
    #pragma unroll
    for (int i = 0; i < 12; i++) f[i] = s_feat[warp][i];
    float mk = s_mask[warp];
    #pragma unroll
    for (int r = 0; r < 8; r++) {
        int c = lane + r * 32;
        float acc = bn[c];
        #pragma unroll
        for (int ff = 0; ff < NFI; ff++) acc += f[ff] * Wn[ff*DN + c];
        float v = acc * mk;
        g_nodeh [(size_t)nlin*DN + c] = v;
        g_nodehr[(size_t)nlin*DN + c] = __float2half_rn(v);
    }
}

// ---------------- 2) kNN: warp-per-node + fused tail output ----------------
__global__ __launch_bounds__(128) void knn_kernel(const int* __restrict__ C,
                                                  float* __restrict__ out_tail)
{
    __shared__ float s_d2[4][NN];
    int wid = threadIdx.x >> 5;
    int lane = threadIdx.x & 31;
    int nlin = blockIdx.x * 4 + wid;
    int b = nlin >> 11;
    int n = nlin & (NN - 1);

    float xi0 = g_Xc[nlin*3+0], xi1 = g_Xc[nlin*3+1], xi2 = g_Xc[nlin*3+2];
    const int* Cb = C + b*NN;
    for (int j = lane; j < NN; j += 32) {
        float dx = __fadd_rn(xi0, -g_Xc[(size_t)(b*NN + j)*3 + 0]);
        float dy = __fadd_rn(xi1, -g_Xc[(size_t)(b*NN + j)*3 + 1]);
        float dz = __fadd_rn(xi2, -g_Xc[(size_t)(b*NN + j)*3 + 2]);
        float d2 = __fadd_rn(__fadd_rn(__fmul_rn(dx,dx), __fmul_rn(dy,dy)), __fmul_rn(dz,dz));
        if (Cb[j] <= 0) d2 = __fadd_rn(d2, BIGF);
        if (j == n)     d2 = __fadd_rn(d2, BIGF);
        s_d2[wid][j] = d2;
    }
    __syncwarp();

    float mi = g_maski[nlin];
    float cnt = 0.0f;
    for (int kk = 0; kk < KNB; kk++) {
        float bv = FLTMAX; int bi = 0x7fffffff;
        #pragma unroll 4
        for (int j = lane; j < NN; j += 32) {
            float v = s_d2[wid][j];
            if (v < bv || (v == bv && j < bi)) { bv = v; bi = j; }
        }
        #pragma unroll
        for (int off = 16; off > 0; off >>= 1) {
            float v2 = __shfl_down_sync(0xffffffffu, bv, off);
            int   i2 = __shfl_down_sync(0xffffffffu, bi, off);
            if (v2 < bv || (v2 == bv && i2 < bi)) { bv = v2; bi = i2; }
        }
        bi = __shfl_sync(0xffffffffu, bi, 0);
        if (lane == 0) {
            int e = nlin*KNB + kk;
            g_eidx[e] = bi;
            float mj = (Cb[bi] > 0) ? 1.0f : 0.0f;
            float mij = mi * mj;
            g_maskij[e] = mij;
            cnt += mij;
            s_d2[wid][bi] = FLTMAX;
            out_tail[e] = (float)bi;
            out_tail[ETOT + NNODE + e] = mij;
        }
        __syncwarp();
    }
    if (lane == 0) {
        g_cnt[nlin] = cnt;
        g_denom[nlin] = cnt + EPSF;
        out_tail[ETOT + nlin] = mi;
    }
}

#define MM_ST 4
#define MM_AS (128*24)
#define MM_BS (128*24)
#define MM_SMEM 66560

// ---------------- 3) fused edge-init ----------------
#define EI_SMEM (4*MM_AS*2)               // 24576

__global__ __launch_bounds__(256, 3) void edge_init_kernel(
    const __half* __restrict__ W, const float* __restrict__ bias,
    float* __restrict__ out, __half* __restrict__ outh)
{
    extern __shared__ float smem_dyn[];
    __half* Asm = (__half*)smem_dyn;
    __half* Bsm = Asm + 2*MM_AS;

    const int tid  = threadIdx.x;
    const int lane = tid & 31;
    const int wid  = tid >> 5;
    const int wm   = wid & 1;
    const int wn   = wid >> 1;
    const int rowBase = blockIdx.x * 128;

    const int laR = tid >> 1, laK = (tid & 1) * 8;
    const unsigned sb = (unsigned)__cvta_generic_to_shared(Bsm) + (laR*24 + laK)*2;
    cp16(sb + 0*MM_BS*2, W + laR*32 + laK);
    cp16(sb + 1*MM_BS*2, W + laR*32 + 16 + laK);
    CP_COMMIT();

    {
        const int eLoc = tid & 127;
        const int half = tid >> 7;
        int e = rowBase + eLoc;
        int nlin = e / KNB;
        int b = nlin >> 11;
        int j = g_eidx[e];
        int jl = b*NN + j;

        float dv[3];
        #pragma unroll
        for (int d = 0; d < 3; d++) dv[d] = g_Xc[jl*3+d] - g_Xc[nlin*3+d];
        float dist = sqrtf(dv[0]*dv[0] + dv[1]*dv[1] + dv[2]*dv[2]);

        if (half == 0) {
            float f[16];
            #pragma unroll
            for (int mc = 0; mc < 16; mc++) {
                float cm = (float)(20.0 * mc / 15.0);
                float z = (dist - cm) * 0.8f;
                f[mc] = expf(-z*z);
            }
            #pragma unroll
            for (int q = 0; q < 8; q++)
                *(__half2*)(Asm + 0*MM_AS + eLoc*24 + 2*q) = __floats2half2_rn(f[2*q], f[2*q+1]);
        } else {
            float Ri[9], Rj[9];
            #pragma unroll
            for (int q = 0; q < 9; q++) { Ri[q] = g_R[nlin*9+q]; Rj[q] = g_R[jl*9+q]; }
            float f[16];
            float inv = 1.0f / (dist + EPSF);
            #pragma unroll
            for (int c = 0; c < 3; c++) {
                float loc = Ri[0*3+c]*dv[0] + Ri[1*3+c]*dv[1] + Ri[2*3+c]*dv[2];
                f[c] = loc * inv;
            }
            #pragma unroll
            for (int ee = 0; ee < 3; ee++)
                #pragma unroll
                for (int ff = 0; ff < 3; ff++)
                    f[3 + ee*3 + ff] = Ri[0*3+ee]*Rj[0*3+ff] + Ri[1*3+ee]*Rj[1*3+ff] + Ri[2*3+ee]*Rj[2*3+ff];
            f[12] = f[13] = f[14] = f[15] = 0.0f;
            #pragma unroll
            for (int q = 0; q < 8; q++)
                *(__half2*)(Asm + 1*MM_AS + eLoc*24 + 2*q) = __floats2half2_rn(f[2*q], f[2*q+1]);
        }
    }
    CP_WAIT0();
    __syncthreads();

    const unsigned aF = (unsigned)__cvta_generic_to_shared(Asm)
        + (((wm*64 + (lane & 15))*24 + (lane >> 4)*8) * 2);
    const unsigned bF = (unsigned)__cvta_generic_to_shared(Bsm)
        + (((wn*32 + (lane & 7) + ((lane >> 4) & 1)*8)*24 + ((lane >> 3) & 1)*8) * 2);

    float acc[4][4][4];
    #pragma unroll
    for (int i = 0; i < 4; i++)
        #pragma unroll
        for (int j = 0; j < 4; j++)
            #pragma unroll
            for (int q = 0; q < 4; q++) acc[i][j][q] = 0.0f;

    #pragma unroll
    for (int c = 0; c < 2; c++) {
        const unsigned aS = aF + c*MM_AS*2;
        const unsigned bS = bF + c*MM_BS*2;
        unsigned a[4][4], bq[4][2];
        #pragma unroll
        for (int mt = 0; mt < 4; mt++)
            ldsm4(a[mt][0], a[mt][1], a[mt][2], a[mt][3], aS + (mt*16*24)*2);
        #pragma unroll
        for (int np = 0; np < 2; np++)
            ldsm4(bq[2*np][0], bq[2*np][1], bq[2*np+1][0], bq[2*np+1][1],
                  bS + (np*16*24)*2);
        #pragma unroll
        for (int mt = 0; mt < 4; mt++)
            #pragma unroll
            for (int nt = 0; nt < 4; nt++)
                mma16(acc[mt][nt], a[mt], bq[nt]);
    }

    #pragma unroll
    for (int mt = 0; mt < 4; mt++) {
        #pragma unroll
        for (int h = 0; h < 2; h++) {
            const int r = wm*64 + mt*16 + (lane >> 2) + h*8;
            const int grow = rowBase + r;
            float mij = g_maskij[grow];
            #pragma unroll
            for (int nt = 0; nt < 4; nt++) {
                const int c0 = wn*32 + nt*8 + 2*(lane & 3);
                float2 bsv = *(const float2*)(bias + c0);
                float v0 = (acc[mt][nt][h*2 + 0] + bsv.x) * mij;
                float v1 = (acc[mt][nt][h*2 + 1] + bsv.y) * mij;
                *(float2*)(out + (size_t)grow*DE + c0) = make_float2(v0, v1);
                *(__half2*)(outh + (size_t)grow*DE + c0) = __floats2half2_rn(v0, v1);
            }
        }
    }
}

// ---------------- 4) fp16 TC GEMM (m16n8k16), 4-stage cp.async + ldmatrix ----------------
// MODE 5: m-path stage-1: masked softplus -> smem reduce -> atomic g_ksum
// MODE 6: node precompute cat (+ fused g_ksum zeroing on y==0,z==0)
template<int KD, int NF, int MODE, int FLG, int A32>
__global__ __launch_bounds__(256, 2) void mm_tc(
    const __half* __restrict__ A, const __half* __restrict__ W,
    const float* __restrict__ bias,
    const float* __restrict__ Yi, const float* __restrict__ Zj,
    float* __restrict__ out, float* __restrict__ out2, __half* __restrict__ outh)
{
    constexpr int CH = KD / 16;
    extern __shared__ float smem_dyn[];
    __half* Asm = (__half*)smem_dyn;
    __half* Bsm = Asm + MM_ST*MM_AS;

    const int tid  = threadIdx.x;
    const int lane = tid & 31;
    const int wid  = tid >> 5;
    const int wm   = wid & 1;
    const int wn   = wid >> 1;

    const int rowBase = blockIdx.x * 128;
    const int n0 = blockIdx.y * 128;

    const __half* Wp = W;
    if (MODE == 6) Wp = W + (size_t)blockIdx.z * 384 * 256;

    const int laR = tid >> 1, laK = (tid & 1) * 8;
    const __half* Ag  = A + (size_t)(rowBase + laR) * KD + laK;
    const __half* Wg = Wp + (size_t)(n0 + laR) * KD + laK;

    const unsigned sa = (unsigned)__cvta_generic_to_shared(Asm) + (laR*24 + laK)*2;
    const unsigned sb = (unsigned)__cvta_generic_to_shared(Bsm) + (laR*24 + laK)*2;

    const unsigned aF = (unsigned)__cvta_generic_to_shared(Asm)
        + (((wm*64 + (lane & 15))*24 + (lane >> 4)*8) * 2);
    const unsigned bF = (unsigned)__cvta_generic_to_shared(Bsm)
        + (((wn*32 + (lane & 7) + ((lane >> 4) & 1)*8)*24 + ((lane >> 3) & 1)*8) * 2);

    #pragma unroll
    for (int s = 0; s < MM_ST-1; s++) {
        if (s < CH) {
            cp16(sa + s*MM_AS*2, Ag + s*16);
            cp16(sb + s*MM_BS*2, Wg + s*16);
        }
        CP_COMMIT();
    }

    if (MODE == 6 && blockIdx.y == 0 && blockIdx.z == 0) {
        float4* p = (float4*)(g_ksum + (size_t)rowBase * DN);
        for (int i = tid; i < 128*DN/4; i += 256)
            p[i] = make_float4(0.f, 0.f, 0.f, 0.f);
    }

    float acc[4][4][4];
    #pragma unroll
    for (int i = 0; i < 4; i++)
        #pragma unroll
        for (int j = 0; j < 4; j++)
            #pragma unroll
            for (int q = 0; q < 4; q++) acc[i][j][q] = 0.0f;

    #pragma unroll 1
    for (int c = 0; c < CH; c++) {
        CP_WAIT2();
        __syncthreads();

        if (c + MM_ST-1 < CH) {
            const int slot = (c + MM_ST-1) & (MM_ST-1);
            const int cc = c + MM_ST-1;
            cp16(sa + slot*MM_AS*2, Ag + cc*16);
            cp16(sb + slot*MM_BS*2, Wg + cc*16);
        }
        CP_COMMIT();

        const unsigned aS = aF + (c & (MM_ST-1))*MM_AS*2;
        const unsigned bS = bF + (c & (MM_ST-1))*MM_BS*2;

        unsigned a[4][4], bq[4][2];
        #pragma unroll
        for (int mt = 0; mt < 4; mt++)
            ldsm4(a[mt][0], a[mt][1], a[mt][2], a[mt][3], aS + (mt*16*24)*2);
        #pragma unroll
        for (int np = 0; np < 2; np++)
            ldsm4(bq[2*np][0], bq[2*np][1], bq[2*np+1][0], bq[2*np+1][1],
                  bS + (np*16*24)*2);
        #pragma unroll
        for (int mt = 0; mt < 4; mt++)
            #pragma unroll
            for (int nt = 0; nt < 4; nt++)
                mma16(acc[mt][nt], a[mt], bq[nt]);
    }

    float* sred = smem_dyn;
    if (MODE == 5) __syncthreads();

    #pragma unroll
    for (int mt = 0; mt < 4; mt++) {
        #pragma unroll
        for (int h = 0; h < 2; h++) {
            const int r = wm*64 + mt*16 + (lane >> 2) + h*8;
            const int grow = rowBase + r;

            const float* yip = nullptr; const float* zjp = nullptr;
            float mij = 0.f;
            if (MODE == 5) {
                int nlin = grow / KNB;
                int b = nlin >> 11;
                yip = Yi + (size_t)nlin * NF + n0;
                zjp = Zj + (size_t)(b*NN + g_eidx[grow]) * NF + n0;
                mij = g_maskij[grow];
            }

            #pragma unroll
            for (int nt = 0; nt < 4; nt++) {
                const int c0 = wn*32 + nt*8 + 2*(lane & 3);
                float v0 = acc[mt][nt][h*2 + 0];
                float v1 = acc[mt][nt][h*2 + 1];
                if (MODE == 6) {
                    float* op;
                    if (n0 < 256) op = out  + (size_t)blockIdx.z*NNODE*DN + (size_t)grow*DN + n0;
                    else          op = out2 + (size_t)blockIdx.z*NNODE*DE + (size_t)grow*DE + (n0-256);
                    *(float2*)(op + c0) = make_float2(v0, v1);
                } else { // MODE 5
                    float2 bsv = *(const float2*)(bias + n0 + c0);
                    float2 yv  = *(const float2*)(yip + c0);
                    float2 zv  = *(const float2*)(zjp + c0);
                    v0 = softplus_f(v0 + bsv.x + yv.x + zv.x) * mij;
                    v1 = softplus_f(v1 + bsv.y + yv.y + zv.y) * mij;
                    sred[r*130 + c0]     = v0;
                    sred[r*130 + c0 + 1] = v1;
                }
            }
        }
    }

    if (MODE == 5) {
        __syncthreads();
        if (tid < 128) {
            const int c = tid;
            const int nfirst = rowBase / KNB;
            const int nlast  = (rowBase + 127) / KNB;
            for (int n = nfirst; n <= nlast; n++) {
                int r0 = n*KNB - rowBase;
                int r1 = r0 + KNB;
                r0 = r0 < 0 ? 0 : r0;
                r1 = r1 > 128 ? 128 : r1;
                float s = 0.0f;
                for (int r = r0; r < r1; r++) s += sred[r*130 + c];
                atomicAdd(&g_ksum[(size_t)n*DN + n0 + c], s);
            }
        }
    }
}

// ---------------- 5) fused e-path + co-scheduled node update ----------------
// blocks [0, ETOT/128): t2 = softplus(A@W1+b1+Yi+Zj) in smem; edge_h=(edge_h+t2@W2+b2)*mij
// blocks [ETOT/128, +64): node_h = (node_h + (ksum@Wm2 + cnt*bm2)/denom)*mask_i
#define FE_SMEM ((8*MM_AS + 4*MM_BS)*2)   // 73728

template<int FLG>
__device__ __forceinline__ void node_update_body(
    const float* __restrict__ Ks, const __half* __restrict__ W,
    const float* __restrict__ bias, float* __restrict__ out,
    __half* __restrict__ outh, float* smem_dyn)
{
    constexpr int KD = 256, CH = 16, NF = 256;
    __half* Asm = (__half*)smem_dyn;
    __half* Bsm = Asm + MM_ST*MM_AS;

    const int tid  = threadIdx.x;
    const int lane = tid & 31;
    const int wid  = tid >> 5;
    const int wm   = wid & 1;
    const int wn   = wid >> 1;

    const int idx = blockIdx.x - ETOT/128;
    const int rowBase = (idx >> 1) * 128;
    const int n0 = (idx & 1) * 128;

    const int laR = tid >> 1, laK = (tid & 1) * 8;
    const float*  Agf = Ks + (size_t)(rowBase + laR) * KD + laK;
    const __half* Wg  = W  + (size_t)(n0 + laR) * KD + laK;

    const unsigned sb = (unsigned)__cvta_generic_to_shared(Bsm) + (laR*24 + laK)*2;
    __half* AsmT = Asm + laR*24 + laK;

    const unsigned aF = (unsigned)__cvta_generic_to_shared(Asm)
        + (((wm*64 + (lane & 15))*24 + (lane >> 4)*8) * 2);
    const unsigned bF = (unsigned)__cvta_generic_to_shared(Bsm)
        + (((wn*32 + (lane & 7) + ((lane >> 4) & 1)*8)*24 + ((lane >> 3) & 1)*8) * 2);

    #pragma unroll
    for (int s = 0; s < MM_ST-1; s++) {
        {
            float4 f0 = *(const float4*)(Agf + s*16);
            float4 f1 = *(const float4*)(Agf + s*16 + 4);
            __half2 hh[4] = {__floats2half2_rn(f0.x,f0.y), __floats2half2_rn(f0.z,f0.w),
                             __floats2half2_rn(f1.x,f1.y), __floats2half2_rn(f1.z,f1.w)};
            *(uint4*)(AsmT + s*MM_AS) = *(uint4*)hh;
            cp16(sb + s*MM_BS*2, Wg + s*16);
        }
        CP_COMMIT();
    }

    float acc[4][4][4];
    #pragma unroll
    for (int i = 0; i < 4; i++)
        #pragma unroll
        for (int j = 0; j < 4; j++)
            #pragma unroll
            for (int q = 0; q < 4; q++) acc[i][j][q] = 0.0f;

    #pragma unroll 1
    for (int c = 0; c < CH; c++) {
        CP_WAIT2();
        __syncthreads();

        if (c + MM_ST-1 < CH) {
            const int slot = (c + MM_ST-1) & (MM_ST-1);
            const int cc = c + MM_ST-1;
            float4 f0 = *(const float4*)(Agf + cc*16);
            float4 f1 = *(const float4*)(Agf + cc*16 + 4);
            __half2 hh[4] = {__floats2half2_rn(f0.x,f0.y), __floats2half2_rn(f0.z,f0.w),
                             __floats2half2_rn(f1.x,f1.y), __floats2half2_rn(f1.z,f1.w)};
            *(uint4*)(AsmT + slot*MM_AS) = *(uint4*)hh;
            cp16(sb + slot*MM_BS*2, Wg + cc*16);
        }
        CP_COMMIT();

        const unsigned aS = aF + (c & (MM_ST-1))*MM_AS*2;
        const unsigned bS = bF + (c & (MM_ST-1))*MM_BS*2;

        unsigned a[4][4], bq[4][2];
        #pragma unroll
        for (int mt = 0; mt < 4; mt++)
            ldsm4(a[mt][0], a[mt][1], a[mt][2], a[mt][3], aS + (mt*16*24)*2);
        #pragma unroll
        for (int np = 0; np < 2; np++)
            ldsm4(bq[2*np][0], bq[2*np][1], bq[2*np+1][0], bq[2*np+1][1],
                  bS + (np*16*24)*2);
        #pragma unroll
        for (int mt = 0; mt < 4; mt++)
            #pragma unroll
            for (int nt = 0; nt < 4; nt++)
                mma16(acc[mt][nt], a[mt], bq[nt]);
    }

    #pragma unroll
    for (int mt = 0; mt < 4; mt++) {
        #pragma unroll
        for (int h = 0; h < 2; h++) {
            const int r = wm*64 + mt*16 + (lane >> 2) + h*8;
            const int grow = rowBase + r;
            float dn = g_denom[grow], mi = g_maski[grow], cn = g_cnt[grow];
            const float* nhp = g_nodeh + (size_t)grow * DN + n0;
            #pragma unroll
            for (int nt = 0; nt < 4; nt++) {
                const int c0 = wn*32 + nt*8 + 2*(lane & 3);
                float2 bsv = *(const float2*)(bias + n0 + c0);
                float2 nv  = *(const float2*)(nhp + c0);
                float v0 = (nv.x + (acc[mt][nt][h*2 + 0] + cn*bsv.x) / dn) * mi;
                float v1 = (nv.y + (acc[mt][nt][h*2 + 1] + cn*bsv.y) / dn) * mi;
                *(float2*)(out + (size_t)grow*NF + n0 + c0) = make_float2(v0, v1);
                if (FLG) *(__half2*)(outh + (size_t)grow*NF + n0 + c0) = __floats2half2_rn(v0, v1);
            }
        }
    }
}

template<int FLG>
__global__ __launch_bounds__(256, 2) void fused_edge(
    const __half* __restrict__ A, const __half* __restrict__ W1,
    const float* __restrict__ bia1,
    const float* __restrict__ Yi, const float* __restrict__ Zj,
    const __half* __restrict__ W2, const float* __restrict__ bia2,
    float* __restrict__ out, __half* __restrict__ outh,
    const float* __restrict__ Ks, const __half* __restrict__ Wm2,
    const float* __restrict__ bm2, float* __restrict__ nout,
    __half* __restrict__ nouth)
{
    extern __shared__ float smem_dyn[];

    if (blockIdx.x >= ETOT/128) {
        node_update_body<FLG>(Ks, Wm2, bm2, nout, nouth, smem_dyn);
        return;
    }

    constexpr int KD = 128, CH = 8;
    __half* Asm  = (__half*)smem_dyn;
    __half* Bsm  = Asm + MM_ST*MM_AS;
    __half* Tm   = Asm;
    __half* B2sm = Asm + 8*MM_AS;

    const int tid  = threadIdx.x;
    const int lane = tid & 31;
    const int wid  = tid >> 5;
    const int wm   = wid & 1;
    const int wn   = wid >> 1;
    const int rowBase = blockIdx.x * 128;

    const int laR = tid >> 1, laK = (tid & 1) * 8;
    const __half* Ag  = A  + (size_t)(rowBase + laR) * KD + laK;
    const __half* W1g = W1 + (size_t)laR * KD + laK;
    const __half* W2g = W2 + (size_t)laR * KD + laK;

    const unsigned sa  = (unsigned)__cvta_generic_to_shared(Asm)  + (laR*24 + laK)*2;
    const unsigned sb  = (unsigned)__cvta_generic_to_shared(Bsm)  + (laR*24 + laK)*2;
    const unsigned sb2 = (unsigned)__cvta_generic_to_shared(B2sm) + (laR*24 + laK)*2;

    const unsigned aF = (unsigned)__cvta_generic_to_shared(Asm)
        + (((wm*64 + (lane & 15))*24 + (lane >> 4)*8) * 2);
    const unsigned bF = (unsigned)__cvta_generic_to_shared(Bsm)
        + (((wn*32 + (lane & 7) + ((lane >> 4) & 1)*8)*24 + ((lane >> 3) & 1)*8) * 2);
    const unsigned bF2 = (unsigned)__cvta_generic_to_shared(B2sm)
        + (((wn*32 + (lane & 7) + ((lane >> 4) & 1)*8)*24 + ((lane >> 3) & 1)*8) * 2);

    #pragma unroll
    for (int s = 0; s < MM_ST-1; s++) {
        cp16(sa + s*MM_AS*2, Ag + s*16);
        cp16(sb + s*MM_BS*2, W1g + s*16);
        CP_COMMIT();
    }

    float acc[4][4][4];
    #pragma unroll
    for (int i = 0; i < 4; i++)
        #pragma unroll
        for (int j = 0; j < 4; j++)
            #pragma unroll
            for (int q = 0; q < 4; q++) acc[i][j][q] = 0.0f;

    #pragma unroll 1
    for (int c = 0; c < CH; c++) {
        CP_WAIT2();
        __syncthreads();
        if (c + MM_ST-1 < CH) {
            const int slot = (c + MM_ST-1) & (MM_ST-1);
            const int cc = c + MM_ST-1;
            cp16(sa + slot*MM_AS*2, Ag + cc*16);
            cp16(sb + slot*MM_BS*2, W1g + cc*16);
        }
        CP_COMMIT();

        const unsigned aS = aF + (c & (MM_ST-1))*MM_AS*2;
        const unsigned bS = bF + (c & (MM_ST-1))*MM_BS*2;
        unsigned a[4][4], bq[4][2];
        #pragma unroll
        for (int mt = 0; mt < 4; mt++)
            ldsm4(a[mt][0], a[mt][1], a[mt][2], a[mt][3], aS + (mt*16*24)*2);
        #pragma unroll
        for (int np = 0; np < 2; np++)
            ldsm4(bq[2*np][0], bq[2*np][1], bq[2*np+1][0], bq[2*np+1][1],
                  bS + (np*16*24)*2);
        #pragma unroll
        for (int mt = 0; mt < 4; mt++)
            #pragma unroll
            for (int nt = 0; nt < 4; nt++)
                mma16(acc[mt][nt], a[mt], bq[nt]);
    }

    __syncthreads();

    #pragma unroll
    for (int s = 0; s < MM_ST-1; s++) {
        cp16(sb2 + s*MM_BS*2, W2g + s*16);
        CP_COMMIT();
    }

    #pragma unroll
    for (int mt = 0; mt < 4; mt++) {
        #pragma unroll
        for (int h = 0; h < 2; h++) {
            const int r = wm*64 + mt*16 + (lane >> 2) + h*8;
            const int grow = rowBase + r;
            int nlin = grow / KNB;
            int b = nlin >> 11;
            const float* yip = Yi + (size_t)nlin * DE;
            const float* zjp = Zj + (size_t)(b*NN + g_eidx[grow]) * DE;
            #pragma unroll
            for (int nt = 0; nt < 4; nt++) {
                const int c0 = wn*32 + nt*8 + 2*(lane & 3);
                float2 bsv = *(const float2*)(bia1 + c0);
                float2 yv  = *(const float2*)(yip + c0);
                float2 zv  = *(const float2*)(zjp + c0);
                float v0 = softplus_f(acc[mt][nt][h*2 + 0] + bsv.x + yv.x + zv.x);
                float v1 = softplus_f(acc[mt][nt][h*2 + 1] + bsv.y + yv.y + zv.y);
                *(__half2*)(Tm + (c0 >> 4)*MM_AS + r*24 + (c0 & 15)) =
                    __floats2half2_rn(v0, v1);
            }
        }
    }

    #pragma unroll
    for (int i = 0; i < 4; i++)
        #pragma unroll
        for (int j = 0; j < 4; j++)
            #pragma unroll
            for (int q = 0; q < 4; q++) acc[i][j][q] = 0.0f;

    #pragma unroll 1
    for (int c = 0; c < CH; c++) {
        CP_WAIT2();
        __syncthreads();
        if (c + MM_ST-1 < CH) {
            const int slot = (c + MM_ST-1) & (MM_ST-1);
            cp16(sb2 + slot*MM_BS*2, W2g + (c + MM_ST-1)*16);
        }
        CP_COMMIT();

        const unsigned aS = aF + c*MM_AS*2;
        const unsigned bS = bF2 + (c & (MM_ST-1))*MM_BS*2;
        unsigned a[4][4], bq[4][2];
        #pragma unroll
        for (int mt = 0; mt < 4; mt++)
            ldsm4(a[mt][0], a[mt][1], a[mt][2], a[mt][3], aS + (mt*16*24)*2);
        #pragma unroll
        for (int np = 0; np < 2; np++)
            ldsm4(bq[2*np][0], bq[2*np][1], bq[2*np+1][0], bq[2*np+1][1],
                  bS + (np*16*24)*2);
        #pragma unroll
        for (int mt = 0; mt < 4; mt++)
            #pragma unroll
            for (int nt = 0; nt < 4; nt++)
                mma16(acc[mt][nt], a[mt], bq[nt]);
    }

    #pragma unroll
    for (int mt = 0; mt < 4; mt++) {
        #pragma unroll
        for (int h = 0; h < 2; h++) {
            const int r = wm*64 + mt*16 + (lane >> 2) + h*8;
            const int grow = rowBase + r;
            float mij = g_maskij[grow];
            const float* ehp = g_edgeh + (size_t)grow * DE;
            #pragma unroll
            for (int nt = 0; nt < 4; nt++) {
                const int c0 = wn*32 + nt*8 + 2*(lane & 3);
                float2 bsv = *(const float2*)(bia2 + c0);
                float2 ev  = *(const float2*)(ehp + c0);
                float v0 = (ev.x + acc[mt][nt][h*2 + 0] + bsv.x) * mij;
                float v1 = (ev.y + acc[mt][nt][h*2 + 1] + bsv.y) * mij;
                *(float2*)(out + (size_t)grow*DE + c0) = make_float2(v0, v1);
                if (FLG) *(__half2*)(outh + (size_t)grow*DE + c0) = __floats2half2_rn(v0, v1);
            }
        }
    }
}

// ---------------- launch ----------------
extern "C" void kernel_launch(void* const* d_in, const int* in_sizes, int n_in,
                              void* d_out, int out_size)
{
    const float* X    = (const float*)d_in[0];
    const int*   C    = (const int*)  d_in[1];
    const float* Wn   = (const float*)d_in[2];
    const float* bn   = (const float*)d_in[3];
    const float* We   = (const float*)d_in[4];
    const float* be   = (const float*)d_in[5];
    const float* Wm1  = (const float*)d_in[6];
    const float* bm1  = (const float*)d_in[7];
    const float* Wm2  = (const float*)d_in[8];
    const float* bm2  = (const float*)d_in[9];
    const float* Wue1 = (const float*)d_in[10];
    const float* bue1 = (const float*)d_in[11];
    const float* Wue2 = (const float*)d_in[12];
    const float* bue2 = (const float*)d_in[13];
    float* out = (float*)d_out;

    cudaFuncSetAttribute(mm_tc<256,384,6,0,0>, cudaFuncAttributeMaxDynamicSharedMemorySize, MM_SMEM);
    cudaFuncSetAttribute(mm_tc<128,256,5,0,0>, cudaFuncAttributeMaxDynamicSharedMemorySize, MM_SMEM);
    cudaFuncSetAttribute(fused_edge<1>, cudaFuncAttributeMaxDynamicSharedMemorySize, FE_SMEM);
    cudaFuncSetAttribute(fused_edge<0>, cudaFuncAttributeMaxDynamicSharedMemorySize, FE_SMEM);
    cudaFuncSetAttribute(edge_init_kernel, cudaFuncAttributeMaxDynamicSharedMemorySize, EI_SMEM);

    float*  Ym;  cudaGetSymbolAddress((void**)&Ym,  g_Ym);
    float*  Ye;  cudaGetSymbolAddress((void**)&Ye,  g_Ye);
    float*  Eh;  cudaGetSymbolAddress((void**)&Eh,  g_edgeh);
    __half* Ehr; cudaGetSymbolAddress((void**)&Ehr, g_edgehr);
    float*  Nh;  cudaGetSymbolAddress((void**)&Nh,  g_nodeh);
    __half* Nhr; cudaGetSymbolAddress((void**)&Nhr, g_nodehr);
    float*  Ks;  cudaGetSymbolAddress((void**)&Ks,  g_ksum);
    __half* Wh;  cudaGetSymbolAddress((void**)&Wh,  g_Wh);

    round_w_kernel<<<512, 256>>>(Wm1, Wue1, Wm2, Wue2, We);
    frame_kernel<<<NNODE/8, 256>>>(X, C, Wn, bn);
    knn_kernel<<<NNODE/4, 128>>>(C, out + S0OUT + S1OUT);
    edge_init_kernel<<<ETOT/128, 256, EI_SMEM>>>(Wh + WT_WE, be, Eh, Ehr);

    const int FE_GRID = ETOT/128 + (NNODE/128)*2;   // 960 edge blocks + 64 node blocks
    for (int l = 0; l < NL; l++) {
        const __half* W1cat = Wh + WT_CAT + (size_t)l*2*384*256;
        const __half* W1me  = Wh + WT_E1M + (size_t)l*256*128;
        const __half* W1ue  = Wh + WT_E1E + (size_t)l*128*128;
        const __half* Wm2l  = Wh + WT_M2  + (size_t)l*256*256;
        const __half* Wue2l = Wh + WT_UE2 + (size_t)l*128*128;
        const bool last = (l == NL-1);

        // node precompute (Ym + Ye fused) + fused g_ksum zeroing
        mm_tc<256, 384, 6, 0, 0><<<dim3(NNODE/128, 3, 2), 256, MM_SMEM>>>(
            Nhr, W1cat, nullptr, nullptr, nullptr, Ym, Ye, nullptr);
        // m-path stage-1 with fused masked k-reduction into g_ksum (reads Ehr)
        mm_tc<128, 256, 5, 0, 0><<<dim3(ETOT/128, 2), 256, MM_SMEM>>>(
            Ehr, W1me, bm1 + l*DN, Ym, Ym + (size_t)NNODE*DN, nullptr, nullptr, nullptr);
        // fused e-path stage-1 + edge update + co-scheduled node update
        if (!last)
            fused_edge<1><<<FE_GRID, 256, FE_SMEM>>>(
                Ehr, W1ue, bue1 + l*DE, Ye, Ye + (size_t)NNODE*DE,
                Wue2l, bue2 + l*DE, Eh, Ehr,
                Ks, Wm2l, bm2 + l*DN, Nh, Nhr);
        else
            fused_edge<0><<<FE_GRID, 256, FE_SMEM>>>(
                Ehr, W1ue, bue1 + l*DE, Ye, Ye + (size_t)NNODE*DE,
                Wue2l, bue2 + l*DE, out + S0OUT, nullptr,
                Ks, Wm2l, bm2 + l*DN, out, nullptr);
    }
}